// round 1
// baseline (speedup 1.0000x reference)
#include <cuda_runtime.h>

#define FULL 0xffffffffu
#define EPSC 1e-6f

// Only rows offset_j + [0,7) of each table are reachable (feature ids < 7).
__constant__ int UOFF[7] = {0, 11577, 11588, 11599, 11610, 11621, 11642};
__constant__ int VOFF[5] = {0, 4733, 4754, 4761, 4772};

// SMEM layout (float2 region then float region)
// us: 49 entries * 32 float2   (user sub-table, entry=(col*7+val), float2=(v[l],v[l+32]))
// ur: 35 entries * 32 float2
// w2: 128*32 float2            (W2 transposed+paired: [i][l] = (W2[l][i], W2[l+32][i]))
// w1: 128*32 float2
// then floats: wo[256], b2[64], b1[64], bo[4], xbuf[8*128]
constexpr int US_F2 = 49 * 32;
constexpr int UR_F2 = 35 * 32;
constexpr int W_F2  = 128 * 32;
constexpr int F2_TOTAL = US_F2 + UR_F2 + 2 * W_F2;           // 10880 float2
constexpr int FL_TOTAL = 256 + 64 + 64 + 4 + 8 * 128;        // 1412 floats
constexpr int SMEM_BYTES = F2_TOTAL * 8 + FL_TOTAL * 4;      // 92688 B

__device__ __forceinline__ float redsum(float v) {
#pragma unroll
    for (int o = 16; o; o >>= 1) v += __shfl_xor_sync(FULL, v, o);
    return v;
}

// neighbor-set embed from smem table
template <int NF>
__device__ __forceinline__ void embed(const int* __restrict__ fl, const float2* __restrict__ tbl,
                                      int l, float& r0, float& r1) {
    int f = (l < NF) ? fl[l] : 0;
    float a0 = 0.f, a1 = 0.f;
#pragma unroll
    for (int j = 0; j < NF; j++) {
        int idx = __shfl_sync(FULL, f, j);
        float2 t = tbl[(j * 7 + idx) * 32 + l];
        a0 += t.x; a1 += t.y;
    }
    r0 = a0; r1 = a1;
}

// graph attention over 8 neighbors whose embeds come from the smem sub-table
template <int NF>
__device__ __forceinline__ void ga_tbl(const int* __restrict__ flist,
                                       const float2* __restrict__ tbl,
                                       const float* __restrict__ wptr,
                                       float c0, float c1, float cden,
                                       int l, float& out0, float& out1) {
    float e0[8], e1[8], cw[8];
#pragma unroll
    for (int kk = 0; kk < 8; kk++) {
        int f = (l < NF) ? flist[kk * NF + l] : 0;
        float a0 = 0.f, a1 = 0.f;
#pragma unroll
        for (int j = 0; j < NF; j++) {
            int idx = __shfl_sync(FULL, f, j);
            float2 t = tbl[(j * 7 + idx) * 32 + l];
            a0 += t.x; a1 += t.y;
        }
        e0[kk] = a0; e1[kk] = a1;
        float d  = a0 * c0 + a1 * c1;
        float nn = a0 * a0 + a1 * a1;
#pragma unroll
        for (int o = 16; o; o >>= 1) {
            d  += __shfl_xor_sync(FULL, d, o);
            nn += __shfl_xor_sync(FULL, nn, o);
        }
        cw[kk] = d / (fmaxf(sqrtf(nn), EPSC) * cden);
    }
    float m = cw[0];
#pragma unroll
    for (int kk = 1; kk < 8; kk++) m = fmaxf(m, cw[kk]);
    float s = 0.f;
#pragma unroll
    for (int kk = 0; kk < 8; kk++) { cw[kk] = __expf(cw[kk] - m); s += cw[kk]; }
    float inv = 1.f / s;
    float o0 = 0.f, o1 = 0.f;
#pragma unroll
    for (int kk = 0; kk < 8; kk++) {
        float w = wptr[kk];
        float sc = cw[kk] * inv;
        o0 += fmaxf(e0[kk] * w, 0.f) * sc;
        o1 += fmaxf(e1[kk] * w, 0.f) * sc;
    }
    out0 = o0; out1 = o1;
}

// graph attention where neighbor embeds are already in registers
__device__ __forceinline__ void ga_reg(const float (&e0)[8], const float (&e1)[8],
                                       const float* __restrict__ wptr,
                                       float c0, float c1, float cden,
                                       int l, float& out0, float& out1) {
    float cw[8];
#pragma unroll
    for (int kk = 0; kk < 8; kk++) {
        float d  = e0[kk] * c0 + e1[kk] * c1;
        float nn = e0[kk] * e0[kk] + e1[kk] * e1[kk];
#pragma unroll
        for (int o = 16; o; o >>= 1) {
            d  += __shfl_xor_sync(FULL, d, o);
            nn += __shfl_xor_sync(FULL, nn, o);
        }
        cw[kk] = d / (fmaxf(sqrtf(nn), EPSC) * cden);
    }
    float m = cw[0];
#pragma unroll
    for (int kk = 1; kk < 8; kk++) m = fmaxf(m, cw[kk]);
    float s = 0.f;
#pragma unroll
    for (int kk = 0; kk < 8; kk++) { cw[kk] = __expf(cw[kk] - m); s += cw[kk]; }
    float inv = 1.f / s;
    float o0 = 0.f, o1 = 0.f;
#pragma unroll
    for (int kk = 0; kk < 8; kk++) {
        float w = wptr[kk];
        float sc = cw[kk] * inv;
        o0 += fmaxf(e0[kk] * w, 0.f) * sc;
        o1 += fmaxf(e1[kk] * w, 0.f) * sc;
    }
    out0 = o0; out1 = o1;
}

// relu(W (128->64) @ x + b), x = (x0 at d=l, x1 at d=l+32, x2 at d=64+l, x3 at d=96+l)
__device__ __forceinline__ void lin128(const float2* __restrict__ W, const float* __restrict__ bvec,
                                       float* __restrict__ myx, int l,
                                       float x0, float x1, float x2, float x3,
                                       float& r0, float& r1) {
    myx[l] = x0; myx[32 + l] = x1; myx[64 + l] = x2; myx[96 + l] = x3;
    __syncwarp();
    float a0 = bvec[l], a1 = bvec[32 + l];
#pragma unroll
    for (int i = 0; i < 128; i++) {
        float xi = myx[i];
        float2 w = W[i * 32 + l];
        a0 += w.x * xi;
        a1 += w.y * xi;
    }
    __syncwarp();
    r0 = fmaxf(a0, 0.f);
    r1 = fmaxf(a1, 0.f);
}

__global__ void __launch_bounds__(256, 2)
gcn_kernel(const int* __restrict__ user_f, const int* __restrict__ url_f,
           const int* __restrict__ u1u_f, const float* __restrict__ u1u_w,
           const int* __restrict__ u1url_f, const float* __restrict__ u1url_w,
           const int* __restrict__ u2u_f, const float* __restrict__ u2u_w,
           const int* __restrict__ u2url_f, const float* __restrict__ u2url_w,
           const int* __restrict__ url2u_f, const float* __restrict__ url2u_w,
           const int* __restrict__ url2url_f, const float* __restrict__ url2url_w,
           const float* __restrict__ user_table, const float* __restrict__ url_table,
           const float* __restrict__ W2, const float* __restrict__ b2,
           const float* __restrict__ W1, const float* __restrict__ b1,
           const float* __restrict__ Wo, const float* __restrict__ bo,
           float* __restrict__ out, int N) {
    extern __shared__ float2 sm2[];
    float2* us = sm2;
    float2* ur = us + US_F2;
    float2* w2 = ur + UR_F2;
    float2* w1 = w2 + W_F2;
    float* flr  = (float*)(w1 + W_F2);
    float* wo   = flr;         // 256
    float* b2s  = flr + 256;   // 64
    float* b1s  = flr + 320;   // 64
    float* bos  = flr + 384;   // 4
    float* xbuf = flr + 388;   // 8*128

    int tid = threadIdx.x;

    // ---- load sub-tables & weights into smem ----
    for (int i = tid; i < 49 * 64; i += blockDim.x) {
        int e = i >> 6, q = i & 63, ln = q >> 1, c = q & 1;
        int j = e / 7, v = e % 7;
        ((float*)us)[i] = user_table[(UOFF[j] + v) * 64 + ln + 32 * c];
    }
    for (int i = tid; i < 35 * 64; i += blockDim.x) {
        int e = i >> 6, q = i & 63, ln = q >> 1, c = q & 1;
        int j = e / 7, v = e % 7;
        ((float*)ur)[i] = url_table[(VOFF[j] + v) * 64 + ln + 32 * c];
    }
    for (int i = tid; i < 128 * 64; i += blockDim.x) {
        int ii = i >> 6, q = i & 63, ln = q >> 1, c = q & 1;
        ((float*)w2)[i] = W2[(ln + 32 * c) * 128 + ii];
        ((float*)w1)[i] = W1[(ln + 32 * c) * 128 + ii];
    }
    for (int i = tid; i < 256; i += blockDim.x) wo[i] = Wo[i];
    if (tid < 64) { b2s[tid] = b2[tid]; b1s[tid] = b1[tid]; }
    if (tid < 2) bos[tid] = bo[tid];
    __syncthreads();

    int l   = tid & 31;
    int wrp = tid >> 5;
    float* myx = xbuf + wrp * 128;
    int gw = blockIdx.x * 8 + wrp;
    int nw = gridDim.x * 8;

    for (int n = gw; n < N; n += nw) {
        float u1url0[8], u1url1[8], u1usr0[8], u1usr1[8];

        // ---- stage A: url branch (hop2 -> hop1) ----
#pragma unroll 1
        for (int k = 0; k < 8; k++) {
            float c0, c1;
            embed<5>(u1url_f + (n * 8 + k) * 5, ur, l, c0, c1);
            float cden = fmaxf(sqrtf(redsum(c0 * c0 + c1 * c1)), EPSC);
            float a0, a1, bb0, bb1;
            ga_tbl<7>(url2u_f + (n * 8 + k) * 56, us, url2u_w + (n * 8 + k) * 8,
                      c0, c1, cden, l, a0, a1);
            ga_tbl<5>(url2url_f + (n * 8 + k) * 40, ur, url2url_w + (n * 8 + k) * 8,
                      c0, c1, cden, l, bb0, bb1);
            lin128(w2, b2s, myx, l, c0, c1, (a0 + bb0) * 0.5f, (a1 + bb1) * 0.5f,
                   u1url0[k], u1url1[k]);
        }

        // ---- stage B: user branch (hop2 -> hop1) ----
#pragma unroll 1
        for (int k = 0; k < 8; k++) {
            float c0, c1;
            embed<7>(u1u_f + (n * 8 + k) * 7, us, l, c0, c1);
            float cden = fmaxf(sqrtf(redsum(c0 * c0 + c1 * c1)), EPSC);
            float a0, a1, bb0, bb1;
            ga_tbl<7>(u2u_f + (n * 8 + k) * 56, us, u2u_w + (n * 8 + k) * 8,
                      c0, c1, cden, l, a0, a1);
            ga_tbl<5>(u2url_f + (n * 8 + k) * 40, ur, u2url_w + (n * 8 + k) * 8,
                      c0, c1, cden, l, bb0, bb1);
            lin128(w2, b2s, myx, l, c0, c1, (a0 + bb0) * 0.5f, (a1 + bb1) * 0.5f,
                   u1usr0[k], u1usr1[k]);
        }

        // ---- stage C: hop1 -> center ----
        float c0, c1;
        embed<7>(user_f + n * 7, us, l, c0, c1);
        float cden = fmaxf(sqrtf(redsum(c0 * c0 + c1 * c1)), EPSC);
        float a0, a1, bb0, bb1;
        ga_reg(u1url0, u1url1, u1url_w + n * 8, c0, c1, cden, l, a0, a1);
        ga_reg(u1usr0, u1usr1, u1u_w + n * 8, c0, c1, cden, l, bb0, bb1);
        float ue0, ue1;
        lin128(w1, b1s, myx, l, c0, c1, (a0 + bb0) * 0.5f, (a1 + bb1) * 0.5f, ue0, ue1);

        float v0, v1;
        embed<5>(url_f + n * 5, ur, l, v0, v1);

        float p0 = wo[l] * ue0 + wo[32 + l] * ue1 + wo[64 + l] * v0 + wo[96 + l] * v1;
        float p1 = wo[128 + l] * ue0 + wo[160 + l] * ue1 + wo[192 + l] * v0 + wo[224 + l] * v1;
#pragma unroll
        for (int o = 16; o; o >>= 1) {
            p0 += __shfl_xor_sync(FULL, p0, o);
            p1 += __shfl_xor_sync(FULL, p1, o);
        }
        if (l == 0) {
            p0 += bos[0]; p1 += bos[1];
            float mm = fmaxf(p0, p1);
            float z0 = __expf(p0 - mm), z1 = __expf(p1 - mm);
            float inv = 1.f / (z0 + z1);
            out[n * 2]     = z0 * inv;
            out[n * 2 + 1] = z1 * inv;
        }
    }
}

extern "C" void kernel_launch(void* const* d_in, const int* in_sizes, int n_in,
                              void* d_out, int out_size) {
    // d_in order per metadata: url_idxs(unused), user_f_list, url_f_list,
    // user_1_user_f_list, user_1_user_weight, user_1_url_f_list, user_1_url_weight,
    // user_2_user_f_list, user_2_user_weight, user_2_url_f_list, user_2_url_weight,
    // url_2_user_f_list, url_2_user_weight, url_2_url_f_list, url_2_url_weight,
    // user_table, url_table, W2, b2, W1, b1, Wo, bo
    const int*   user_f   = (const int*)d_in[1];
    const int*   url_f    = (const int*)d_in[2];
    const int*   u1u_f    = (const int*)d_in[3];
    const float* u1u_w    = (const float*)d_in[4];
    const int*   u1url_f  = (const int*)d_in[5];
    const float* u1url_w  = (const float*)d_in[6];
    const int*   u2u_f    = (const int*)d_in[7];
    const float* u2u_w    = (const float*)d_in[8];
    const int*   u2url_f  = (const int*)d_in[9];
    const float* u2url_w  = (const float*)d_in[10];
    const int*   url2u_f  = (const int*)d_in[11];
    const float* url2u_w  = (const float*)d_in[12];
    const int*   url2url_f = (const int*)d_in[13];
    const float* url2url_w = (const float*)d_in[14];
    const float* user_table = (const float*)d_in[15];
    const float* url_table  = (const float*)d_in[16];
    const float* W2 = (const float*)d_in[17];
    const float* b2 = (const float*)d_in[18];
    const float* W1 = (const float*)d_in[19];
    const float* b1 = (const float*)d_in[20];
    const float* Wo = (const float*)d_in[21];
    const float* bo = (const float*)d_in[22];
    float* out = (float*)d_out;

    int N = in_sizes[0];  // url_idxs length

    cudaFuncSetAttribute(gcn_kernel, cudaFuncAttributeMaxDynamicSharedMemorySize, SMEM_BYTES);
    int sm = 148;
    cudaDeviceGetAttribute(&sm, cudaDevAttrMultiProcessorCount, 0);
    int grid = sm * 2;

    gcn_kernel<<<grid, 256, SMEM_BYTES>>>(
        user_f, url_f, u1u_f, u1u_w, u1url_f, u1url_w,
        u2u_f, u2u_w, u2url_f, u2url_w,
        url2u_f, url2u_w, url2url_f, url2url_w,
        user_table, url_table, W2, b2, W1, b1, Wo, bo, out, N);
}

// round 2
// speedup vs baseline: 1.5348x; 1.5348x over previous
#include <cuda_runtime.h>

#define FULL 0xffffffffu

// Only rows offset_j + [0,7) of each table are reachable (feature ids < 7).
__constant__ int UOFF[7] = {0, 11577, 11588, 11599, 11610, 11621, 11642};
__constant__ int VOFF[5] = {0, 4733, 4754, 4761, 4772};

constexpr int US_F2 = 49 * 32;     // user sub-table, entry=(col*7+val), float2=(v[l],v[l+32])
constexpr int UR_F2 = 35 * 32;     // url sub-table
constexpr int W_F2  = 128 * 32;    // W2 transposed+paired
constexpr int XS_FLOATS = 8 * 128 * 8;  // per-warp x-vector staging [128][8]
constexpr int SMEM_BYTES = (US_F2 + UR_F2 + W_F2) * 8 + (256 + 64 + 64 + 4 + XS_FLOATS) * 4;

__device__ float2 W1T[128 * 32];   // [(i*32+l)] = (W1[l][i], W1[l+32][i])
__device__ unsigned int g_ctr;

__global__ void prep_kernel(const float* __restrict__ W1) {
    int i = blockIdx.x * blockDim.x + threadIdx.x;
    if (i == 0) g_ctr = 0;
    if (i < 128 * 32) {
        int col = i >> 5, l = i & 31;
        W1T[i] = make_float2(W1[l * 128 + col], W1[(l + 32) * 128 + col]);
    }
}

__device__ __forceinline__ float redsum(float v) {
#pragma unroll
    for (int o = 16; o; o >>= 1) v += __shfl_xor_sync(FULL, v, o);
    return v;
}

// dynamic-position index broadcast (pos warp-uniform)
__device__ __forceinline__ int getidx(int f0, int f1, int pos) {
    int v = (pos < 32) ? f0 : f1;
    return __shfl_sync(FULL, v, pos & 31);
}

// shared tail of graph attention: reduce 16 partials, softmax(cosine), weighted sum
__device__ __forceinline__ void ga_tail(const float (&e0)[8], const float (&e1)[8],
                                        float (&d)[8], float (&nn)[8],
                                        const float* __restrict__ wptr, float icd,
                                        float& out0, float& out1) {
#pragma unroll
    for (int o = 16; o; o >>= 1) {
#pragma unroll
        for (int kk = 0; kk < 8; kk++) {
            d[kk]  += __shfl_xor_sync(FULL, d[kk], o);
            nn[kk] += __shfl_xor_sync(FULL, nn[kk], o);
        }
    }
    float4 wA = *(const float4*)wptr;
    float4 wB = *(const float4*)(wptr + 4);
    float w[8] = {wA.x, wA.y, wA.z, wA.w, wB.x, wB.y, wB.z, wB.w};
    float cw[8];
    float s = 0.f;
#pragma unroll
    for (int kk = 0; kk < 8; kk++) {
        float r = fminf(__frsqrt_rn(nn[kk]), 1e6f);   // = 1/max(sqrt(nn),1e-6)
        cw[kk] = __expf(d[kk] * r * icd);             // cosine in [-1,1]; no max-sub needed
        s += cw[kk];
    }
    float inv = __fdividef(1.f, s);
    float o0 = 0.f, o1 = 0.f;
#pragma unroll
    for (int kk = 0; kk < 8; kk++) {
        float sc = cw[kk] * inv;
        o0 = fmaf(fmaxf(e0[kk] * w[kk], 0.f), sc, o0);
        o1 = fmaf(fmaxf(e1[kk] * w[kk], 0.f), sc, o1);
    }
    out0 = o0; out1 = o1;
}

// graph attention over 8 neighbors gathered from the smem sub-table
template <int NF>
__device__ __forceinline__ void ga_tbl(const int* __restrict__ flist,
                                       const float2* __restrict__ tbl,
                                       const float* __restrict__ wptr,
                                       float c0, float c1, float icd, int l,
                                       float& out0, float& out1) {
    int f0 = flist[l];
    int f1 = (l < 8 * NF - 32) ? flist[32 + l] : 0;
    float e0[8], e1[8], d[8], nn[8];
#pragma unroll
    for (int kk = 0; kk < 8; kk++) {
        float a0 = 0.f, a1 = 0.f;
#pragma unroll
        for (int j = 0; j < NF; j++) {
            const int pos = kk * NF + j;
            int idx = __shfl_sync(FULL, (pos < 32) ? f0 : f1, pos & 31);
            float2 t = tbl[(j * 7 + idx) * 32 + l];
            a0 += t.x; a1 += t.y;
        }
        e0[kk] = a0; e1[kk] = a1;
        d[kk]  = a0 * c0 + a1 * c1;
        nn[kk] = a0 * a0 + a1 * a1;
    }
    ga_tail(e0, e1, d, nn, wptr, icd, out0, out1);
}

// graph attention where neighbor embeds are already in registers
__device__ __forceinline__ void ga_reg(const float (&e0)[8], const float (&e1)[8],
                                       const float* __restrict__ wptr,
                                       float c0, float c1, float icd, int l,
                                       float& out0, float& out1) {
    float d[8], nn[8];
#pragma unroll
    for (int kk = 0; kk < 8; kk++) {
        d[kk]  = e0[kk] * c0 + e1[kk] * c1;
        nn[kk] = e0[kk] * e0[kk] + e1[kk] * e1[kk];
    }
    ga_tail(e0, e1, d, nn, wptr, icd, out0, out1);
}

// batched relu(W(128->64) @ x_k + b) for 8 vectors staged in xsw[128][8]
__device__ __forceinline__ void lin_b8(const float2* __restrict__ Wt,
                                       float bb0, float bb1,
                                       const float* __restrict__ xsw, int l,
                                       float (&r0)[8], float (&r1)[8]) {
    float a0[8], a1[8];
#pragma unroll
    for (int k = 0; k < 8; k++) { a0[k] = bb0; a1[k] = bb1; }
#pragma unroll 16
    for (int i = 0; i < 128; i++) {
        float4 xA = *(const float4*)(xsw + i * 8);
        float4 xB = *(const float4*)(xsw + i * 8 + 4);
        float xv[8] = {xA.x, xA.y, xA.z, xA.w, xB.x, xB.y, xB.z, xB.w};
        float2 w = Wt[i * 32 + l];
#pragma unroll
        for (int k = 0; k < 8; k++) {
            a0[k] = fmaf(w.x, xv[k], a0[k]);
            a1[k] = fmaf(w.y, xv[k], a1[k]);
        }
    }
#pragma unroll
    for (int k = 0; k < 8; k++) {
        r0[k] = fmaxf(a0[k], 0.f);
        r1[k] = fmaxf(a1[k], 0.f);
    }
}

__global__ void __launch_bounds__(256, 2)
gcn_kernel(const int* __restrict__ user_f, const int* __restrict__ url_f,
           const int* __restrict__ u1u_f, const float* __restrict__ u1u_w,
           const int* __restrict__ u1url_f, const float* __restrict__ u1url_w,
           const int* __restrict__ u2u_f, const float* __restrict__ u2u_w,
           const int* __restrict__ u2url_f, const float* __restrict__ u2url_w,
           const int* __restrict__ url2u_f, const float* __restrict__ url2u_w,
           const int* __restrict__ url2url_f, const float* __restrict__ url2url_w,
           const float* __restrict__ user_table, const float* __restrict__ url_table,
           const float* __restrict__ W2, const float* __restrict__ b2,
           const float* __restrict__ b1,
           const float* __restrict__ Wo, const float* __restrict__ bo,
           float* __restrict__ out, int N) {
    extern __shared__ float2 sm2[];
    float2* us = sm2;
    float2* ur = us + US_F2;
    float2* w2 = ur + UR_F2;
    float* flr  = (float*)(w2 + W_F2);
    float* wo   = flr;         // 256
    float* b2s  = flr + 256;   // 64
    float* b1s  = flr + 320;   // 64
    float* bos  = flr + 384;   // 4
    float* xs   = flr + 388;   // 8 warps * 128 * 8

    int tid = threadIdx.x;

    // ---- load sub-tables & weights into smem ----
    for (int i = tid; i < 49 * 64; i += blockDim.x) {
        int e = i >> 6, q = i & 63, ln = q >> 1, c = q & 1;
        int j = e / 7, v = e % 7;
        ((float*)us)[i] = user_table[(UOFF[j] + v) * 64 + ln + 32 * c];
    }
    for (int i = tid; i < 35 * 64; i += blockDim.x) {
        int e = i >> 6, q = i & 63, ln = q >> 1, c = q & 1;
        int j = e / 7, v = e % 7;
        ((float*)ur)[i] = url_table[(VOFF[j] + v) * 64 + ln + 32 * c];
    }
    for (int i = tid; i < 128 * 64; i += blockDim.x) {
        int ii = i >> 6, q = i & 63, ln = q >> 1, c = q & 1;
        ((float*)w2)[i] = W2[(ln + 32 * c) * 128 + ii];
    }
    for (int i = tid; i < 256; i += blockDim.x) wo[i] = Wo[i];
    if (tid < 64) { b2s[tid] = b2[tid]; b1s[tid] = b1[tid]; }
    if (tid < 2) bos[tid] = bo[tid];
    __syncthreads();

    int l   = tid & 31;
    int wrp = tid >> 5;
    float* xsw = xs + wrp * 1024;
    float bb20 = b2s[l], bb21 = b2s[32 + l];

    for (;;) {
        int n;
        if (l == 0) n = (int)atomicAdd(&g_ctr, 1u);
        n = __shfl_sync(FULL, n, 0);
        if (n >= N) break;

        float rA0[8], rA1[8], rB0[8], rB1[8];

        // ---- stage A: url branch (hop2 -> hop1) ----
        {
            const int* pc = u1url_f + n * 40;
            int fc0 = pc[l];
            int fc1 = (l < 8) ? pc[32 + l] : 0;
#pragma unroll 1
            for (int k = 0; k < 8; k++) {
                float c0 = 0.f, c1 = 0.f;
#pragma unroll
                for (int j = 0; j < 5; j++) {
                    int idx = getidx(fc0, fc1, k * 5 + j);
                    float2 t = ur[(j * 7 + idx) * 32 + l];
                    c0 += t.x; c1 += t.y;
                }
                float icd = fminf(__frsqrt_rn(redsum(c0 * c0 + c1 * c1)), 1e6f);
                float a0, a1, bq0, bq1;
                ga_tbl<7>(url2u_f + (n * 8 + k) * 56, us, url2u_w + (n * 8 + k) * 8,
                          c0, c1, icd, l, a0, a1);
                ga_tbl<5>(url2url_f + (n * 8 + k) * 40, ur, url2url_w + (n * 8 + k) * 8,
                          c0, c1, icd, l, bq0, bq1);
                xsw[l * 8 + k]        = c0;
                xsw[(32 + l) * 8 + k] = c1;
                xsw[(64 + l) * 8 + k] = (a0 + bq0) * 0.5f;
                xsw[(96 + l) * 8 + k] = (a1 + bq1) * 0.5f;
            }
            __syncwarp();
            lin_b8(w2, bb20, bb21, xsw, l, rA0, rA1);
            __syncwarp();
        }

        // ---- stage B: user branch (hop2 -> hop1) ----
        {
            const int* pc = u1u_f + n * 56;
            int fc0 = pc[l];
            int fc1 = (l < 24) ? pc[32 + l] : 0;
#pragma unroll 1
            for (int k = 0; k < 8; k++) {
                float c0 = 0.f, c1 = 0.f;
#pragma unroll
                for (int j = 0; j < 7; j++) {
                    int idx = getidx(fc0, fc1, k * 7 + j);
                    float2 t = us[(j * 7 + idx) * 32 + l];
                    c0 += t.x; c1 += t.y;
                }
                float icd = fminf(__frsqrt_rn(redsum(c0 * c0 + c1 * c1)), 1e6f);
                float a0, a1, bq0, bq1;
                ga_tbl<7>(u2u_f + (n * 8 + k) * 56, us, u2u_w + (n * 8 + k) * 8,
                          c0, c1, icd, l, a0, a1);
                ga_tbl<5>(u2url_f + (n * 8 + k) * 40, ur, u2url_w + (n * 8 + k) * 8,
                          c0, c1, icd, l, bq0, bq1);
                xsw[l * 8 + k]        = c0;
                xsw[(32 + l) * 8 + k] = c1;
                xsw[(64 + l) * 8 + k] = (a0 + bq0) * 0.5f;
                xsw[(96 + l) * 8 + k] = (a1 + bq1) * 0.5f;
            }
            __syncwarp();
            lin_b8(w2, bb20, bb21, xsw, l, rB0, rB1);
            __syncwarp();
        }

        // ---- stage C: hop1 -> center ----
        {
            const int* pu = user_f + n * 7;
            int uf = (l < 7) ? pu[l] : 0;
            float c0 = 0.f, c1 = 0.f;
#pragma unroll
            for (int j = 0; j < 7; j++) {
                int idx = __shfl_sync(FULL, uf, j);
                float2 t = us[(j * 7 + idx) * 32 + l];
                c0 += t.x; c1 += t.y;
            }
            float icd = fminf(__frsqrt_rn(redsum(c0 * c0 + c1 * c1)), 1e6f);
            float a0, a1, bq0, bq1;
            ga_reg(rA0, rA1, u1url_w + n * 8, c0, c1, icd, l, a0, a1);
            ga_reg(rB0, rB1, u1u_w + n * 8, c0, c1, icd, l, bq0, bq1);

            xsw[l * 8]        = c0;
            xsw[(32 + l) * 8] = c1;
            xsw[(64 + l) * 8] = (a0 + bq0) * 0.5f;
            xsw[(96 + l) * 8] = (a1 + bq1) * 0.5f;
            __syncwarp();

            float s0 = b1s[l], s1 = b1s[32 + l], t0 = 0.f, t1 = 0.f;
            const float2* W1p = W1T;
#pragma unroll 16
            for (int i = 0; i < 128; i += 2) {
                float x0 = xsw[i * 8];
                float x1 = xsw[(i + 1) * 8];
                float2 w0 = __ldg(W1p + i * 32 + l);
                float2 w1 = __ldg(W1p + (i + 1) * 32 + l);
                s0 = fmaf(w0.x, x0, s0); s1 = fmaf(w0.y, x0, s1);
                t0 = fmaf(w1.x, x1, t0); t1 = fmaf(w1.y, x1, t1);
            }
            __syncwarp();
            float ue0 = fmaxf(s0 + t0, 0.f);
            float ue1 = fmaxf(s1 + t1, 0.f);

            const int* pv = url_f + n * 5;
            int vf = (l < 5) ? pv[l] : 0;
            float v0 = 0.f, v1 = 0.f;
#pragma unroll
            for (int j = 0; j < 5; j++) {
                int idx = __shfl_sync(FULL, vf, j);
                float2 t = ur[(j * 7 + idx) * 32 + l];
                v0 += t.x; v1 += t.y;
            }

            float p0 = wo[l] * ue0 + wo[32 + l] * ue1 + wo[64 + l] * v0 + wo[96 + l] * v1;
            float p1 = wo[128 + l] * ue0 + wo[160 + l] * ue1 + wo[192 + l] * v0 + wo[224 + l] * v1;
#pragma unroll
            for (int o = 16; o; o >>= 1) {
                p0 += __shfl_xor_sync(FULL, p0, o);
                p1 += __shfl_xor_sync(FULL, p1, o);
            }
            if (l == 0) {
                p0 += bos[0]; p1 += bos[1];
                float mm = fmaxf(p0, p1);
                float z0 = __expf(p0 - mm), z1 = __expf(p1 - mm);
                float inv = __fdividef(1.f, z0 + z1);
                out[n * 2]     = z0 * inv;
                out[n * 2 + 1] = z1 * inv;
            }
        }
    }
}

extern "C" void kernel_launch(void* const* d_in, const int* in_sizes, int n_in,
                              void* d_out, int out_size) {
    const int*   user_f    = (const int*)d_in[1];
    const int*   url_f     = (const int*)d_in[2];
    const int*   u1u_f     = (const int*)d_in[3];
    const float* u1u_w     = (const float*)d_in[4];
    const int*   u1url_f   = (const int*)d_in[5];
    const float* u1url_w   = (const float*)d_in[6];
    const int*   u2u_f     = (const int*)d_in[7];
    const float* u2u_w     = (const float*)d_in[8];
    const int*   u2url_f   = (const int*)d_in[9];
    const float* u2url_w   = (const float*)d_in[10];
    const int*   url2u_f   = (const int*)d_in[11];
    const float* url2u_w   = (const float*)d_in[12];
    const int*   url2url_f = (const int*)d_in[13];
    const float* url2url_w = (const float*)d_in[14];
    const float* user_table = (const float*)d_in[15];
    const float* url_table  = (const float*)d_in[16];
    const float* W2 = (const float*)d_in[17];
    const float* b2 = (const float*)d_in[18];
    const float* W1 = (const float*)d_in[19];
    const float* b1 = (const float*)d_in[20];
    const float* Wo = (const float*)d_in[21];
    const float* bo = (const float*)d_in[22];
    float* out = (float*)d_out;

    int N = in_sizes[0];

    cudaFuncSetAttribute(gcn_kernel, cudaFuncAttributeMaxDynamicSharedMemorySize, SMEM_BYTES);
    int sm = 148;
    cudaDeviceGetAttribute(&sm, cudaDevAttrMultiProcessorCount, 0);
    int grid = sm * 2;

    prep_kernel<<<16, 256>>>(W1);
    gcn_kernel<<<grid, 256, SMEM_BYTES>>>(
        user_f, url_f, u1u_f, u1u_w, u1url_f, u1url_w,
        u2u_f, u2u_w, u2url_f, u2url_w,
        url2u_f, url2u_w, url2url_f, url2url_w,
        user_table, url_table, W2, b2, b1, Wo, bo, out, N);
}

// round 3
// speedup vs baseline: 1.5359x; 1.0007x over previous
#include <cuda_runtime.h>

#define FULL 0xffffffffu

// Only rows offset_j + [0,7) of each table are reachable (feature ids < 7).
__constant__ int UOFF[7] = {0, 11577, 11588, 11599, 11610, 11621, 11642};
__constant__ int VOFF[5] = {0, 4733, 4754, 4761, 4772};

constexpr int US_F2 = 49 * 32;     // user sub-table, entry=(col*7+val), float2=(v[l],v[l+32])
constexpr int UR_F2 = 35 * 32;     // url sub-table
constexpr int W_F2  = 128 * 32;    // W2 transposed+paired
constexpr int XS_FLOATS = 8 * 128 * 8;  // per-warp x-vector staging [128][8]
constexpr int SMEM_BYTES = (US_F2 + UR_F2 + W_F2) * 8 + (256 + 64 + 64 + 4 + XS_FLOATS) * 4;

__device__ float2 W1T[128 * 32];   // [(i*32+l)] = (W1[l][i], W1[l+32][i])
__device__ unsigned int g_ctr;

__global__ void prep_kernel(const float* __restrict__ W1) {
    int i = blockIdx.x * blockDim.x + threadIdx.x;
    if (i == 0) g_ctr = 0;
    if (i < 128 * 32) {
        int col = i >> 5, l = i & 31;
        W1T[i] = make_float2(W1[l * 128 + col], W1[(l + 32) * 128 + col]);
    }
}

__device__ __forceinline__ float redsum(float v) {
#pragma unroll
    for (int o = 16; o; o >>= 1) v += __shfl_xor_sync(FULL, v, o);
    return v;
}

// dynamic-position index broadcast (pos warp-uniform)
__device__ __forceinline__ int getidx(int f0, int f1, int pos) {
    int v = (pos < 32) ? f0 : f1;
    return __shfl_sync(FULL, v, pos & 31);
}

// shared tail of graph attention: reduce 16 partials, softmax(cosine), weighted sum
__device__ __forceinline__ void ga_tail(const float (&e0)[8], const float (&e1)[8],
                                        float (&d)[8], float (&nn)[8],
                                        const float* __restrict__ wptr, float icd,
                                        float& out0, float& out1) {
#pragma unroll
    for (int o = 16; o; o >>= 1) {
#pragma unroll
        for (int kk = 0; kk < 8; kk++) {
            d[kk]  += __shfl_xor_sync(FULL, d[kk], o);
            nn[kk] += __shfl_xor_sync(FULL, nn[kk], o);
        }
    }
    float4 wA = *(const float4*)wptr;
    float4 wB = *(const float4*)(wptr + 4);
    float w[8] = {wA.x, wA.y, wA.z, wA.w, wB.x, wB.y, wB.z, wB.w};
    float cw[8];
    float s = 0.f;
#pragma unroll
    for (int kk = 0; kk < 8; kk++) {
        float r = fminf(__frsqrt_rn(nn[kk]), 1e6f);   // = 1/max(sqrt(nn),1e-6)
        cw[kk] = __expf(d[kk] * r * icd);             // cosine in [-1,1]; no max-sub needed
        s += cw[kk];
    }
    float inv = __fdividef(1.f, s);
    float o0 = 0.f, o1 = 0.f;
#pragma unroll
    for (int kk = 0; kk < 8; kk++) {
        float sc = cw[kk] * inv;
        o0 = fmaf(fmaxf(e0[kk] * w[kk], 0.f), sc, o0);
        o1 = fmaf(fmaxf(e1[kk] * w[kk], 0.f), sc, o1);
    }
    out0 = o0; out1 = o1;
}

// graph attention over 8 neighbors gathered from the smem sub-table
template <int NF>
__device__ __forceinline__ void ga_tbl(const int* __restrict__ flist,
                                       const float2* __restrict__ tbl,
                                       const float* __restrict__ wptr,
                                       float c0, float c1, float icd, int l,
                                       float& out0, float& out1) {
    int f0 = flist[l];
    int f1 = (l < 8 * NF - 32) ? flist[32 + l] : 0;
    float e0[8], e1[8], d[8], nn[8];
#pragma unroll
    for (int kk = 0; kk < 8; kk++) {
        float a0 = 0.f, a1 = 0.f;
#pragma unroll
        for (int j = 0; j < NF; j++) {
            const int pos = kk * NF + j;
            int idx = __shfl_sync(FULL, (pos < 32) ? f0 : f1, pos & 31);
            float2 t = tbl[(j * 7 + idx) * 32 + l];
            a0 += t.x; a1 += t.y;
        }
        e0[kk] = a0; e1[kk] = a1;
        d[kk]  = a0 * c0 + a1 * c1;
        nn[kk] = a0 * a0 + a1 * a1;
    }
    ga_tail(e0, e1, d, nn, wptr, icd, out0, out1);
}

// graph attention where neighbor embeds are already in registers
__device__ __forceinline__ void ga_reg(const float (&e0)[8], const float (&e1)[8],
                                       const float* __restrict__ wptr,
                                       float c0, float c1, float icd, int l,
                                       float& out0, float& out1) {
    float d[8], nn[8];
#pragma unroll
    for (int kk = 0; kk < 8; kk++) {
        d[kk]  = e0[kk] * c0 + e1[kk] * c1;
        nn[kk] = e0[kk] * e0[kk] + e1[kk] * e1[kk];
    }
    ga_tail(e0, e1, d, nn, wptr, icd, out0, out1);
}

// batched relu(W(128->64) @ x_k + b) for 8 vectors staged in xsw[128][8]
__device__ __forceinline__ void lin_b8(const float2* __restrict__ Wt,
                                       float bb0, float bb1,
                                       const float* __restrict__ xsw, int l,
                                       float (&r0)[8], float (&r1)[8]) {
    float a0[8], a1[8];
#pragma unroll
    for (int k = 0; k < 8; k++) { a0[k] = bb0; a1[k] = bb1; }
#pragma unroll 16
    for (int i = 0; i < 128; i++) {
        float4 xA = *(const float4*)(xsw + i * 8);
        float4 xB = *(const float4*)(xsw + i * 8 + 4);
        float xv[8] = {xA.x, xA.y, xA.z, xA.w, xB.x, xB.y, xB.z, xB.w};
        float2 w = Wt[i * 32 + l];
#pragma unroll
        for (int k = 0; k < 8; k++) {
            a0[k] = fmaf(w.x, xv[k], a0[k]);
            a1[k] = fmaf(w.y, xv[k], a1[k]);
        }
    }
#pragma unroll
    for (int k = 0; k < 8; k++) {
        r0[k] = fmaxf(a0[k], 0.f);
        r1[k] = fmaxf(a1[k], 0.f);
    }
}

__global__ void __launch_bounds__(256, 2)
gcn_kernel(const int* __restrict__ user_f, const int* __restrict__ url_f,
           const int* __restrict__ u1u_f, const float* __restrict__ u1u_w,
           const int* __restrict__ u1url_f, const float* __restrict__ u1url_w,
           const int* __restrict__ u2u_f, const float* __restrict__ u2u_w,
           const int* __restrict__ u2url_f, const float* __restrict__ u2url_w,
           const int* __restrict__ url2u_f, const float* __restrict__ url2u_w,
           const int* __restrict__ url2url_f, const float* __restrict__ url2url_w,
           const float* __restrict__ user_table, const float* __restrict__ url_table,
           const float* __restrict__ W2, const float* __restrict__ b2,
           const float* __restrict__ b1,
           const float* __restrict__ Wo, const float* __restrict__ bo,
           float* __restrict__ out, int N) {
    extern __shared__ float2 sm2[];
    float2* us = sm2;
    float2* ur = us + US_F2;
    float2* w2 = ur + UR_F2;
    float* flr  = (float*)(w2 + W_F2);
    float* wo   = flr;         // 256
    float* b2s  = flr + 256;   // 64
    float* b1s  = flr + 320;   // 64
    float* bos  = flr + 384;   // 4
    float* xs   = flr + 388;   // 8 warps * 128 * 8

    int tid = threadIdx.x;

    // ---- load sub-tables & weights into smem ----
    for (int i = tid; i < 49 * 64; i += blockDim.x) {
        int e = i >> 6, q = i & 63, ln = q >> 1, c = q & 1;
        int j = e / 7, v = e % 7;
        ((float*)us)[i] = user_table[(UOFF[j] + v) * 64 + ln + 32 * c];
    }
    for (int i = tid; i < 35 * 64; i += blockDim.x) {
        int e = i >> 6, q = i & 63, ln = q >> 1, c = q & 1;
        int j = e / 7, v = e % 7;
        ((float*)ur)[i] = url_table[(VOFF[j] + v) * 64 + ln + 32 * c];
    }
    for (int i = tid; i < 128 * 64; i += blockDim.x) {
        int ii = i >> 6, q = i & 63, ln = q >> 1, c = q & 1;
        ((float*)w2)[i] = W2[(ln + 32 * c) * 128 + ii];
    }
    for (int i = tid; i < 256; i += blockDim.x) wo[i] = Wo[i];
    if (tid < 64) { b2s[tid] = b2[tid]; b1s[tid] = b1[tid]; }
    if (tid < 2) bos[tid] = bo[tid];
    __syncthreads();

    int l   = tid & 31;
    int wrp = tid >> 5;
    float* xsw = xs + wrp * 1024;
    float bb20 = b2s[l], bb21 = b2s[32 + l];

    for (;;) {
        int n;
        if (l == 0) n = (int)atomicAdd(&g_ctr, 1u);
        n = __shfl_sync(FULL, n, 0);
        if (n >= N) break;

        float rA0[8], rA1[8], rB0[8], rB1[8];

        // ---- stage A: url branch (hop2 -> hop1) ----
        {
            const int* pc = u1url_f + n * 40;
            int fc0 = pc[l];
            int fc1 = (l < 8) ? pc[32 + l] : 0;
#pragma unroll 1
            for (int k = 0; k < 8; k++) {
                float c0 = 0.f, c1 = 0.f;
#pragma unroll
                for (int j = 0; j < 5; j++) {
                    int idx = getidx(fc0, fc1, k * 5 + j);
                    float2 t = ur[(j * 7 + idx) * 32 + l];
                    c0 += t.x; c1 += t.y;
                }
                float icd = fminf(__frsqrt_rn(redsum(c0 * c0 + c1 * c1)), 1e6f);
                float a0, a1, bq0, bq1;
                ga_tbl<7>(url2u_f + (n * 8 + k) * 56, us, url2u_w + (n * 8 + k) * 8,
                          c0, c1, icd, l, a0, a1);
                ga_tbl<5>(url2url_f + (n * 8 + k) * 40, ur, url2url_w + (n * 8 + k) * 8,
                          c0, c1, icd, l, bq0, bq1);
                xsw[l * 8 + k]        = c0;
                xsw[(32 + l) * 8 + k] = c1;
                xsw[(64 + l) * 8 + k] = (a0 + bq0) * 0.5f;
                xsw[(96 + l) * 8 + k] = (a1 + bq1) * 0.5f;
            }
            __syncwarp();
            lin_b8(w2, bb20, bb21, xsw, l, rA0, rA1);
            __syncwarp();
        }

        // ---- stage B: user branch (hop2 -> hop1) ----
        {
            const int* pc = u1u_f + n * 56;
            int fc0 = pc[l];
            int fc1 = (l < 24) ? pc[32 + l] : 0;
#pragma unroll 1
            for (int k = 0; k < 8; k++) {
                float c0 = 0.f, c1 = 0.f;
#pragma unroll
                for (int j = 0; j < 7; j++) {
                    int idx = getidx(fc0, fc1, k * 7 + j);
                    float2 t = us[(j * 7 + idx) * 32 + l];
                    c0 += t.x; c1 += t.y;
                }
                float icd = fminf(__frsqrt_rn(redsum(c0 * c0 + c1 * c1)), 1e6f);
                float a0, a1, bq0, bq1;
                ga_tbl<7>(u2u_f + (n * 8 + k) * 56, us, u2u_w + (n * 8 + k) * 8,
                          c0, c1, icd, l, a0, a1);
                ga_tbl<5>(u2url_f + (n * 8 + k) * 40, ur, u2url_w + (n * 8 + k) * 8,
                          c0, c1, icd, l, bq0, bq1);
                xsw[l * 8 + k]        = c0;
                xsw[(32 + l) * 8 + k] = c1;
                xsw[(64 + l) * 8 + k] = (a0 + bq0) * 0.5f;
                xsw[(96 + l) * 8 + k] = (a1 + bq1) * 0.5f;
            }
            __syncwarp();
            lin_b8(w2, bb20, bb21, xsw, l, rB0, rB1);
            __syncwarp();
        }

        // ---- stage C: hop1 -> center ----
        {
            const int* pu = user_f + n * 7;
            int uf = (l < 7) ? pu[l] : 0;
            float c0 = 0.f, c1 = 0.f;
#pragma unroll
            for (int j = 0; j < 7; j++) {
                int idx = __shfl_sync(FULL, uf, j);
                float2 t = us[(j * 7 + idx) * 32 + l];
                c0 += t.x; c1 += t.y;
            }
            float icd = fminf(__frsqrt_rn(redsum(c0 * c0 + c1 * c1)), 1e6f);
            float a0, a1, bq0, bq1;
            ga_reg(rA0, rA1, u1url_w + n * 8, c0, c1, icd, l, a0, a1);
            ga_reg(rB0, rB1, u1u_w + n * 8, c0, c1, icd, l, bq0, bq1);

            xsw[l * 8]        = c0;
            xsw[(32 + l) * 8] = c1;
            xsw[(64 + l) * 8] = (a0 + bq0) * 0.5f;
            xsw[(96 + l) * 8] = (a1 + bq1) * 0.5f;
            __syncwarp();

            float s0 = b1s[l], s1 = b1s[32 + l], t0 = 0.f, t1 = 0.f;
            const float2* W1p = W1T;
#pragma unroll 16
            for (int i = 0; i < 128; i += 2) {
                float x0 = xsw[i * 8];
                float x1 = xsw[(i + 1) * 8];
                float2 w0 = __ldg(W1p + i * 32 + l);
                float2 w1 = __ldg(W1p + (i + 1) * 32 + l);
                s0 = fmaf(w0.x, x0, s0); s1 = fmaf(w0.y, x0, s1);
                t0 = fmaf(w1.x, x1, t0); t1 = fmaf(w1.y, x1, t1);
            }
            __syncwarp();
            float ue0 = fmaxf(s0 + t0, 0.f);
            float ue1 = fmaxf(s1 + t1, 0.f);

            const int* pv = url_f + n * 5;
            int vf = (l < 5) ? pv[l] : 0;
            float v0 = 0.f, v1 = 0.f;
#pragma unroll
            for (int j = 0; j < 5; j++) {
                int idx = __shfl_sync(FULL, vf, j);
                float2 t = ur[(j * 7 + idx) * 32 + l];
                v0 += t.x; v1 += t.y;
            }

            float p0 = wo[l] * ue0 + wo[32 + l] * ue1 + wo[64 + l] * v0 + wo[96 + l] * v1;
            float p1 = wo[128 + l] * ue0 + wo[160 + l] * ue1 + wo[192 + l] * v0 + wo[224 + l] * v1;
#pragma unroll
            for (int o = 16; o; o >>= 1) {
                p0 += __shfl_xor_sync(FULL, p0, o);
                p1 += __shfl_xor_sync(FULL, p1, o);
            }
            if (l == 0) {
                p0 += bos[0]; p1 += bos[1];
                float mm = fmaxf(p0, p1);
                float z0 = __expf(p0 - mm), z1 = __expf(p1 - mm);
                float inv = __fdividef(1.f, z0 + z1);
                out[n * 2]     = z0 * inv;
                out[n * 2 + 1] = z1 * inv;
            }
        }
    }
}

extern "C" void kernel_launch(void* const* d_in, const int* in_sizes, int n_in,
                              void* d_out, int out_size) {
    const int*   user_f    = (const int*)d_in[1];
    const int*   url_f     = (const int*)d_in[2];
    const int*   u1u_f     = (const int*)d_in[3];
    const float* u1u_w     = (const float*)d_in[4];
    const int*   u1url_f   = (const int*)d_in[5];
    const float* u1url_w   = (const float*)d_in[6];
    const int*   u2u_f     = (const int*)d_in[7];
    const float* u2u_w     = (const float*)d_in[8];
    const int*   u2url_f   = (const int*)d_in[9];
    const float* u2url_w   = (const float*)d_in[10];
    const int*   url2u_f   = (const int*)d_in[11];
    const float* url2u_w   = (const float*)d_in[12];
    const int*   url2url_f = (const int*)d_in[13];
    const float* url2url_w = (const float*)d_in[14];
    const float* user_table = (const float*)d_in[15];
    const float* url_table  = (const float*)d_in[16];
    const float* W2 = (const float*)d_in[17];
    const float* b2 = (const float*)d_in[18];
    const float* W1 = (const float*)d_in[19];
    const float* b1 = (const float*)d_in[20];
    const float* Wo = (const float*)d_in[21];
    const float* bo = (const float*)d_in[22];
    float* out = (float*)d_out;

    int N = in_sizes[0];

    cudaFuncSetAttribute(gcn_kernel, cudaFuncAttributeMaxDynamicSharedMemorySize, SMEM_BYTES);
    int sm = 148;
    cudaDeviceGetAttribute(&sm, cudaDevAttrMultiProcessorCount, 0);
    int grid = sm * 2;

    prep_kernel<<<16, 256>>>(W1);
    gcn_kernel<<<grid, 256, SMEM_BYTES>>>(
        user_f, url_f, u1u_f, u1u_w, u1url_f, u1url_w,
        u2u_f, u2u_w, u2url_f, u2url_w,
        url2u_f, url2u_w, url2url_f, url2url_w,
        user_table, url_table, W2, b2, b1, Wo, bo, out, N);
}

// round 5
// speedup vs baseline: 1.8008x; 1.1724x over previous
#include <cuda_runtime.h>
#include <cstdint>

#define FULL 0xffffffffu

__constant__ int UOFF[7] = {0, 11577, 11588, 11599, 11610, 11621, 11642};
__constant__ int VOFF[5] = {0, 4733, 4754, 4761, 4772};

constexpr int NWARP = 16;
constexpr int XS_STRIDE = 9;
constexpr int XS_FLOATS = 128 * XS_STRIDE;   // 1152 per warp
constexpr int YA_FLOATS = 64 * 8;            // 512 per warp
constexpr int AW_FLOATS = 64 * 32 * 4;       // 8192 floats (64 frags x 32 lanes x float4)
constexpr int US_FLOATS = 49 * 64;
constexpr int UR_FLOATS = 35 * 64;
constexpr int SMEM_FLOATS = 2 * AW_FLOATS + US_FLOATS + UR_FLOATS
                          + NWARP * (XS_FLOATS + YA_FLOATS);
constexpr int SMEM_BYTES = SMEM_FLOATS * 4;  // 193536

__device__ float2 W1T[128 * 32];   // [(i*32+l)] = (W1[l][i], W1[l+32][i])
__device__ unsigned int g_ctr;

__global__ void prep_kernel(const float* __restrict__ W1) {
    int i = blockIdx.x * blockDim.x + threadIdx.x;
    if (i == 0) g_ctr = 0;
    if (i < 128 * 32) {
        int col = i >> 5, l = i & 31;
        W1T[i] = make_float2(W1[l * 128 + col], W1[(l + 32) * 128 + col]);
    }
}

__device__ __forceinline__ float bfly_add(float v) {
#pragma unroll
    for (int o = 16; o; o >>= 1) v += __shfl_xor_sync(FULL, v, o);
    return v;
}
__device__ __forceinline__ float tf32r(float x) {
    float r; asm("cvt.rna.tf32.f32 %0, %1;" : "=f"(r) : "f"(x)); return r;
}
__device__ __forceinline__ void addp(unsigned long long& a, unsigned long long b) {
    asm("add.rn.f32x2 %0, %0, %1;" : "+l"(a) : "l"(b));
}
__device__ __forceinline__ unsigned long long pack2(float x, float y) {
    unsigned long long r;
    asm("mov.b64 %0, {%1, %2};" : "=l"(r) : "f"(x), "f"(y));
    return r;
}
__device__ __forceinline__ float lo32(unsigned long long v) { return __uint_as_float((unsigned)v); }
__device__ __forceinline__ float hi32(unsigned long long v) { return __uint_as_float((unsigned)(v >> 32)); }

__device__ __forceinline__ void mma8(float (&c)[4], const uint4& a, unsigned b0, unsigned b1) {
    asm volatile("mma.sync.aligned.m16n8k8.row.col.f32.tf32.tf32.f32 "
                 "{%0,%1,%2,%3},{%4,%5,%6,%7},{%8,%9},{%0,%1,%2,%3};"
                 : "+f"(c[0]), "+f"(c[1]), "+f"(c[2]), "+f"(c[3])
                 : "r"(a.x), "r"(a.y), "r"(a.z), "r"(a.w), "r"(b0), "r"(b1));
}

// softmax(cosine) + weighted relu-sum over 8 neighbors.
// (d,nn) pairs reduced with packed-f32x2 butterflies (3 instr/pair/step).
__device__ __forceinline__ void ga_tail(const float (&e0)[8], const float (&e1)[8],
                                        float (&d)[8], float (&nn)[8],
                                        const float* __restrict__ wptr, float icd,
                                        float& out0, float& out1) {
    unsigned long long p[8];
#pragma unroll
    for (int kk = 0; kk < 8; kk++) p[kk] = pack2(d[kk], nn[kk]);
#pragma unroll
    for (int o = 16; o; o >>= 1) {
#pragma unroll
        for (int kk = 0; kk < 8; kk++) {
            unsigned long long q = __shfl_xor_sync(FULL, p[kk], o);
            addp(p[kk], q);
        }
    }
    float4 wA = *(const float4*)wptr;
    float4 wB = *(const float4*)(wptr + 4);
    float w[8] = {wA.x, wA.y, wA.z, wA.w, wB.x, wB.y, wB.z, wB.w};
    float cw[8];
    float s = 0.f;
#pragma unroll
    for (int kk = 0; kk < 8; kk++) {
        float r = fminf(__frsqrt_rn(hi32(p[kk])), 1e6f);   // = 1/max(sqrt(nn),1e-6)
        cw[kk] = __expf(lo32(p[kk]) * r * icd);            // cosine in [-1,1]; safe
        s += cw[kk];
    }
    float inv = __fdividef(1.f, s);
    float o0 = 0.f, o1 = 0.f;
#pragma unroll
    for (int kk = 0; kk < 8; kk++) {
        float sc = cw[kk] * inv;
        o0 = fmaf(fmaxf(e0[kk] * w[kk], 0.f), sc, o0);
        o1 = fmaf(fmaxf(e1[kk] * w[kk], 0.f), sc, o1);
    }
    out0 = o0; out1 = o1;
}

// graph attention over 8 neighbors gathered from a smem sub-table (tbB = base + l*8)
template <int NF>
__device__ __forceinline__ void ga_tbl(const int* __restrict__ flist,
                                       const char* tbB,
                                       const float* __restrict__ wptr,
                                       float c0, float c1, float icd, int l,
                                       float& out0, float& out1) {
    int f0 = flist[l] << 8;
    int f1 = (l < 8 * NF - 32) ? (flist[32 + l] << 8) : 0;
    float e0[8], e1[8], d[8], nn[8];
#pragma unroll
    for (int kk = 0; kk < 8; kk++) {
        unsigned long long acc = 0;
#pragma unroll
        for (int j = 0; j < NF; j++) {
            const int pos = kk * NF + j;
            int off = __shfl_sync(FULL, (pos < 32) ? f0 : f1, pos & 31);
            addp(acc, *(const unsigned long long*)(tbB + off + j * 1792));
        }
        float a0 = lo32(acc), a1 = hi32(acc);
        e0[kk] = a0; e1[kk] = a1;
        d[kk]  = fmaf(a1, c1, a0 * c0);
        nn[kk] = fmaf(a1, a1, a0 * a0);
    }
    ga_tail(e0, e1, d, nn, wptr, icd, out0, out1);
}

__device__ __forceinline__ void ga_reg(const float (&e0)[8], const float (&e1)[8],
                                       const float* __restrict__ wptr,
                                       float c0, float c1, float icd,
                                       float& out0, float& out1) {
    float d[8], nn[8];
#pragma unroll
    for (int kk = 0; kk < 8; kk++) {
        d[kk]  = fmaf(e1[kk], c1, e0[kk] * c0);
        nn[kk] = fmaf(e1[kk], e1[kk], e0[kk] * e0[kk]);
    }
    ga_tail(e0, e1, d, nn, wptr, icd, out0, out1);
}

// relu(W2(64x128) @ X[128x8] + b2) via 3xTF32 mma; Y[64][8] -> ybuf rows stride YS
template <int YS>
__device__ __forceinline__ void lin_mma(const uint4* __restrict__ AWhi,
                                        const uint4* __restrict__ AWlo,
                                        const float* __restrict__ xsw,
                                        float* __restrict__ ybuf,
                                        const float (&bA)[4], const float (&bB)[4],
                                        int lane) {
    int g = lane >> 2, tg = lane & 3;
    float acc[4][4];
#pragma unroll
    for (int m = 0; m < 4; m++) {
        acc[m][0] = bA[m]; acc[m][1] = bA[m];
        acc[m][2] = bB[m]; acc[m][3] = bB[m];
    }
#pragma unroll 2
    for (int kt = 0; kt < 16; kt++) {
        float xa = xsw[(8 * kt + tg) * XS_STRIDE + g];
        float xb = xsw[(8 * kt + tg + 4) * XS_STRIDE + g];
        float ha = tf32r(xa), hb = tf32r(xb);
        unsigned bh0 = __float_as_uint(ha), bh1 = __float_as_uint(hb);
        unsigned bl0 = __float_as_uint(xa - ha), bl1 = __float_as_uint(xb - hb);
        const uint4* ph = AWhi + kt * 32 + lane;
        const uint4* pl = AWlo + kt * 32 + lane;
#pragma unroll
        for (int m = 0; m < 4; m++) {
            uint4 ah = ph[m * 16 * 32];
            uint4 al = pl[m * 16 * 32];
            mma8(acc[m], ah, bh0, bh1);
            mma8(acc[m], ah, bl0, bl1);
            mma8(acc[m], al, bh0, bh1);
        }
    }
    __syncwarp();
#pragma unroll
    for (int m = 0; m < 4; m++) {
        ybuf[(16 * m + g) * YS + 2 * tg]         = fmaxf(acc[m][0], 0.f);
        ybuf[(16 * m + g) * YS + 2 * tg + 1]     = fmaxf(acc[m][1], 0.f);
        ybuf[(16 * m + g + 8) * YS + 2 * tg]     = fmaxf(acc[m][2], 0.f);
        ybuf[(16 * m + g + 8) * YS + 2 * tg + 1] = fmaxf(acc[m][3], 0.f);
    }
    __syncwarp();
}

__global__ void __launch_bounds__(512, 1)
gcn_kernel(const int* __restrict__ user_f, const int* __restrict__ url_f,
           const int* __restrict__ u1u_f, const float* __restrict__ u1u_w,
           const int* __restrict__ u1url_f, const float* __restrict__ u1url_w,
           const int* __restrict__ u2u_f, const float* __restrict__ u2u_w,
           const int* __restrict__ u2url_f, const float* __restrict__ u2url_w,
           const int* __restrict__ url2u_f, const float* __restrict__ url2u_w,
           const int* __restrict__ url2url_f, const float* __restrict__ url2url_w,
           const float* __restrict__ user_table, const float* __restrict__ url_table,
           const float* __restrict__ W2, const float* __restrict__ b2,
           const float* __restrict__ b1,
           const float* __restrict__ Wo, const float* __restrict__ bo,
           float* __restrict__ out, int N) {
    extern __shared__ float smf[];
    float* AWhiF = smf;
    float* AWloF = smf + AW_FLOATS;
    float* usF   = smf + 2 * AW_FLOATS;
    float* urF   = usF + US_FLOATS;
    float* xsAll = urF + UR_FLOATS;
    float* yaAll = xsAll + NWARP * XS_FLOATS;

    int tid = threadIdx.x;

    // ---- W2 A-fragments, hi/lo tf32 split (frag fid = m*16+kt) ----
    for (int i = tid; i < 2048; i += 512) {
        int fid = i >> 5, ln = i & 31;
        int m = fid >> 4, kt = fid & 15;
        int g = ln >> 2, tg = ln & 3;
        int r0 = 16 * m + g, r1 = r0 + 8, q0 = 8 * kt + tg, q1 = q0 + 4;
        float v0 = W2[r0 * 128 + q0], v1 = W2[r1 * 128 + q0];
        float v2 = W2[r0 * 128 + q1], v3 = W2[r1 * 128 + q1];
        float h0 = tf32r(v0), h1 = tf32r(v1), h2 = tf32r(v2), h3 = tf32r(v3);
        ((float4*)AWhiF)[fid * 32 + ln] = make_float4(h0, h1, h2, h3);
        ((float4*)AWloF)[fid * 32 + ln] = make_float4(v0 - h0, v1 - h1, v2 - h2, v3 - h3);
    }
    // ---- embedding sub-tables: entry e=(col*7+val), lane-pair layout ----
    for (int i = tid; i < 49 * 64; i += 512) {
        int e = i >> 6, q = i & 63, ln = q >> 1, c = q & 1;
        int j = e / 7, v = e % 7;
        usF[i] = user_table[(UOFF[j] + v) * 64 + ln + 32 * c];
    }
    for (int i = tid; i < 35 * 64; i += 512) {
        int e = i >> 6, q = i & 63, ln = q >> 1, c = q & 1;
        int j = e / 7, v = e % 7;
        urF[i] = url_table[(VOFF[j] + v) * 64 + ln + 32 * c];
    }
    __syncthreads();

    int l   = tid & 31;
    int wrp = tid >> 5;
    float* xsw = xsAll + wrp * XS_FLOATS;
    float* yAw = yaAll + wrp * YA_FLOATS;
    const char* usB = (const char*)usF + (l << 3);
    const char* urB = (const char*)urF + (l << 3);
    const uint4* AWhi = (const uint4*)AWhiF;
    const uint4* AWlo = (const uint4*)AWloF;

    int g = l >> 2;
    float bA[4], bB[4];
#pragma unroll
    for (int m = 0; m < 4; m++) { bA[m] = __ldg(b2 + 16 * m + g); bB[m] = __ldg(b2 + 16 * m + 8 + g); }
    float b10 = __ldg(b1 + l), b11 = __ldg(b1 + 32 + l);
    float wo0 = __ldg(Wo + l),       wo1 = __ldg(Wo + 32 + l);
    float wo2 = __ldg(Wo + 64 + l),  wo3 = __ldg(Wo + 96 + l);
    float wo4 = __ldg(Wo + 128 + l), wo5 = __ldg(Wo + 160 + l);
    float wo6 = __ldg(Wo + 192 + l), wo7 = __ldg(Wo + 224 + l);
    float bo0 = __ldg(bo), bo1 = __ldg(bo + 1);

    for (;;) {
        int n;
        if (l == 0) n = (int)atomicAdd(&g_ctr, 1u);
        n = __shfl_sync(FULL, n, 0);
        if (n >= N) break;

        // ---- stage A: url branch -> yA ----
        {
            const int* pc = u1url_f + n * 40;
            int fc0 = pc[l] << 8;
            int fc1 = (l < 8) ? (pc[32 + l] << 8) : 0;
#pragma unroll 1
            for (int k = 0; k < 8; k++) {
                unsigned long long cacc = 0;
#pragma unroll
                for (int j = 0; j < 5; j++) {
                    const int pos = k * 5 + j;
                    int off = __shfl_sync(FULL, (pos < 32) ? fc0 : fc1, pos & 31);
                    addp(cacc, *(const unsigned long long*)(urB + off + j * 1792));
                }
                float c0 = lo32(cacc), c1 = hi32(cacc);
                float icd = fminf(__frsqrt_rn(bfly_add(fmaf(c1, c1, c0 * c0))), 1e6f);
                float a0, a1, q0, q1;
                ga_tbl<7>(url2u_f + (n * 8 + k) * 56, usB, url2u_w + (n * 8 + k) * 8,
                          c0, c1, icd, l, a0, a1);
                ga_tbl<5>(url2url_f + (n * 8 + k) * 40, urB, url2url_w + (n * 8 + k) * 8,
                          c0, c1, icd, l, q0, q1);
                xsw[l * XS_STRIDE + k]        = c0;
                xsw[(32 + l) * XS_STRIDE + k] = c1;
                xsw[(64 + l) * XS_STRIDE + k] = (a0 + q0) * 0.5f;
                xsw[(96 + l) * XS_STRIDE + k] = (a1 + q1) * 0.5f;
            }
            __syncwarp();
            lin_mma<8>(AWhi, AWlo, xsw, yAw, bA, bB, l);
        }

        // ---- stage B: user branch -> regs ----
        float eB0[8], eB1[8];
        {
            const int* pc = u1u_f + n * 56;
            int fc0 = pc[l] << 8;
            int fc1 = (l < 24) ? (pc[32 + l] << 8) : 0;
#pragma unroll 1
            for (int k = 0; k < 8; k++) {
                unsigned long long cacc = 0;
#pragma unroll
                for (int j = 0; j < 7; j++) {
                    const int pos = k * 7 + j;
                    int off = __shfl_sync(FULL, (pos < 32) ? fc0 : fc1, pos & 31);
                    addp(cacc, *(const unsigned long long*)(usB + off + j * 1792));
                }
                float c0 = lo32(cacc), c1 = hi32(cacc);
                float icd = fminf(__frsqrt_rn(bfly_add(fmaf(c1, c1, c0 * c0))), 1e6f);
                float a0, a1, q0, q1;
                ga_tbl<7>(u2u_f + (n * 8 + k) * 56, usB, u2u_w + (n * 8 + k) * 8,
                          c0, c1, icd, l, a0, a1);
                ga_tbl<5>(u2url_f + (n * 8 + k) * 40, urB, u2url_w + (n * 8 + k) * 8,
                          c0, c1, icd, l, q0, q1);
                xsw[l * XS_STRIDE + k]        = c0;
                xsw[(32 + l) * XS_STRIDE + k] = c1;
                xsw[(64 + l) * XS_STRIDE + k] = (a0 + q0) * 0.5f;
                xsw[(96 + l) * XS_STRIDE + k] = (a1 + q1) * 0.5f;
            }
            __syncwarp();
            lin_mma<XS_STRIDE>(AWhi, AWlo, xsw, xsw, bA, bB, l);
#pragma unroll
            for (int k = 0; k < 8; k++) {
                eB0[k] = xsw[l * XS_STRIDE + k];
                eB1[k] = xsw[(32 + l) * XS_STRIDE + k];
            }
            __syncwarp();
        }

        // ---- stage C: hop1 -> center ----
        {
            int uf = (l < 7) ? (user_f[n * 7 + l] << 8) : 0;
            unsigned long long cacc = 0;
#pragma unroll
            for (int j = 0; j < 7; j++) {
                int off = __shfl_sync(FULL, uf, j);
                addp(cacc, *(const unsigned long long*)(usB + off + j * 1792));
            }
            float c0 = lo32(cacc), c1 = hi32(cacc);
            float icd = fminf(__frsqrt_rn(bfly_add(fmaf(c1, c1, c0 * c0))), 1e6f);

            float eA0[8], eA1[8];
            float4 t0 = *(const float4*)(yAw + l * 8);
            float4 t1 = *(const float4*)(yAw + l * 8 + 4);
            float4 t2 = *(const float4*)(yAw + (l + 32) * 8);
            float4 t3 = *(const float4*)(yAw + (l + 32) * 8 + 4);
            eA0[0] = t0.x; eA0[1] = t0.y; eA0[2] = t0.z; eA0[3] = t0.w;
            eA0[4] = t1.x; eA0[5] = t1.y; eA0[6] = t1.z; eA0[7] = t1.w;
            eA1[0] = t2.x; eA1[1] = t2.y; eA1[2] = t2.z; eA1[3] = t2.w;
            eA1[4] = t3.x; eA1[5] = t3.y; eA1[6] = t3.z; eA1[7] = t3.w;

            float a0, a1, q0, q1;
            ga_reg(eA0, eA1, u1url_w + n * 8, c0, c1, icd, a0, a1);
            ga_reg(eB0, eB1, u1u_w + n * 8, c0, c1, icd, q0, q1);

            xsw[l * XS_STRIDE]        = c0;
            xsw[(32 + l) * XS_STRIDE] = c1;
            xsw[(64 + l) * XS_STRIDE] = (a0 + q0) * 0.5f;
            xsw[(96 + l) * XS_STRIDE] = (a1 + q1) * 0.5f;
            __syncwarp();

            float s0 = b10, s1 = b11, u0 = 0.f, u1 = 0.f;
#pragma unroll 8
            for (int i = 0; i < 128; i += 2) {
                float x0 = xsw[i * XS_STRIDE];
                float x1 = xsw[(i + 1) * XS_STRIDE];
                float2 w0 = __ldg(W1T + i * 32 + l);
                float2 w1 = __ldg(W1T + (i + 1) * 32 + l);
                s0 = fmaf(w0.x, x0, s0); s1 = fmaf(w0.y, x0, s1);
                u0 = fmaf(w1.x, x1, u0); u1 = fmaf(w1.y, x1, u1);
            }
            __syncwarp();
            float ue0 = fmaxf(s0 + u0, 0.f);
            float ue1 = fmaxf(s1 + u1, 0.f);

            int vf = (l < 5) ? (url_f[n * 5 + l] << 8) : 0;
            unsigned long long vacc = 0;
#pragma unroll
            for (int j = 0; j < 5; j++) {
                int off = __shfl_sync(FULL, vf, j);
                addp(vacc, *(const unsigned long long*)(urB + off + j * 1792));
            }
            float v0 = lo32(vacc), v1 = hi32(vacc);

            float p0 = fmaf(wo0, ue0, fmaf(wo1, ue1, fmaf(wo2, v0, wo3 * v1)));
            float p1 = fmaf(wo4, ue0, fmaf(wo5, ue1, fmaf(wo6, v0, wo7 * v1)));
            unsigned long long pp = pack2(p0, p1);
#pragma unroll
            for (int o = 16; o; o >>= 1) {
                unsigned long long q = __shfl_xor_sync(FULL, pp, o);
                addp(pp, q);
            }
            if (l == 0) {
                p0 = lo32(pp) + bo0; p1 = hi32(pp) + bo1;
                float mm = fmaxf(p0, p1);
                float z0 = __expf(p0 - mm), z1 = __expf(p1 - mm);
                float inv = __fdividef(1.f, z0 + z1);
                *(float2*)(out + n * 2) = make_float2(z0 * inv, z1 * inv);
            }
        }
    }
}

extern "C" void kernel_launch(void* const* d_in, const int* in_sizes, int n_in,
                              void* d_out, int out_size) {
    const int*   user_f    = (const int*)d_in[1];
    const int*   url_f     = (const int*)d_in[2];
    const int*   u1u_f     = (const int*)d_in[3];
    const float* u1u_w     = (const float*)d_in[4];
    const int*   u1url_f   = (const int*)d_in[5];
    const float* u1url_w   = (const float*)d_in[6];
    const int*   u2u_f     = (const int*)d_in[7];
    const float* u2u_w     = (const float*)d_in[8];
    const int*   u2url_f   = (const int*)d_in[9];
    const float* u2url_w   = (const float*)d_in[10];
    const int*   url2u_f   = (const int*)d_in[11];
    const float* url2u_w   = (const float*)d_in[12];
    const int*   url2url_f = (const int*)d_in[13];
    const float* url2url_w = (const float*)d_in[14];
    const float* user_table = (const float*)d_in[15];
    const float* url_table  = (const float*)d_in[16];
    const float* W2 = (const float*)d_in[17];
    const float* b2 = (const float*)d_in[18];
    const float* W1 = (const float*)d_in[19];
    const float* b1 = (const float*)d_in[20];
    const float* Wo = (const float*)d_in[21];
    const float* bo = (const float*)d_in[22];
    float* out = (float*)d_out;

    int N = in_sizes[0];

    cudaFuncSetAttribute(gcn_kernel, cudaFuncAttributeMaxDynamicSharedMemorySize, SMEM_BYTES);
    int sm = 148;
    cudaDeviceGetAttribute(&sm, cudaDevAttrMultiProcessorCount, 0);

    prep_kernel<<<16, 256>>>(W1);
    gcn_kernel<<<sm, 512, SMEM_BYTES>>>(
        user_f, url_f, u1u_f, u1u_w, u1url_f, u1url_w,
        u2u_f, u2u_w, u2url_f, u2url_w,
        url2u_f, url2u_w, url2url_f, url2url_w,
        user_table, url_table, W2, b2, b1, Wo, bo, out, N);
}

// round 8
// speedup vs baseline: 2.1955x; 1.2192x over previous
#include <cuda_runtime.h>
#include <cstdint>

#define FULL 0xffffffffu
typedef unsigned long long ull;

__constant__ int UOFF[7] = {0, 11577, 11588, 11599, 11610, 11621, 11642};
__constant__ int VOFF[5] = {0, 4733, 4754, 4761, 4772};

constexpr int NWARP = 16;
constexpr int XS_STRIDE = 9;
constexpr int XS_FLOATS = 128 * XS_STRIDE;   // 1152 per warp
constexpr int YA_FLOATS = 64 * 8;            // 512 per warp
constexpr int AW_FLOATS = 64 * 32 * 4;       // 8192 floats each (hi / lo)
constexpr int US_FLOATS = 49 * 64;
constexpr int UR_FLOATS = 35 * 64;
constexpr int SMEM_FLOATS = 2 * AW_FLOATS + US_FLOATS + UR_FLOATS
                          + NWARP * (XS_FLOATS + YA_FLOATS);
constexpr int SMEM_BYTES = SMEM_FLOATS * 4;  // 193536

__device__ float2 W1T[128 * 32];   // [(i*32+l)] = (W1[l][i], W1[l+32][i])
__device__ unsigned int g_ctr;

__global__ void prep_kernel(const float* __restrict__ W1) {
    int i = blockIdx.x * blockDim.x + threadIdx.x;
    if (i == 0) g_ctr = 0;
    if (i < 128 * 32) {
        int col = i >> 5, l = i & 31;
        W1T[i] = make_float2(W1[l * 128 + col], W1[(l + 32) * 128 + col]);
    }
}

__device__ __forceinline__ float bfly_add(float v) {
#pragma unroll
    for (int o = 16; o; o >>= 1) v += __shfl_xor_sync(FULL, v, o);
    return v;
}
__device__ __forceinline__ float tf32r(float x) {
    float r; asm("cvt.rna.tf32.f32 %0, %1;" : "=f"(r) : "f"(x)); return r;
}
__device__ __forceinline__ void addp(ull& a, ull b) {
    asm("add.rn.f32x2 %0, %0, %1;" : "+l"(a) : "l"(b));
}
__device__ __forceinline__ ull pack2(float x, float y) {
    ull r; asm("mov.b64 %0, {%1, %2};" : "=l"(r) : "f"(x), "f"(y));
    return r;
}
__device__ __forceinline__ float lo32(ull v) { return __uint_as_float((unsigned)v); }
__device__ __forceinline__ float hi32(ull v) { return __uint_as_float((unsigned)(v >> 32)); }

__device__ __forceinline__ void mma8(float (&c)[4], const uint4& a, unsigned b0, unsigned b1) {
    asm volatile("mma.sync.aligned.m16n8k8.row.col.f32.tf32.tf32.f32 "
                 "{%0,%1,%2,%3},{%4,%5,%6,%7},{%8,%9},{%0,%1,%2,%3};"
                 : "+f"(c[0]), "+f"(c[1]), "+f"(c[2]), "+f"(c[3])
                 : "r"(a.x), "r"(a.y), "r"(a.z), "r"(a.w), "r"(b0), "r"(b1));
}

// softmax(cosine) + weighted relu-sum over 8 neighbors.
// fold-and-redistribute multi-reduce (register/shfl only):
// after the folds, lane l holds the full (d,nn) sum of neighbor j = (l>>2)&7;
// only that lane runs rsqrt/exp, then 8 broadcasts recover cw[0..7].
__device__ __forceinline__ void ga_tail(const float (&e0)[8], const float (&e1)[8],
                                        float (&d)[8], float (&nn)[8],
                                        const float* __restrict__ wptr, float icd,
                                        int l, float& out0, float& out1) {
    ull P[8];
#pragma unroll
    for (int kk = 0; kk < 8; kk++) P[kk] = pack2(d[kk], nn[kk]);
#pragma unroll
    for (int i = 0; i < 8; i++) addp(P[i], __shfl_xor_sync(FULL, P[i], 16));
    bool b4 = (l & 16) != 0;
    ull Q[4];
#pragma unroll
    for (int i = 0; i < 4; i++) Q[i] = b4 ? P[i + 4] : P[i];
#pragma unroll
    for (int i = 0; i < 4; i++) addp(Q[i], __shfl_xor_sync(FULL, Q[i], 8));
    bool b3 = (l & 8) != 0;
    ull R0 = b3 ? Q[2] : Q[0];
    ull R1 = b3 ? Q[3] : Q[1];
    addp(R0, __shfl_xor_sync(FULL, R0, 4));
    addp(R1, __shfl_xor_sync(FULL, R1, 4));
    ull S = (l & 4) ? R1 : R0;
    addp(S, __shfl_xor_sync(FULL, S, 2));
    addp(S, __shfl_xor_sync(FULL, S, 1));
    float rr = fminf(__frsqrt_rn(hi32(S)), 1e6f);      // 1/max(sqrt(nn),1e-6)
    float mycw = __expf(lo32(S) * rr * icd);           // cosine in [-1,1]; safe
    float4 wA = *(const float4*)wptr;
    float4 wB = *(const float4*)(wptr + 4);
    float w[8] = {wA.x, wA.y, wA.z, wA.w, wB.x, wB.y, wB.z, wB.w};
    float cw[8];
#pragma unroll
    for (int k = 0; k < 8; k++) cw[k] = __shfl_sync(FULL, mycw, 4 * k);
    float s = 0.f;
#pragma unroll
    for (int k = 0; k < 8; k++) s += cw[k];
    float inv = __fdividef(1.f, s);
    float o0 = 0.f, o1 = 0.f;
#pragma unroll
    for (int k = 0; k < 8; k++) {
        float sc = cw[k] * inv;
        o0 = fmaf(fmaxf(e0[k] * w[k], 0.f), sc, o0);
        o1 = fmaf(fmaxf(e1[k] * w[k], 0.f), sc, o1);
    }
    out0 = o0; out1 = o1;
}

// graph attention over 8 neighbors gathered from a smem sub-table (tbB = base + l*8)
template <int NF>
__device__ __forceinline__ void ga_tbl(const int* __restrict__ flist,
                                       const char* tbB,
                                       const float* __restrict__ wptr,
                                       float c0, float c1, float icd, int l,
                                       float& out0, float& out1) {
    int f0 = flist[l] << 8;
    int f1 = (l < 8 * NF - 32) ? (flist[32 + l] << 8) : 0;
    float e0[8], e1[8], d[8], nn[8];
#pragma unroll
    for (int kk = 0; kk < 8; kk++) {
        ull acc = 0;
#pragma unroll
        for (int j = 0; j < NF; j++) {
            const int pos = kk * NF + j;
            int off = __shfl_sync(FULL, (pos < 32) ? f0 : f1, pos & 31);
            addp(acc, *(const ull*)(tbB + off + j * 1792));
        }
        float a0 = lo32(acc), a1 = hi32(acc);
        e0[kk] = a0; e1[kk] = a1;
        d[kk]  = fmaf(a1, c1, a0 * c0);
        nn[kk] = fmaf(a1, a1, a0 * a0);
    }
    ga_tail(e0, e1, d, nn, wptr, icd, l, out0, out1);
}

__device__ __forceinline__ void ga_reg(const float (&e0)[8], const float (&e1)[8],
                                       const float* __restrict__ wptr,
                                       float c0, float c1, float icd, int l,
                                       float& out0, float& out1) {
    float d[8], nn[8];
#pragma unroll
    for (int kk = 0; kk < 8; kk++) {
        d[kk]  = fmaf(e1[kk], c1, e0[kk] * c0);
        nn[kk] = fmaf(e1[kk], e1[kk], e0[kk] * e0[kk]);
    }
    ga_tail(e0, e1, d, nn, wptr, icd, l, out0, out1);
}

// relu(W2(64x128) @ X[128x8] + b2) via 3xTF32 mma; Y[64][8] -> ybuf rows stride YS
template <int YS>
__device__ __forceinline__ void lin_mma(const uint4* __restrict__ AWhi,
                                        const uint4* __restrict__ AWlo,
                                        const float* __restrict__ xsw,
                                        float* __restrict__ ybuf,
                                        const float (&bA)[4], const float (&bB)[4],
                                        int lane) {
    int g = lane >> 2, tg = lane & 3;
    float acc[4][4];
#pragma unroll
    for (int m = 0; m < 4; m++) {
        acc[m][0] = bA[m]; acc[m][1] = bA[m];
        acc[m][2] = bB[m]; acc[m][3] = bB[m];
    }
#pragma unroll 2
    for (int kt = 0; kt < 16; kt++) {
        float xa = xsw[(8 * kt + tg) * XS_STRIDE + g];
        float xb = xsw[(8 * kt + tg + 4) * XS_STRIDE + g];
        float ha = tf32r(xa), hb = tf32r(xb);
        unsigned bh0 = __float_as_uint(ha), bh1 = __float_as_uint(hb);
        unsigned bl0 = __float_as_uint(xa - ha), bl1 = __float_as_uint(xb - hb);
        const uint4* ph = AWhi + kt * 32 + lane;
        const uint4* pl = AWlo + kt * 32 + lane;
#pragma unroll
        for (int m = 0; m < 4; m++) {
            uint4 ah = ph[m * 16 * 32];
            uint4 al = pl[m * 16 * 32];
            mma8(acc[m], ah, bh0, bh1);
            mma8(acc[m], ah, bl0, bl1);
            mma8(acc[m], al, bh0, bh1);
        }
    }
    __syncwarp();
#pragma unroll
    for (int m = 0; m < 4; m++) {
        ybuf[(16 * m + g) * YS + 2 * tg]         = fmaxf(acc[m][0], 0.f);
        ybuf[(16 * m + g) * YS + 2 * tg + 1]     = fmaxf(acc[m][1], 0.f);
        ybuf[(16 * m + g + 8) * YS + 2 * tg]     = fmaxf(acc[m][2], 0.f);
        ybuf[(16 * m + g + 8) * YS + 2 * tg + 1] = fmaxf(acc[m][3], 0.f);
    }
    __syncwarp();
}

__global__ void __launch_bounds__(512, 1)
gcn_kernel(const int* __restrict__ user_f, const int* __restrict__ url_f,
           const int* __restrict__ u1u_f, const float* __restrict__ u1u_w,
           const int* __restrict__ u1url_f, const float* __restrict__ u1url_w,
           const int* __restrict__ u2u_f, const float* __restrict__ u2u_w,
           const int* __restrict__ u2url_f, const float* __restrict__ u2url_w,
           const int* __restrict__ url2u_f, const float* __restrict__ url2u_w,
           const int* __restrict__ url2url_f, const float* __restrict__ url2url_w,
           const float* __restrict__ user_table, const float* __restrict__ url_table,
           const float* __restrict__ W2, const float* __restrict__ b2,
           const float* __restrict__ b1,
           const float* __restrict__ Wo, const float* __restrict__ bo,
           float* __restrict__ out, int N) {
    extern __shared__ float smf[];
    float* AWhiF = smf;
    float* AWloF = smf + AW_FLOATS;
    float* usF   = smf + 2 * AW_FLOATS;
    float* urF   = usF + US_FLOATS;
    float* xsAll = urF + UR_FLOATS;
    float* yaAll = xsAll + NWARP * XS_FLOATS;

    int tid = threadIdx.x;

    // ---- W2 A-fragments, hi/lo tf32 split (frag fid = m*16+kt) ----
    for (int i = tid; i < 2048; i += 512) {
        int fid = i >> 5, ln = i & 31;
        int m = fid >> 4, kt = fid & 15;
        int gg = ln >> 2, tg = ln & 3;
        int r0 = 16 * m + gg, r1 = r0 + 8, q0 = 8 * kt + tg, q1 = q0 + 4;
        float v0 = W2[r0 * 128 + q0], v1 = W2[r1 * 128 + q0];
        float v2 = W2[r0 * 128 + q1], v3 = W2[r1 * 128 + q1];
        float h0 = tf32r(v0), h1 = tf32r(v1), h2 = tf32r(v2), h3 = tf32r(v3);
        ((float4*)AWhiF)[fid * 32 + ln] = make_float4(h0, h1, h2, h3);
        ((float4*)AWloF)[fid * 32 + ln] = make_float4(v0 - h0, v1 - h1, v2 - h2, v3 - h3);
    }
    // ---- embedding sub-tables: entry e=(col*7+val), lane-pair layout ----
    for (int i = tid; i < 49 * 64; i += 512) {
        int e = i >> 6, q = i & 63, ln = q >> 1, c = q & 1;
        int j = e / 7, v = e % 7;
        usF[i] = user_table[(UOFF[j] + v) * 64 + ln + 32 * c];
    }
    for (int i = tid; i < 35 * 64; i += 512) {
        int e = i >> 6, q = i & 63, ln = q >> 1, c = q & 1;
        int j = e / 7, v = e % 7;
        urF[i] = url_table[(VOFF[j] + v) * 64 + ln + 32 * c];
    }
    __syncthreads();

    int l   = tid & 31;
    int wrp = tid >> 5;
    float* xsw = xsAll + wrp * XS_FLOATS;
    float* yAw = yaAll + wrp * YA_FLOATS;
    const char* usB = (const char*)usF + (l << 3);
    const char* urB = (const char*)urF + (l << 3);
    const uint4* AWhi = (const uint4*)AWhiF;
    const uint4* AWlo = (const uint4*)AWloF;

    int g = l >> 2;
    float bA[4], bB[4];
#pragma unroll
    for (int m = 0; m < 4; m++) { bA[m] = __ldg(b2 + 16 * m + g); bB[m] = __ldg(b2 + 16 * m + 8 + g); }
    float b10 = __ldg(b1 + l), b11 = __ldg(b1 + 32 + l);
    float wo0 = __ldg(Wo + l),       wo1 = __ldg(Wo + 32 + l);
    float wo2 = __ldg(Wo + 64 + l),  wo3 = __ldg(Wo + 96 + l);
    float wo4 = __ldg(Wo + 128 + l), wo5 = __ldg(Wo + 160 + l);
    float wo6 = __ldg(Wo + 192 + l), wo7 = __ldg(Wo + 224 + l);
    float bo0 = __ldg(bo), bo1 = __ldg(bo + 1);

    for (;;) {
        int n;
        if (l == 0) n = (int)atomicAdd(&g_ctr, 1u);
        n = __shfl_sync(FULL, n, 0);
        if (n >= N) break;

        // ---- stage A: url branch -> yA ----
        {
            const int* pc = u1url_f + n * 40;
            int fc0 = pc[l] << 8;
            int fc1 = (l < 8) ? (pc[32 + l] << 8) : 0;
#pragma unroll 1
            for (int k = 0; k < 8; k++) {
                ull cacc = 0;
#pragma unroll
                for (int j = 0; j < 5; j++) {
                    const int pos = k * 5 + j;
                    int off = __shfl_sync(FULL, (pos < 32) ? fc0 : fc1, pos & 31);
                    addp(cacc, *(const ull*)(urB + off + j * 1792));
                }
                float c0 = lo32(cacc), c1 = hi32(cacc);
                float icd = fminf(__frsqrt_rn(bfly_add(fmaf(c1, c1, c0 * c0))), 1e6f);
                float a0, a1, q0, q1;
                ga_tbl<7>(url2u_f + (n * 8 + k) * 56, usB, url2u_w + (n * 8 + k) * 8,
                          c0, c1, icd, l, a0, a1);
                ga_tbl<5>(url2url_f + (n * 8 + k) * 40, urB, url2url_w + (n * 8 + k) * 8,
                          c0, c1, icd, l, q0, q1);
                xsw[l * XS_STRIDE + k]        = c0;
                xsw[(32 + l) * XS_STRIDE + k] = c1;
                xsw[(64 + l) * XS_STRIDE + k] = (a0 + q0) * 0.5f;
                xsw[(96 + l) * XS_STRIDE + k] = (a1 + q1) * 0.5f;
            }
            __syncwarp();
            lin_mma<8>(AWhi, AWlo, xsw, yAw, bA, bB, l);
        }

        // ---- stage B: user branch -> regs ----
        float eB0[8], eB1[8];
        {
            const int* pc = u1u_f + n * 56;
            int fc0 = pc[l] << 8;
            int fc1 = (l < 24) ? (pc[32 + l] << 8) : 0;
#pragma unroll 1
            for (int k = 0; k < 8; k++) {
                ull cacc = 0;
#pragma unroll
                for (int j = 0; j < 7; j++) {
                    const int pos = k * 7 + j;
                    int off = __shfl_sync(FULL, (pos < 32) ? fc0 : fc1, pos & 31);
                    addp(cacc, *(const ull*)(usB + off + j * 1792));
                }
                float c0 = lo32(cacc), c1 = hi32(cacc);
                float icd = fminf(__frsqrt_rn(bfly_add(fmaf(c1, c1, c0 * c0))), 1e6f);
                float a0, a1, q0, q1;
                ga_tbl<7>(u2u_f + (n * 8 + k) * 56, usB, u2u_w + (n * 8 + k) * 8,
                          c0, c1, icd, l, a0, a1);
                ga_tbl<5>(u2url_f + (n * 8 + k) * 40, urB, u2url_w + (n * 8 + k) * 8,
                          c0, c1, icd, l, q0, q1);
                xsw[l * XS_STRIDE + k]        = c0;
                xsw[(32 + l) * XS_STRIDE + k] = c1;
                xsw[(64 + l) * XS_STRIDE + k] = (a0 + q0) * 0.5f;
                xsw[(96 + l) * XS_STRIDE + k] = (a1 + q1) * 0.5f;
            }
            __syncwarp();
            lin_mma<XS_STRIDE>(AWhi, AWlo, xsw, xsw, bA, bB, l);
#pragma unroll
            for (int k = 0; k < 8; k++) {
                eB0[k] = xsw[l * XS_STRIDE + k];
                eB1[k] = xsw[(32 + l) * XS_STRIDE + k];
            }
            __syncwarp();
        }

        // ---- stage C: hop1 -> center ----
        {
            int uf = (l < 7) ? (user_f[n * 7 + l] << 8) : 0;
            ull cacc = 0;
#pragma unroll
            for (int j = 0; j < 7; j++) {
                int off = __shfl_sync(FULL, uf, j);
                addp(cacc, *(const ull*)(usB + off + j * 1792));
            }
            float c0 = lo32(cacc), c1 = hi32(cacc);
            float icd = fminf(__frsqrt_rn(bfly_add(fmaf(c1, c1, c0 * c0))), 1e6f);

            float eA0[8], eA1[8];
            float4 t0 = *(const float4*)(yAw + l * 8);
            float4 t1 = *(const float4*)(yAw + l * 8 + 4);
            float4 t2 = *(const float4*)(yAw + (l + 32) * 8);
            float4 t3 = *(const float4*)(yAw + (l + 32) * 8 + 4);
            eA0[0] = t0.x; eA0[1] = t0.y; eA0[2] = t0.z; eA0[3] = t0.w;
            eA0[4] = t1.x; eA0[5] = t1.y; eA0[6] = t1.z; eA0[7] = t1.w;
            eA1[0] = t2.x; eA1[1] = t2.y; eA1[2] = t2.z; eA1[3] = t2.w;
            eA1[4] = t3.x; eA1[5] = t3.y; eA1[6] = t3.z; eA1[7] = t3.w;

            float a0, a1, q0, q1;
            ga_reg(eA0, eA1, u1url_w + n * 8, c0, c1, icd, l, a0, a1);
            ga_reg(eB0, eB1, u1u_w + n * 8, c0, c1, icd, l, q0, q1);

            xsw[l * XS_STRIDE]        = c0;
            xsw[(32 + l) * XS_STRIDE] = c1;
            xsw[(64 + l) * XS_STRIDE] = (a0 + q0) * 0.5f;
            xsw[(96 + l) * XS_STRIDE] = (a1 + q1) * 0.5f;
            __syncwarp();

            float s0 = b10, s1 = b11, u0 = 0.f, u1 = 0.f;
#pragma unroll 8
            for (int i = 0; i < 128; i += 2) {
                float x0 = xsw[i * XS_STRIDE];
                float x1 = xsw[(i + 1) * XS_STRIDE];
                float2 w0 = __ldg(W1T + i * 32 + l);
                float2 w1 = __ldg(W1T + (i + 1) * 32 + l);
                s0 = fmaf(w0.x, x0, s0); s1 = fmaf(w0.y, x0, s1);
                u0 = fmaf(w1.x, x1, u0); u1 = fmaf(w1.y, x1, u1);
            }
            __syncwarp();
            float ue0 = fmaxf(s0 + u0, 0.f);
            float ue1 = fmaxf(s1 + u1, 0.f);

            int vf = (l < 5) ? (url_f[n * 5 + l] << 8) : 0;
            ull vacc = 0;
#pragma unroll
            for (int j = 0; j < 5; j++) {
                int off = __shfl_sync(FULL, vf, j);
                addp(vacc, *(const ull*)(urB + off + j * 1792));
            }
            float v0 = lo32(vacc), v1 = hi32(vacc);

            float p0 = fmaf(wo0, ue0, fmaf(wo1, ue1, fmaf(wo2, v0, wo3 * v1)));
            float p1 = fmaf(wo4, ue0, fmaf(wo5, ue1, fmaf(wo6, v0, wo7 * v1)));
            ull pp = pack2(p0, p1);
#pragma unroll
            for (int o = 16; o; o >>= 1) {
                ull q = __shfl_xor_sync(FULL, pp, o);
                addp(pp, q);
            }
            if (l == 0) {
                p0 = lo32(pp) + bo0; p1 = hi32(pp) + bo1;
                float mm = fmaxf(p0, p1);
                float z0 = __expf(p0 - mm), z1 = __expf(p1 - mm);
                float inv = __fdividef(1.f, z0 + z1);
                *(float2*)(out + n * 2) = make_float2(z0 * inv, z1 * inv);
            }
        }
    }
}

extern "C" void kernel_launch(void* const* d_in, const int* in_sizes, int n_in,
                              void* d_out, int out_size) {
    const int*   user_f    = (const int*)d_in[1];
    const int*   url_f     = (const int*)d_in[2];
    const int*   u1u_f     = (const int*)d_in[3];
    const float* u1u_w     = (const float*)d_in[4];
    const int*   u1url_f   = (const int*)d_in[5];
    const float* u1url_w   = (const float*)d_in[6];
    const int*   u2u_f     = (const int*)d_in[7];
    const float* u2u_w     = (const float*)d_in[8];
    const int*   u2url_f   = (const int*)d_in[9];
    const float* u2url_w   = (const float*)d_in[10];
    const int*   url2u_f   = (const int*)d_in[11];
    const float* url2u_w   = (const float*)d_in[12];
    const int*   url2url_f = (const int*)d_in[13];
    const float* url2url_w = (const float*)d_in[14];
    const float* user_table = (const float*)d_in[15];
    const float* url_table  = (const float*)d_in[16];
    const float* W2 = (const float*)d_in[17];
    const float* b2 = (const float*)d_in[18];
    const float* W1 = (const float*)d_in[19];
    const float* b1 = (const float*)d_in[20];
    const float* Wo = (const float*)d_in[21];
    const float* bo = (const float*)d_in[22];
    float* out = (float*)d_out;

    int N = in_sizes[0];

    cudaFuncSetAttribute(gcn_kernel, cudaFuncAttributeMaxDynamicSharedMemorySize, SMEM_BYTES);
    int sm = 148;
    cudaDeviceGetAttribute(&sm, cudaDevAttrMultiProcessorCount, 0);

    prep_kernel<<<16, 256>>>(W1);
    gcn_kernel<<<sm, 512, SMEM_BYTES>>>(
        user_f, url_f, u1u_f, u1u_w, u1url_f, u1url_w,
        u2u_f, u2u_w, u2url_f, u2url_w,
        url2u_f, url2u_w, url2url_f, url2url_w,
        user_table, url_table, W2, b2, b1, Wo, bo, out, N);
}

// round 9
// speedup vs baseline: 2.4218x; 1.1031x over previous
#include <cuda_runtime.h>
#include <cstdint>

#define FULL 0xffffffffu
typedef unsigned long long ull;

__constant__ int UOFF[7] = {0, 11577, 11588, 11599, 11610, 11621, 11642};
__constant__ int VOFF[5] = {0, 4733, 4754, 4761, 4772};

constexpr int NWARP = 16;
constexpr int XS_STRIDE = 9;
constexpr int XS_FLOATS = 128 * XS_STRIDE;   // 1152 per warp
constexpr int AW_FLOATS = 64 * 32 * 4;       // 8192 floats each (hi / lo)
constexpr int UP_FLOATS = 4 * 49 * 64;       // user pair tables
constexpr int VP_FLOATS = 3 * 49 * 64;       // url pair tables
constexpr int PAIR_STRIDE_B = 49 * 256;      // 12544 bytes per pair table
constexpr int SMEM_FLOATS = 2 * AW_FLOATS + UP_FLOATS + VP_FLOATS + NWARP * XS_FLOATS;
constexpr int SMEM_BYTES = SMEM_FLOATS * 4;  // 227072

__device__ float2 W1T[128 * 32];   // [(i*32+l)] = (W1[l][i], W1[l+32][i])
__device__ unsigned int g_ctr;

__global__ void prep_kernel(const float* __restrict__ W1) {
    int i = blockIdx.x * blockDim.x + threadIdx.x;
    if (i == 0) g_ctr = 0;
    if (i < 128 * 32) {
        int col = i >> 5, l = i & 31;
        W1T[i] = make_float2(W1[l * 128 + col], W1[(l + 32) * 128 + col]);
    }
}

__device__ __forceinline__ float bfly_add(float v) {
#pragma unroll
    for (int o = 16; o; o >>= 1) v += __shfl_xor_sync(FULL, v, o);
    return v;
}
__device__ __forceinline__ float tf32r(float x) {
    float r; asm("cvt.rna.tf32.f32 %0, %1;" : "=f"(r) : "f"(x)); return r;
}
__device__ __forceinline__ void addp(ull& a, ull b) {
    asm("add.rn.f32x2 %0, %0, %1;" : "+l"(a) : "l"(b));
}
__device__ __forceinline__ ull pack2(float x, float y) {
    ull r; asm("mov.b64 %0, {%1, %2};" : "=l"(r) : "f"(x), "f"(y));
    return r;
}
__device__ __forceinline__ float lo32(ull v) { return __uint_as_float((unsigned)v); }
__device__ __forceinline__ float hi32(ull v) { return __uint_as_float((unsigned)(v >> 32)); }

__device__ __forceinline__ void mma8(float (&c)[4], const uint4& a, unsigned b0, unsigned b1) {
    asm volatile("mma.sync.aligned.m16n8k8.row.col.f32.tf32.tf32.f32 "
                 "{%0,%1,%2,%3},{%4,%5,%6,%7},{%8,%9},{%0,%1,%2,%3};"
                 : "+f"(c[0]), "+f"(c[1]), "+f"(c[2]), "+f"(c[3])
                 : "r"(a.x), "r"(a.y), "r"(a.z), "r"(a.w), "r"(b0), "r"(b1));
}

// pair-table embed for one feature list segment starting at warp-uniform `base`.
// NF original features -> ceil(NF/2) pair-table lookups.
template <int NF>
__device__ __forceinline__ void center_embed(int f0, int f1, int base, const char* tbB,
                                             float& c0, float& c1) {
    ull acc = 0;
#pragma unroll
    for (int p = 0; 2 * p + 1 < NF; p++) {
        int pa = base + 2 * p, pb = pa + 1;
        int ia = __shfl_sync(FULL, (pa < 32) ? f0 : f1, pa & 31);
        int ib = __shfl_sync(FULL, (pb < 32) ? f0 : f1, pb & 31);
        addp(acc, *(const ull*)(tbB + ia * 1792 + (ib << 8) + p * PAIR_STRIDE_B));
    }
    int ps = base + NF - 1;
    int ia = __shfl_sync(FULL, (ps < 32) ? f0 : f1, ps & 31);
    addp(acc, *(const ull*)(tbB + ia * 1792 + ((NF - 1) / 2) * PAIR_STRIDE_B));
    c0 = lo32(acc); c1 = hi32(acc);
}

// softmax(cosine) + weighted relu-sum over 8 neighbors.
// fold-and-redistribute multi-reduce; lane 4j owns neighbor j's (d,nn) sum.
__device__ __forceinline__ void ga_tail(const float (&e0)[8], const float (&e1)[8],
                                        float (&d)[8], float (&nn)[8],
                                        const float* __restrict__ wptr, float icd,
                                        int l, float& out0, float& out1) {
    ull P[8];
#pragma unroll
    for (int kk = 0; kk < 8; kk++) P[kk] = pack2(d[kk], nn[kk]);
#pragma unroll
    for (int i = 0; i < 8; i++) addp(P[i], __shfl_xor_sync(FULL, P[i], 16));
    bool b4 = (l & 16) != 0;
    ull Q[4];
#pragma unroll
    for (int i = 0; i < 4; i++) Q[i] = b4 ? P[i + 4] : P[i];
#pragma unroll
    for (int i = 0; i < 4; i++) addp(Q[i], __shfl_xor_sync(FULL, Q[i], 8));
    bool b3 = (l & 8) != 0;
    ull R0 = b3 ? Q[2] : Q[0];
    ull R1 = b3 ? Q[3] : Q[1];
    addp(R0, __shfl_xor_sync(FULL, R0, 4));
    addp(R1, __shfl_xor_sync(FULL, R1, 4));
    ull S = (l & 4) ? R1 : R0;
    addp(S, __shfl_xor_sync(FULL, S, 2));
    addp(S, __shfl_xor_sync(FULL, S, 1));
    float rr = fminf(__frsqrt_rn(hi32(S)), 1e6f);      // 1/max(sqrt(nn),1e-6)
    float mycw = __expf(lo32(S) * rr * icd);           // cosine in [-1,1]; safe
    float4 wA = *(const float4*)wptr;
    float4 wB = *(const float4*)(wptr + 4);
    float w[8] = {wA.x, wA.y, wA.z, wA.w, wB.x, wB.y, wB.z, wB.w};
    float cw[8];
#pragma unroll
    for (int k = 0; k < 8; k++) cw[k] = __shfl_sync(FULL, mycw, 4 * k);
    float s = 0.f;
#pragma unroll
    for (int k = 0; k < 8; k++) s += cw[k];
    float inv = __fdividef(1.f, s);
    float o0 = 0.f, o1 = 0.f;
#pragma unroll
    for (int k = 0; k < 8; k++) {
        float sc = cw[k] * inv;
        o0 = fmaf(fmaxf(e0[k] * w[k], 0.f), sc, o0);
        o1 = fmaf(fmaxf(e1[k] * w[k], 0.f), sc, o1);
    }
    out0 = o0; out1 = o1;
}

// graph attention over 8 neighbors via pair tables; all shuffle positions compile-time.
template <int NF>
__device__ __forceinline__ void ga_tbl(const int* __restrict__ flist,
                                       const char* tbB,
                                       const float* __restrict__ wptr,
                                       float c0, float c1, float icd, int l,
                                       float& out0, float& out1) {
    int f0 = flist[l];
    int f1 = (l < 8 * NF - 32) ? flist[32 + l] : 0;
    float e0[8], e1[8], d[8], nn[8];
#pragma unroll
    for (int kk = 0; kk < 8; kk++) {
        ull acc = 0;
#pragma unroll
        for (int p = 0; 2 * p + 1 < NF; p++) {
            const int pa = kk * NF + 2 * p, pb = pa + 1;
            int ia = __shfl_sync(FULL, (pa < 32) ? f0 : f1, pa & 31);
            int ib = __shfl_sync(FULL, (pb < 32) ? f0 : f1, pb & 31);
            addp(acc, *(const ull*)(tbB + ia * 1792 + (ib << 8) + p * PAIR_STRIDE_B));
        }
        {
            const int ps = kk * NF + NF - 1;
            int ia = __shfl_sync(FULL, (ps < 32) ? f0 : f1, ps & 31);
            addp(acc, *(const ull*)(tbB + ia * 1792 + ((NF - 1) / 2) * PAIR_STRIDE_B));
        }
        float a0 = lo32(acc), a1 = hi32(acc);
        e0[kk] = a0; e1[kk] = a1;
        d[kk]  = fmaf(a1, c1, a0 * c0);
        nn[kk] = fmaf(a1, a1, a0 * a0);
    }
    ga_tail(e0, e1, d, nn, wptr, icd, l, out0, out1);
}

__device__ __forceinline__ void ga_reg(const float (&e0)[8], const float (&e1)[8],
                                       const float* __restrict__ wptr,
                                       float c0, float c1, float icd, int l,
                                       float& out0, float& out1) {
    float d[8], nn[8];
#pragma unroll
    for (int kk = 0; kk < 8; kk++) {
        d[kk]  = fmaf(e1[kk], c1, e0[kk] * c0);
        nn[kk] = fmaf(e1[kk], e1[kk], e0[kk] * e0[kk]);
    }
    ga_tail(e0, e1, d, nn, wptr, icd, l, out0, out1);
}

// relu(W2(64x128) @ X[128x8] + b2) via 3xTF32 mma; Y written back into xsw (stride 9)
__device__ __forceinline__ void lin_mma(const uint4* __restrict__ AWhi,
                                        const uint4* __restrict__ AWlo,
                                        float* __restrict__ xsw,
                                        const float (&bA)[4], const float (&bB)[4],
                                        int lane) {
    int g = lane >> 2, tg = lane & 3;
    float acc[4][4];
#pragma unroll
    for (int m = 0; m < 4; m++) {
        acc[m][0] = bA[m]; acc[m][1] = bA[m];
        acc[m][2] = bB[m]; acc[m][3] = bB[m];
    }
#pragma unroll 2
    for (int kt = 0; kt < 16; kt++) {
        float xa = xsw[(8 * kt + tg) * XS_STRIDE + g];
        float xb = xsw[(8 * kt + tg + 4) * XS_STRIDE + g];
        float ha = tf32r(xa), hb = tf32r(xb);
        unsigned bh0 = __float_as_uint(ha), bh1 = __float_as_uint(hb);
        unsigned bl0 = __float_as_uint(xa - ha), bl1 = __float_as_uint(xb - hb);
        const uint4* ph = AWhi + kt * 32 + lane;
        const uint4* pl = AWlo + kt * 32 + lane;
#pragma unroll
        for (int m = 0; m < 4; m++) {
            uint4 ah = ph[m * 16 * 32];
            uint4 al = pl[m * 16 * 32];
            mma8(acc[m], ah, bh0, bh1);
            mma8(acc[m], ah, bl0, bl1);
            mma8(acc[m], al, bh0, bh1);
        }
    }
    __syncwarp();
#pragma unroll
    for (int m = 0; m < 4; m++) {
        xsw[(16 * m + g) * XS_STRIDE + 2 * tg]         = fmaxf(acc[m][0], 0.f);
        xsw[(16 * m + g) * XS_STRIDE + 2 * tg + 1]     = fmaxf(acc[m][1], 0.f);
        xsw[(16 * m + g + 8) * XS_STRIDE + 2 * tg]     = fmaxf(acc[m][2], 0.f);
        xsw[(16 * m + g + 8) * XS_STRIDE + 2 * tg + 1] = fmaxf(acc[m][3], 0.f);
    }
    __syncwarp();
}

__global__ void __launch_bounds__(512, 1)
gcn_kernel(const int* __restrict__ user_f, const int* __restrict__ url_f,
           const int* __restrict__ u1u_f, const float* __restrict__ u1u_w,
           const int* __restrict__ u1url_f, const float* __restrict__ u1url_w,
           const int* __restrict__ u2u_f, const float* __restrict__ u2u_w,
           const int* __restrict__ u2url_f, const float* __restrict__ u2url_w,
           const int* __restrict__ url2u_f, const float* __restrict__ url2u_w,
           const int* __restrict__ url2url_f, const float* __restrict__ url2url_w,
           const float* __restrict__ user_table, const float* __restrict__ url_table,
           const float* __restrict__ W2, const float* __restrict__ b2,
           const float* __restrict__ b1,
           const float* __restrict__ Wo, const float* __restrict__ bo,
           float* __restrict__ out, int N) {
    extern __shared__ float smf[];
    float* AWhiF = smf;
    float* AWloF = smf + AW_FLOATS;
    float* upF   = smf + 2 * AW_FLOATS;
    float* vpF   = upF + UP_FLOATS;
    float* xsAll = vpF + VP_FLOATS;

    int tid = threadIdx.x;

    // ---- W2 A-fragments, hi/lo tf32 split (frag fid = m*16+kt) ----
    for (int i = tid; i < 2048; i += 512) {
        int fid = i >> 5, ln = i & 31;
        int m = fid >> 4, kt = fid & 15;
        int gg = ln >> 2, tg = ln & 3;
        int r0 = 16 * m + gg, r1 = r0 + 8, q0 = 8 * kt + tg, q1 = q0 + 4;
        float v0 = W2[r0 * 128 + q0], v1 = W2[r1 * 128 + q0];
        float v2 = W2[r0 * 128 + q1], v3 = W2[r1 * 128 + q1];
        float h0 = tf32r(v0), h1 = tf32r(v1), h2 = tf32r(v2), h3 = tf32r(v3);
        ((float4*)AWhiF)[fid * 32 + ln] = make_float4(h0, h1, h2, h3);
        ((float4*)AWloF)[fid * 32 + ln] = make_float4(v0 - h0, v1 - h1, v2 - h2, v3 - h3);
    }
    // ---- user pair tables: P0=(c0,c1) P1=(c2,c3) P2=(c4,c5) P3=(c6 only) ----
    // entry (p, ia, ib) at float index ((p*49 + ia*7 + ib)*64 + 2*ln + c) holding dim ln+32c
    for (int i = tid; i < UP_FLOATS; i += 512) {
        int e = i >> 6, q = i & 63, ln = q >> 1, c = q & 1;
        int dim = ln + 32 * c;
        int p = e / 49, rem = e % 49, ia = rem / 7, ib = rem % 7;
        float v;
        if (p < 3) v = user_table[(UOFF[2 * p] + ia) * 64 + dim]
                     + user_table[(UOFF[2 * p + 1] + ib) * 64 + dim];
        else       v = user_table[(UOFF[6] + ia) * 64 + dim];
        upF[i] = v;
    }
    // ---- url pair tables: P0=(c0,c1) P1=(c2,c3) P2=(c4 only) ----
    for (int i = tid; i < VP_FLOATS; i += 512) {
        int e = i >> 6, q = i & 63, ln = q >> 1, c = q & 1;
        int dim = ln + 32 * c;
        int p = e / 49, rem = e % 49, ia = rem / 7, ib = rem % 7;
        float v;
        if (p < 2) v = url_table[(VOFF[2 * p] + ia) * 64 + dim]
                     + url_table[(VOFF[2 * p + 1] + ib) * 64 + dim];
        else       v = url_table[(VOFF[4] + ia) * 64 + dim];
        vpF[i] = v;
    }
    __syncthreads();

    int l   = tid & 31;
    int wrp = tid >> 5;
    float* xsw = xsAll + wrp * XS_FLOATS;
    const char* upB = (const char*)upF + (l << 3);
    const char* vpB = (const char*)vpF + (l << 3);
    const uint4* AWhi = (const uint4*)AWhiF;
    const uint4* AWlo = (const uint4*)AWloF;

    int g = l >> 2;
    float bA[4], bB[4];
#pragma unroll
    for (int m = 0; m < 4; m++) { bA[m] = __ldg(b2 + 16 * m + g); bB[m] = __ldg(b2 + 16 * m + 8 + g); }
    float b10 = __ldg(b1 + l), b11 = __ldg(b1 + 32 + l);
    float wo0 = __ldg(Wo + l),       wo1 = __ldg(Wo + 32 + l);
    float wo2 = __ldg(Wo + 64 + l),  wo3 = __ldg(Wo + 96 + l);
    float wo4 = __ldg(Wo + 128 + l), wo5 = __ldg(Wo + 160 + l);
    float wo6 = __ldg(Wo + 192 + l), wo7 = __ldg(Wo + 224 + l);
    float bo0 = __ldg(bo), bo1 = __ldg(bo + 1);

    for (;;) {
        int n;
        if (l == 0) n = (int)atomicAdd(&g_ctr, 1u);
        n = __shfl_sync(FULL, n, 0);
        if (n >= N) break;

        // ---- stage B: user branch (hop2 -> hop1) -> eB regs ----
        float eB0[8], eB1[8];
        {
            const int* pc = u1u_f + n * 56;
            int fc0 = pc[l];
            int fc1 = (l < 24) ? pc[32 + l] : 0;
#pragma unroll 1
            for (int k = 0; k < 8; k++) {
                float c0, c1;
                center_embed<7>(fc0, fc1, k * 7, upB, c0, c1);
                float icd = fminf(__frsqrt_rn(bfly_add(fmaf(c1, c1, c0 * c0))), 1e6f);
                float a0, a1, q0, q1;
                ga_tbl<7>(u2u_f + (n * 8 + k) * 56, upB, u2u_w + (n * 8 + k) * 8,
                          c0, c1, icd, l, a0, a1);
                ga_tbl<5>(u2url_f + (n * 8 + k) * 40, vpB, u2url_w + (n * 8 + k) * 8,
                          c0, c1, icd, l, q0, q1);
                xsw[l * XS_STRIDE + k]        = c0;
                xsw[(32 + l) * XS_STRIDE + k] = c1;
                xsw[(64 + l) * XS_STRIDE + k] = (a0 + q0) * 0.5f;
                xsw[(96 + l) * XS_STRIDE + k] = (a1 + q1) * 0.5f;
            }
            __syncwarp();
            lin_mma(AWhi, AWlo, xsw, bA, bB, l);
#pragma unroll
            for (int k = 0; k < 8; k++) {
                eB0[k] = xsw[l * XS_STRIDE + k];
                eB1[k] = xsw[(32 + l) * XS_STRIDE + k];
            }
            __syncwarp();
        }

        // ---- stage A: url branch (hop2 -> hop1) -> Y stays in xsw ----
        {
            const int* pc = u1url_f + n * 40;
            int fc0 = pc[l];
            int fc1 = (l < 8) ? pc[32 + l] : 0;
#pragma unroll 1
            for (int k = 0; k < 8; k++) {
                float c0, c1;
                center_embed<5>(fc0, fc1, k * 5, vpB, c0, c1);
                float icd = fminf(__frsqrt_rn(bfly_add(fmaf(c1, c1, c0 * c0))), 1e6f);
                float a0, a1, q0, q1;
                ga_tbl<7>(url2u_f + (n * 8 + k) * 56, upB, url2u_w + (n * 8 + k) * 8,
                          c0, c1, icd, l, a0, a1);
                ga_tbl<5>(url2url_f + (n * 8 + k) * 40, vpB, url2url_w + (n * 8 + k) * 8,
                          c0, c1, icd, l, q0, q1);
                xsw[l * XS_STRIDE + k]        = c0;
                xsw[(32 + l) * XS_STRIDE + k] = c1;
                xsw[(64 + l) * XS_STRIDE + k] = (a0 + q0) * 0.5f;
                xsw[(96 + l) * XS_STRIDE + k] = (a1 + q1) * 0.5f;
            }
            __syncwarp();
            lin_mma(AWhi, AWlo, xsw, bA, bB, l);
        }

        // ---- stage C: hop1 -> center ----
        {
            int uf = (l < 7) ? user_f[n * 7 + l] : 0;
            float c0, c1;
            center_embed<7>(uf, 0, 0, upB, c0, c1);
            float icd = fminf(__frsqrt_rn(bfly_add(fmaf(c1, c1, c0 * c0))), 1e6f);

            // eA from xsw (stage A's Y) — read before clobbering column 0
            float eA0[8], eA1[8];
#pragma unroll
            for (int k = 0; k < 8; k++) {
                eA0[k] = xsw[l * XS_STRIDE + k];
                eA1[k] = xsw[(32 + l) * XS_STRIDE + k];
            }

            float a0, a1, q0, q1;
            ga_reg(eA0, eA1, u1url_w + n * 8, c0, c1, icd, l, a0, a1);
            ga_reg(eB0, eB1, u1u_w + n * 8, c0, c1, icd, l, q0, q1);

            xsw[l * XS_STRIDE]        = c0;
            xsw[(32 + l) * XS_STRIDE] = c1;
            xsw[(64 + l) * XS_STRIDE] = (a0 + q0) * 0.5f;
            xsw[(96 + l) * XS_STRIDE] = (a1 + q1) * 0.5f;
            __syncwarp();

            float s0 = b10, s1 = b11, u0 = 0.f, u1 = 0.f;
#pragma unroll 8
            for (int i = 0; i < 128; i += 2) {
                float x0 = xsw[i * XS_STRIDE];
                float x1 = xsw[(i + 1) * XS_STRIDE];
                float2 w0 = __ldg(W1T + i * 32 + l);
                float2 w1 = __ldg(W1T + (i + 1) * 32 + l);
                s0 = fmaf(w0.x, x0, s0); s1 = fmaf(w0.y, x0, s1);
                u0 = fmaf(w1.x, x1, u0); u1 = fmaf(w1.y, x1, u1);
            }
            __syncwarp();
            float ue0 = fmaxf(s0 + u0, 0.f);
            float ue1 = fmaxf(s1 + u1, 0.f);

            int vf = (l < 5) ? url_f[n * 5 + l] : 0;
            float v0, v1;
            center_embed<5>(vf, 0, 0, vpB, v0, v1);

            float p0 = fmaf(wo0, ue0, fmaf(wo1, ue1, fmaf(wo2, v0, wo3 * v1)));
            float p1 = fmaf(wo4, ue0, fmaf(wo5, ue1, fmaf(wo6, v0, wo7 * v1)));
            ull pp = pack2(p0, p1);
#pragma unroll
            for (int o = 16; o; o >>= 1) {
                ull q = __shfl_xor_sync(FULL, pp, o);
                addp(pp, q);
            }
            if (l == 0) {
                p0 = lo32(pp) + bo0; p1 = hi32(pp) + bo1;
                float mm = fmaxf(p0, p1);
                float z0 = __expf(p0 - mm), z1 = __expf(p1 - mm);
                float inv = __fdividef(1.f, z0 + z1);
                *(float2*)(out + n * 2) = make_float2(z0 * inv, z1 * inv);
            }
        }
    }
}

extern "C" void kernel_launch(void* const* d_in, const int* in_sizes, int n_in,
                              void* d_out, int out_size) {
    const int*   user_f    = (const int*)d_in[1];
    const int*   url_f     = (const int*)d_in[2];
    const int*   u1u_f     = (const int*)d_in[3];
    const float* u1u_w     = (const float*)d_in[4];
    const int*   u1url_f   = (const int*)d_in[5];
    const float* u1url_w   = (const float*)d_in[6];
    const int*   u2u_f     = (const int*)d_in[7];
    const float* u2u_w     = (const float*)d_in[8];
    const int*   u2url_f   = (const int*)d_in[9];
    const float* u2url_w   = (const float*)d_in[10];
    const int*   url2u_f   = (const int*)d_in[11];
    const float* url2u_w   = (const float*)d_in[12];
    const int*   url2url_f = (const int*)d_in[13];
    const float* url2url_w = (const float*)d_in[14];
    const float* user_table = (const float*)d_in[15];
    const float* url_table  = (const float*)d_in[16];
    const float* W2 = (const float*)d_in[17];
    const float* b2 = (const float*)d_in[18];
    const float* W1 = (const float*)d_in[19];
    const float* b1 = (const float*)d_in[20];
    const float* Wo = (const float*)d_in[21];
    const float* bo = (const float*)d_in[22];
    float* out = (float*)d_out;

    int N = in_sizes[0];

    cudaFuncSetAttribute(gcn_kernel, cudaFuncAttributeMaxDynamicSharedMemorySize, SMEM_BYTES);
    int sm = 148;
    cudaDeviceGetAttribute(&sm, cudaDevAttrMultiProcessorCount, 0);

    prep_kernel<<<16, 256>>>(W1);
    gcn_kernel<<<sm, 512, SMEM_BYTES>>>(
        user_f, url_f, u1u_f, u1u_w, u1url_f, u1url_w,
        u2u_f, u2u_w, u2url_f, u2url_w,
        url2u_f, url2u_w, url2url_f, url2url_w,
        user_table, url_table, W2, b2, b1, Wo, bo, out, N);
}

// round 10
// speedup vs baseline: 2.6557x; 1.0966x over previous
#include <cuda_runtime.h>
#include <cuda_bf16.h>
#include <cstdint>

#define FULL 0xffffffffu
typedef unsigned long long ull;

__constant__ int UOFF[7] = {0, 11577, 11588, 11599, 11610, 11621, 11642};
__constant__ int VOFF[5] = {0, 4733, 4754, 4761, 4772};

constexpr int NWARP = 16;
constexpr int XS_STRIDE = 9;
constexpr int XS_FLOATS = 128 * XS_STRIDE;   // 1152 per warp
constexpr int AW_FLOATS = 32 * 32 * 4;       // 4096 floats each (bf16 hi / lo frag tables)
constexpr int UP_FLOATS = 4 * 49 * 64;       // user pair tables
constexpr int VP_FLOATS = 3 * 49 * 64;       // url pair tables
constexpr int PAIR_STRIDE_B = 49 * 256;      // 12544 bytes per pair table
constexpr int SMEM_FLOATS = 2 * AW_FLOATS + UP_FLOATS + VP_FLOATS + NWARP * XS_FLOATS;
constexpr int SMEM_BYTES = SMEM_FLOATS * 4;  // 194304

__device__ float2 W1T[128 * 32];   // [(i*32+l)] = (W1[l][i], W1[l+32][i])
__device__ unsigned int g_ctr;

__global__ void prep_kernel(const float* __restrict__ W1) {
    int i = blockIdx.x * blockDim.x + threadIdx.x;
    if (i == 0) g_ctr = 0;
    if (i < 128 * 32) {
        int col = i >> 5, l = i & 31;
        W1T[i] = make_float2(W1[l * 128 + col], W1[(l + 32) * 128 + col]);
    }
}

__device__ __forceinline__ float bfly_add(float v) {
#pragma unroll
    for (int o = 16; o; o >>= 1) v += __shfl_xor_sync(FULL, v, o);
    return v;
}
__device__ __forceinline__ void addp(ull& a, ull b) {
    asm("add.rn.f32x2 %0, %0, %1;" : "+l"(a) : "l"(b));
}
__device__ __forceinline__ ull pack2(float x, float y) {
    ull r; asm("mov.b64 %0, {%1, %2};" : "=l"(r) : "f"(x), "f"(y));
    return r;
}
__device__ __forceinline__ float lo32(ull v) { return __uint_as_float((unsigned)v); }
__device__ __forceinline__ float hi32(ull v) { return __uint_as_float((unsigned)(v >> 32)); }

// pack two floats as bf16x2 (first arg -> low half / lower k index)
__device__ __forceinline__ unsigned pk_bf(float lo, float hi) {
    __nv_bfloat162 h;
    h.x = __float2bfloat16_rn(lo);
    h.y = __float2bfloat16_rn(hi);
    return *(unsigned*)&h;
}
__device__ __forceinline__ float bfr(float x) {
    return __bfloat162float(__float2bfloat16_rn(x));
}

__device__ __forceinline__ void mma16(float (&c)[4], const uint4& a, unsigned b0, unsigned b1) {
    asm volatile("mma.sync.aligned.m16n8k16.row.col.f32.bf16.bf16.f32 "
                 "{%0,%1,%2,%3},{%4,%5,%6,%7},{%8,%9},{%0,%1,%2,%3};"
                 : "+f"(c[0]), "+f"(c[1]), "+f"(c[2]), "+f"(c[3])
                 : "r"(a.x), "r"(a.y), "r"(a.z), "r"(a.w), "r"(b0), "r"(b1));
}

// pair-table embed for one feature list segment starting at warp-uniform `base`.
template <int NF>
__device__ __forceinline__ void center_embed(int f0, int f1, int base, const char* tbB,
                                             float& c0, float& c1) {
    ull acc = 0;
#pragma unroll
    for (int p = 0; 2 * p + 1 < NF; p++) {
        int pa = base + 2 * p, pb = pa + 1;
        int ia = __shfl_sync(FULL, (pa < 32) ? f0 : f1, pa & 31);
        int ib = __shfl_sync(FULL, (pb < 32) ? f0 : f1, pb & 31);
        addp(acc, *(const ull*)(tbB + ia * 1792 + (ib << 8) + p * PAIR_STRIDE_B));
    }
    int ps = base + NF - 1;
    int ia = __shfl_sync(FULL, (ps < 32) ? f0 : f1, ps & 31);
    addp(acc, *(const ull*)(tbB + ia * 1792 + ((NF - 1) / 2) * PAIR_STRIDE_B));
    c0 = lo32(acc); c1 = hi32(acc);
}

// softmax(cosine) + weighted relu-sum over 8 neighbors.
// fold-and-redistribute multi-reduce; lane 4j owns neighbor j's (d,nn) sum.
__device__ __forceinline__ void ga_tail(const float (&e0)[8], const float (&e1)[8],
                                        float (&d)[8], float (&nn)[8],
                                        const float* __restrict__ wptr, float icd,
                                        int l, float& out0, float& out1) {
    ull P[8];
#pragma unroll
    for (int kk = 0; kk < 8; kk++) P[kk] = pack2(d[kk], nn[kk]);
#pragma unroll
    for (int i = 0; i < 8; i++) addp(P[i], __shfl_xor_sync(FULL, P[i], 16));
    bool b4 = (l & 16) != 0;
    ull Q[4];
#pragma unroll
    for (int i = 0; i < 4; i++) Q[i] = b4 ? P[i + 4] : P[i];
#pragma unroll
    for (int i = 0; i < 4; i++) addp(Q[i], __shfl_xor_sync(FULL, Q[i], 8));
    bool b3 = (l & 8) != 0;
    ull R0 = b3 ? Q[2] : Q[0];
    ull R1 = b3 ? Q[3] : Q[1];
    addp(R0, __shfl_xor_sync(FULL, R0, 4));
    addp(R1, __shfl_xor_sync(FULL, R1, 4));
    ull S = (l & 4) ? R1 : R0;
    addp(S, __shfl_xor_sync(FULL, S, 2));
    addp(S, __shfl_xor_sync(FULL, S, 1));
    float rr = fminf(__frsqrt_rn(hi32(S)), 1e6f);      // 1/max(sqrt(nn),1e-6)
    float mycw = __expf(lo32(S) * rr * icd);           // cosine in [-1,1]; safe
    float4 wA = *(const float4*)wptr;
    float4 wB = *(const float4*)(wptr + 4);
    float w[8] = {wA.x, wA.y, wA.z, wA.w, wB.x, wB.y, wB.z, wB.w};
    float cw[8];
#pragma unroll
    for (int k = 0; k < 8; k++) cw[k] = __shfl_sync(FULL, mycw, 4 * k);
    float s = 0.f;
#pragma unroll
    for (int k = 0; k < 8; k++) s += cw[k];
    float inv = __fdividef(1.f, s);
    float o0 = 0.f, o1 = 0.f;
#pragma unroll
    for (int k = 0; k < 8; k++) {
        float sc = cw[k] * inv;
        o0 = fmaf(fmaxf(e0[k] * w[k], 0.f), sc, o0);
        o1 = fmaf(fmaxf(e1[k] * w[k], 0.f), sc, o1);
    }
    out0 = o0; out1 = o1;
}

// graph attention over 8 neighbors via pair tables; all shuffle positions compile-time.
template <int NF>
__device__ __forceinline__ void ga_tbl(const int* __restrict__ flist,
                                       const char* tbB,
                                       const float* __restrict__ wptr,
                                       float c0, float c1, float icd, int l,
                                       float& out0, float& out1) {
    int f0 = flist[l];
    int f1 = (l < 8 * NF - 32) ? flist[32 + l] : 0;
    float e0[8], e1[8], d[8], nn[8];
#pragma unroll
    for (int kk = 0; kk < 8; kk++) {
        ull acc = 0;
#pragma unroll
        for (int p = 0; 2 * p + 1 < NF; p++) {
            const int pa = kk * NF + 2 * p, pb = pa + 1;
            int ia = __shfl_sync(FULL, (pa < 32) ? f0 : f1, pa & 31);
            int ib = __shfl_sync(FULL, (pb < 32) ? f0 : f1, pb & 31);
            addp(acc, *(const ull*)(tbB + ia * 1792 + (ib << 8) + p * PAIR_STRIDE_B));
        }
        {
            const int ps = kk * NF + NF - 1;
            int ia = __shfl_sync(FULL, (ps < 32) ? f0 : f1, ps & 31);
            addp(acc, *(const ull*)(tbB + ia * 1792 + ((NF - 1) / 2) * PAIR_STRIDE_B));
        }
        float a0 = lo32(acc), a1 = hi32(acc);
        e0[kk] = a0; e1[kk] = a1;
        d[kk]  = fmaf(a1, c1, a0 * c0);
        nn[kk] = fmaf(a1, a1, a0 * a0);
    }
    ga_tail(e0, e1, d, nn, wptr, icd, l, out0, out1);
}

__device__ __forceinline__ void ga_reg(const float (&e0)[8], const float (&e1)[8],
                                       const float* __restrict__ wptr,
                                       float c0, float c1, float icd, int l,
                                       float& out0, float& out1) {
    float d[8], nn[8];
#pragma unroll
    for (int kk = 0; kk < 8; kk++) {
        d[kk]  = fmaf(e1[kk], c1, e0[kk] * c0);
        nn[kk] = fmaf(e1[kk], e1[kk], e0[kk] * e0[kk]);
    }
    ga_tail(e0, e1, d, nn, wptr, icd, l, out0, out1);
}

// relu(W2(64x128) @ X[128x8] + b2) via 3xBF16-k16 mma (hi/lo split);
// Y written back into xsw (stride XS_STRIDE)
__device__ __forceinline__ void lin_mma(const uint4* __restrict__ AWhi,
                                        const uint4* __restrict__ AWlo,
                                        float* __restrict__ xsw,
                                        const float (&bA)[4], const float (&bB)[4],
                                        int lane) {
    int g = lane >> 2, tg = lane & 3;
    float acc[4][4];
#pragma unroll
    for (int m = 0; m < 4; m++) {
        acc[m][0] = bA[m]; acc[m][1] = bA[m];
        acc[m][2] = bB[m]; acc[m][3] = bB[m];
    }
#pragma unroll 2
    for (int kt = 0; kt < 8; kt++) {
        int r0 = 16 * kt + 2 * tg;
        float xa0 = xsw[r0 * XS_STRIDE + g];
        float xa1 = xsw[(r0 + 1) * XS_STRIDE + g];
        float xb0 = xsw[(r0 + 8) * XS_STRIDE + g];
        float xb1 = xsw[(r0 + 9) * XS_STRIDE + g];
        float ha0 = bfr(xa0), ha1 = bfr(xa1), hb0 = bfr(xb0), hb1 = bfr(xb1);
        unsigned Bh0 = pk_bf(ha0, ha1), Bh1 = pk_bf(hb0, hb1);
        unsigned Bl0 = pk_bf(xa0 - ha0, xa1 - ha1), Bl1 = pk_bf(xb0 - hb0, xb1 - hb1);
        const uint4* ph = AWhi + kt * 4 * 32 + lane;
        const uint4* pl = AWlo + kt * 4 * 32 + lane;
#pragma unroll
        for (int m = 0; m < 4; m++) {
            uint4 ah = ph[m * 32];
            uint4 al = pl[m * 32];
            mma16(acc[m], ah, Bh0, Bh1);
            mma16(acc[m], ah, Bl0, Bl1);
            mma16(acc[m], al, Bh0, Bh1);
        }
    }
    __syncwarp();
#pragma unroll
    for (int m = 0; m < 4; m++) {
        xsw[(16 * m + g) * XS_STRIDE + 2 * tg]         = fmaxf(acc[m][0], 0.f);
        xsw[(16 * m + g) * XS_STRIDE + 2 * tg + 1]     = fmaxf(acc[m][1], 0.f);
        xsw[(16 * m + g + 8) * XS_STRIDE + 2 * tg]     = fmaxf(acc[m][2], 0.f);
        xsw[(16 * m + g + 8) * XS_STRIDE + 2 * tg + 1] = fmaxf(acc[m][3], 0.f);
    }
    __syncwarp();
}

__global__ void __launch_bounds__(512, 1)
gcn_kernel(const int* __restrict__ user_f, const int* __restrict__ url_f,
           const int* __restrict__ u1u_f, const float* __restrict__ u1u_w,
           const int* __restrict__ u1url_f, const float* __restrict__ u1url_w,
           const int* __restrict__ u2u_f, const float* __restrict__ u2u_w,
           const int* __restrict__ u2url_f, const float* __restrict__ u2url_w,
           const int* __restrict__ url2u_f, const float* __restrict__ url2u_w,
           const int* __restrict__ url2url_f, const float* __restrict__ url2url_w,
           const float* __restrict__ user_table, const float* __restrict__ url_table,
           const float* __restrict__ W2, const float* __restrict__ b2,
           const float* __restrict__ b1,
           const float* __restrict__ Wo, const float* __restrict__ bo,
           float* __restrict__ out, int N) {
    extern __shared__ float smf[];
    float* AWhiF = smf;
    float* AWloF = smf + AW_FLOATS;
    float* upF   = smf + 2 * AW_FLOATS;
    float* vpF   = upF + UP_FLOATS;
    float* xsAll = vpF + VP_FLOATS;

    int tid = threadIdx.x;

    // ---- W2 A-fragments for m16n8k16 bf16, hi/lo split (frag fid = kt*4+m) ----
    for (int i = tid; i < 1024; i += 512) {
        int fid = i >> 5, ln = i & 31;
        int kt = fid >> 2, m = fid & 3;
        int gg = ln >> 2, tg = ln & 3;
        int r0 = 16 * m + gg, r1 = r0 + 8;
        int c0 = 16 * kt + 2 * tg, c1 = c0 + 1, c2 = c0 + 8, c3 = c0 + 9;
        float v00 = W2[r0 * 128 + c0], v01 = W2[r0 * 128 + c1];
        float v10 = W2[r1 * 128 + c0], v11 = W2[r1 * 128 + c1];
        float v02 = W2[r0 * 128 + c2], v03 = W2[r0 * 128 + c3];
        float v12 = W2[r1 * 128 + c2], v13 = W2[r1 * 128 + c3];
        float h00 = bfr(v00), h01 = bfr(v01), h10 = bfr(v10), h11 = bfr(v11);
        float h02 = bfr(v02), h03 = bfr(v03), h12 = bfr(v12), h13 = bfr(v13);
        uint4 hi, lo;
        hi.x = pk_bf(h00, h01); hi.y = pk_bf(h10, h11);
        hi.z = pk_bf(h02, h03); hi.w = pk_bf(h12, h13);
        lo.x = pk_bf(v00 - h00, v01 - h01); lo.y = pk_bf(v10 - h10, v11 - h11);
        lo.z = pk_bf(v02 - h02, v03 - h03); lo.w = pk_bf(v12 - h12, v13 - h13);
        ((uint4*)AWhiF)[fid * 32 + ln] = hi;
        ((uint4*)AWloF)[fid * 32 + ln] = lo;
    }
    // ---- user pair tables: P0=(c0,c1) P1=(c2,c3) P2=(c4,c5) P3=(c6 only) ----
    for (int i = tid; i < UP_FLOATS; i += 512) {
        int e = i >> 6, q = i & 63, ln = q >> 1, c = q & 1;
        int dim = ln + 32 * c;
        int p = e / 49, rem = e % 49, ia = rem / 7, ib = rem % 7;
        float v;
        if (p < 3) v = user_table[(UOFF[2 * p] + ia) * 64 + dim]
                     + user_table[(UOFF[2 * p + 1] + ib) * 64 + dim];
        else       v = user_table[(UOFF[6] + ia) * 64 + dim];
        upF[i] = v;
    }
    // ---- url pair tables: P0=(c0,c1) P1=(c2,c3) P2=(c4 only) ----
    for (int i = tid; i < VP_FLOATS; i += 512) {
        int e = i >> 6, q = i & 63, ln = q >> 1, c = q & 1;
        int dim = ln + 32 * c;
        int p = e / 49, rem = e % 49, ia = rem / 7, ib = rem % 7;
        float v;
        if (p < 2) v = url_table[(VOFF[2 * p] + ia) * 64 + dim]
                     + url_table[(VOFF[2 * p + 1] + ib) * 64 + dim];
        else       v = url_table[(VOFF[4] + ia) * 64 + dim];
        vpF[i] = v;
    }
    __syncthreads();

    int l   = tid & 31;
    int wrp = tid >> 5;
    float* xsw = xsAll + wrp * XS_FLOATS;
    const char* upB = (const char*)upF + (l << 3);
    const char* vpB = (const char*)vpF + (l << 3);
    const uint4* AWhi = (const uint4*)AWhiF;
    const uint4* AWlo = (const uint4*)AWloF;

    int g = l >> 2;
    float bA[4], bB[4];
#pragma unroll
    for (int m = 0; m < 4; m++) { bA[m] = __ldg(b2 + 16 * m + g); bB[m] = __ldg(b2 + 16 * m + 8 + g); }
    float b10 = __ldg(b1 + l), b11 = __ldg(b1 + 32 + l);
    float wo0 = __ldg(Wo + l),       wo1 = __ldg(Wo + 32 + l);
    float wo2 = __ldg(Wo + 64 + l),  wo3 = __ldg(Wo + 96 + l);
    float wo4 = __ldg(Wo + 128 + l), wo5 = __ldg(Wo + 160 + l);
    float wo6 = __ldg(Wo + 192 + l), wo7 = __ldg(Wo + 224 + l);
    float bo0 = __ldg(bo), bo1 = __ldg(bo + 1);

    for (;;) {
        int n;
        if (l == 0) n = (int)atomicAdd(&g_ctr, 1u);
        n = __shfl_sync(FULL, n, 0);
        if (n >= N) break;

        // ---- stage B: user branch (hop2 -> hop1) -> eB regs ----
        float eB0[8], eB1[8];
        {
            const int* pc = u1u_f + n * 56;
            int fc0 = pc[l];
            int fc1 = (l < 24) ? pc[32 + l] : 0;
#pragma unroll 1
            for (int k = 0; k < 8; k++) {
                float c0, c1;
                center_embed<7>(fc0, fc1, k * 7, upB, c0, c1);
                float icd = fminf(__frsqrt_rn(bfly_add(fmaf(c1, c1, c0 * c0))), 1e6f);
                float a0, a1, q0, q1;
                ga_tbl<7>(u2u_f + (n * 8 + k) * 56, upB, u2u_w + (n * 8 + k) * 8,
                          c0, c1, icd, l, a0, a1);
                ga_tbl<5>(u2url_f + (n * 8 + k) * 40, vpB, u2url_w + (n * 8 + k) * 8,
                          c0, c1, icd, l, q0, q1);
                xsw[l * XS_STRIDE + k]        = c0;
                xsw[(32 + l) * XS_STRIDE + k] = c1;
                xsw[(64 + l) * XS_STRIDE + k] = (a0 + q0) * 0.5f;
                xsw[(96 + l) * XS_STRIDE + k] = (a1 + q1) * 0.5f;
            }
            __syncwarp();
            lin_mma(AWhi, AWlo, xsw, bA, bB, l);
#pragma unroll
            for (int k = 0; k < 8; k++) {
                eB0[k] = xsw[l * XS_STRIDE + k];
                eB1[k] = xsw[(32 + l) * XS_STRIDE + k];
            }
            __syncwarp();
        }

        // ---- stage A: url branch (hop2 -> hop1) -> Y stays in xsw ----
        {
            const int* pc = u1url_f + n * 40;
            int fc0 = pc[l];
            int fc1 = (l < 8) ? pc[32 + l] : 0;
#pragma unroll 1
            for (int k = 0; k < 8; k++) {
                float c0, c1;
                center_embed<5>(fc0, fc1, k * 5, vpB, c0, c1);
                float icd = fminf(__frsqrt_rn(bfly_add(fmaf(c1, c1, c0 * c0))), 1e6f);
                float a0, a1, q0, q1;
                ga_tbl<7>(url2u_f + (n * 8 + k) * 56, upB, url2u_w + (n * 8 + k) * 8,
                          c0, c1, icd, l, a0, a1);
                ga_tbl<5>(url2url_f + (n * 8 + k) * 40, vpB, url2url_w + (n * 8 + k) * 8,
                          c0, c1, icd, l, q0, q1);
                xsw[l * XS_STRIDE + k]        = c0;
                xsw[(32 + l) * XS_STRIDE + k] = c1;
                xsw[(64 + l) * XS_STRIDE + k] = (a0 + q0) * 0.5f;
                xsw[(96 + l) * XS_STRIDE + k] = (a1 + q1) * 0.5f;
            }
            __syncwarp();
            lin_mma(AWhi, AWlo, xsw, bA, bB, l);
        }

        // ---- stage C: hop1 -> center ----
        {
            int uf = (l < 7) ? user_f[n * 7 + l] : 0;
            float c0, c1;
            center_embed<7>(uf, 0, 0, upB, c0, c1);
            float icd = fminf(__frsqrt_rn(bfly_add(fmaf(c1, c1, c0 * c0))), 1e6f);

            // eA from xsw (stage A's Y) — read before clobbering column 0
            float eA0[8], eA1[8];
#pragma unroll
            for (int k = 0; k < 8; k++) {
                eA0[k] = xsw[l * XS_STRIDE + k];
                eA1[k] = xsw[(32 + l) * XS_STRIDE + k];
            }

            float a0, a1, q0, q1;
            ga_reg(eA0, eA1, u1url_w + n * 8, c0, c1, icd, l, a0, a1);
            ga_reg(eB0, eB1, u1u_w + n * 8, c0, c1, icd, l, q0, q1);

            xsw[l * XS_STRIDE]        = c0;
            xsw[(32 + l) * XS_STRIDE] = c1;
            xsw[(64 + l) * XS_STRIDE] = (a0 + q0) * 0.5f;
            xsw[(96 + l) * XS_STRIDE] = (a1 + q1) * 0.5f;
            __syncwarp();

            float s0 = b10, s1 = b11, u0 = 0.f, u1 = 0.f;
#pragma unroll 8
            for (int i = 0; i < 128; i += 2) {
                float x0 = xsw[i * XS_STRIDE];
                float x1 = xsw[(i + 1) * XS_STRIDE];
                float2 w0 = __ldg(W1T + i * 32 + l);
                float2 w1 = __ldg(W1T + (i + 1) * 32 + l);
                s0 = fmaf(w0.x, x0, s0); s1 = fmaf(w0.y, x0, s1);
                u0 = fmaf(w1.x, x1, u0); u1 = fmaf(w1.y, x1, u1);
            }
            __syncwarp();
            float ue0 = fmaxf(s0 + u0, 0.f);
            float ue1 = fmaxf(s1 + u1, 0.f);

            int vf = (l < 5) ? url_f[n * 5 + l] : 0;
            float v0, v1;
            center_embed<5>(vf, 0, 0, vpB, v0, v1);

            float p0 = fmaf(wo0, ue0, fmaf(wo1, ue1, fmaf(wo2, v0, wo3 * v1)));
            float p1 = fmaf(wo4, ue0, fmaf(wo5, ue1, fmaf(wo6, v0, wo7 * v1)));
            ull pp = pack2(p0, p1);
#pragma unroll
            for (int o = 16; o; o >>= 1) {
                ull q = __shfl_xor_sync(FULL, pp, o);
                addp(pp, q);
            }
            if (l == 0) {
                p0 = lo32(pp) + bo0; p1 = hi32(pp) + bo1;
                float mm = fmaxf(p0, p1);
                float z0 = __expf(p0 - mm), z1 = __expf(p1 - mm);
                float inv = __fdividef(1.f, z0 + z1);
                *(float2*)(out + n * 2) = make_float2(z0 * inv, z1 * inv);
            }
        }
    }
}

extern "C" void kernel_launch(void* const* d_in, const int* in_sizes, int n_in,
                              void* d_out, int out_size) {
    const int*   user_f    = (const int*)d_in[1];
    const int*   url_f     = (const int*)d_in[2];
    const int*   u1u_f     = (const int*)d_in[3];
    const float* u1u_w     = (const float*)d_in[4];
    const int*   u1url_f   = (const int*)d_in[5];
    const float* u1url_w   = (const float*)d_in[6];
    const int*   u2u_f     = (const int*)d_in[7];
    const float* u2u_w     = (const float*)d_in[8];
    const int*   u2url_f   = (const int*)d_in[9];
    const float* u2url_w   = (const float*)d_in[10];
    const int*   url2u_f   = (const int*)d_in[11];
    const float* url2u_w   = (const float*)d_in[12];
    const int*   url2url_f = (const int*)d_in[13];
    const float* url2url_w = (const float*)d_in[14];
    const float* user_table = (const float*)d_in[15];
    const float* url_table  = (const float*)d_in[16];
    const float* W2 = (const float*)d_in[17];
    const float* b2 = (const float*)d_in[18];
    const float* W1 = (const float*)d_in[19];
    const float* b1 = (const float*)d_in[20];
    const float* Wo = (const float*)d_in[21];
    const float* bo = (const float*)d_in[22];
    float* out = (float*)d_out;

    int N = in_sizes[0];

    cudaFuncSetAttribute(gcn_kernel, cudaFuncAttributeMaxDynamicSharedMemorySize, SMEM_BYTES);
    int sm = 148;
    cudaDeviceGetAttribute(&sm, cudaDevAttrMultiProcessorCount, 0);

    prep_kernel<<<16, 256>>>(W1);
    gcn_kernel<<<sm, 512, SMEM_BYTES>>>(
        user_f, url_f, u1u_f, u1u_w, u1url_f, u1url_w,
        u2u_f, u2u_w, u2url_f, u2url_w,
        url2u_f, url2u_w, url2url_f, url2url_w,
        user_table, url_table, W2, b2, b1, Wo, bo, out, N);
}

// round 11
// speedup vs baseline: 2.8950x; 1.0901x over previous
#include <cuda_runtime.h>
#include <cuda_bf16.h>
#include <cstdint>

#define FULL 0xffffffffu
typedef unsigned long long ull;

__constant__ int UOFF[7] = {0, 11577, 11588, 11599, 11610, 11621, 11642};
__constant__ int VOFF[5] = {0, 4733, 4754, 4761, 4772};

constexpr int NWARP = 16;
constexpr int XS_STRIDE = 9;
constexpr int XS_FLOATS = 128 * XS_STRIDE;   // 1152 per warp
constexpr int AW_FLOATS = 32 * 32 * 4;       // 4096 floats each (bf16 hi / lo frag tables)
constexpr int UP_FLOATS = (3 * 49 + 7) * 64; // 9856: 3 user pair tables + 7-entry single
constexpr int VP_FLOATS = (2 * 49 + 7) * 64; // 6720: 2 url pair tables + 7-entry single
constexpr int PAIR_STRIDE_B = 49 * 256;      // 12544 bytes per pair table
constexpr int SMEM_FLOATS = 2 * AW_FLOATS + UP_FLOATS + VP_FLOATS + NWARP * XS_FLOATS;
constexpr int SMEM_BYTES = SMEM_FLOATS * 4;  // 172800

__device__ float2 W1T[128 * 32];   // [(i*32+l)] = (W1[l][i], W1[l+32][i])
__device__ unsigned int g_ctr;

__global__ void prep_kernel(const float* __restrict__ W1) {
    int i = blockIdx.x * blockDim.x + threadIdx.x;
    if (i == 0) g_ctr = 0;
    if (i < 128 * 32) {
        int col = i >> 5, l = i & 31;
        W1T[i] = make_float2(W1[l * 128 + col], W1[(l + 32) * 128 + col]);
    }
}

__device__ __forceinline__ float bfly_add(float v) {
#pragma unroll
    for (int o = 16; o; o >>= 1) v += __shfl_xor_sync(FULL, v, o);
    return v;
}
__device__ __forceinline__ void addp(ull& a, ull b) {
    asm("add.rn.f32x2 %0, %0, %1;" : "+l"(a) : "l"(b));
}
__device__ __forceinline__ ull pack2(float x, float y) {
    ull r; asm("mov.b64 %0, {%1, %2};" : "=l"(r) : "f"(x), "f"(y));
    return r;
}
__device__ __forceinline__ float lo32(ull v) { return __uint_as_float((unsigned)v); }
__device__ __forceinline__ float hi32(ull v) { return __uint_as_float((unsigned)(v >> 32)); }

// pack two floats as bf16x2 (first arg -> low half / lower k index)
__device__ __forceinline__ unsigned pk_bf(float lo, float hi) {
    __nv_bfloat162 h;
    h.x = __float2bfloat16_rn(lo);
    h.y = __float2bfloat16_rn(hi);
    return *(unsigned*)&h;
}
__device__ __forceinline__ float bfr(float x) {
    return __bfloat162float(__float2bfloat16_rn(x));
}

__device__ __forceinline__ void mma16(float (&c)[4], const uint4& a, unsigned b0, unsigned b1) {
    asm volatile("mma.sync.aligned.m16n8k16.row.col.f32.bf16.bf16.f32 "
                 "{%0,%1,%2,%3},{%4,%5,%6,%7},{%8,%9},{%0,%1,%2,%3};"
                 : "+f"(c[0]), "+f"(c[1]), "+f"(c[2]), "+f"(c[3])
                 : "r"(a.x), "r"(a.y), "r"(a.z), "r"(a.w), "r"(b0), "r"(b1));
}

// precombine adjacent-feature pair offsets:
// o0[l] = f[l]*1792 + f[l+1]*256 (l+1 wraps into f1 at lane 31); o1 same for f1.
__device__ __forceinline__ void precomb(int f0, int f1, int l, int& o0, int& o1) {
    int f0n = __shfl_down_sync(FULL, f0, 1);
    int f10 = __shfl_sync(FULL, f1, 0);
    f0n = (l == 31) ? f10 : f0n;
    int f1n = __shfl_down_sync(FULL, f1, 1);
    o0 = f0 * 1792 + (f0n << 8);
    o1 = f1 * 1792 + (f1n << 8);
}

// pair-table embed for one feature-list segment at warp-uniform `base`.
template <int NF>
__device__ __forceinline__ void center_embed(int f0, int f1, int o0, int o1, int base,
                                             const char* tbB, float& c0, float& c1) {
    constexpr int SINGLE_B = ((NF + 1) / 2 - 1) * PAIR_STRIDE_B;
    ull acc = 0;
#pragma unroll
    for (int p = 0; 2 * p + 1 < NF; p++) {
        int pa = base + 2 * p;
        int off = __shfl_sync(FULL, (pa < 32) ? o0 : o1, pa & 31);
        addp(acc, *(const ull*)(tbB + off + p * PAIR_STRIDE_B));
    }
    int ps = base + NF - 1;
    int ia = __shfl_sync(FULL, (ps < 32) ? f0 : f1, ps & 31);
    addp(acc, *(const ull*)(tbB + (ia << 8) + SINGLE_B));
    c0 = lo32(acc); c1 = hi32(acc);
}

// softmax(cosine) + weighted relu-sum over 8 neighbors.
// fold-and-redistribute multi-reduce; lane 4j owns neighbor j's (d,nn) sum.
__device__ __forceinline__ void ga_tail(const float (&e0)[8], const float (&e1)[8],
                                        float (&d)[8], float (&nn)[8],
                                        const float* __restrict__ wptr, float icd,
                                        int l, float& out0, float& out1) {
    ull P[8];
#pragma unroll
    for (int kk = 0; kk < 8; kk++) P[kk] = pack2(d[kk], nn[kk]);
#pragma unroll
    for (int i = 0; i < 8; i++) addp(P[i], __shfl_xor_sync(FULL, P[i], 16));
    bool b4 = (l & 16) != 0;
    ull Q[4];
#pragma unroll
    for (int i = 0; i < 4; i++) Q[i] = b4 ? P[i + 4] : P[i];
#pragma unroll
    for (int i = 0; i < 4; i++) addp(Q[i], __shfl_xor_sync(FULL, Q[i], 8));
    bool b3 = (l & 8) != 0;
    ull R0 = b3 ? Q[2] : Q[0];
    ull R1 = b3 ? Q[3] : Q[1];
    addp(R0, __shfl_xor_sync(FULL, R0, 4));
    addp(R1, __shfl_xor_sync(FULL, R1, 4));
    ull S = (l & 4) ? R1 : R0;
    addp(S, __shfl_xor_sync(FULL, S, 2));
    addp(S, __shfl_xor_sync(FULL, S, 1));
    float rr = fminf(__frsqrt_rn(hi32(S)), 1e6f);      // 1/max(sqrt(nn),1e-6)
    float mycw = __expf(lo32(S) * rr * icd);           // cosine in [-1,1]; safe
    float4 wA = *(const float4*)wptr;
    float4 wB = *(const float4*)(wptr + 4);
    float w[8] = {wA.x, wA.y, wA.z, wA.w, wB.x, wB.y, wB.z, wB.w};
    float cw[8];
#pragma unroll
    for (int k = 0; k < 8; k++) cw[k] = __shfl_sync(FULL, mycw, 4 * k);
    float s = 0.f;
#pragma unroll
    for (int k = 0; k < 8; k++) s += cw[k];
    float inv = __fdividef(1.f, s);
    float o0 = 0.f, o1 = 0.f;
#pragma unroll
    for (int k = 0; k < 8; k++) {
        float sc = cw[k] * inv;
        o0 = fmaf(fmaxf(e0[k] * w[k], 0.f), sc, o0);
        o1 = fmaf(fmaxf(e1[k] * w[k], 0.f), sc, o1);
    }
    out0 = o0; out1 = o1;
}

// graph attention over 8 neighbors via pair tables with precombined offsets;
// all shuffle positions compile-time.
template <int NF>
__device__ __forceinline__ void ga_tbl(const int* __restrict__ flist,
                                       const char* tbB,
                                       const float* __restrict__ wptr,
                                       float c0, float c1, float icd, int l,
                                       float& out0, float& out1) {
    constexpr int SINGLE_B = ((NF + 1) / 2 - 1) * PAIR_STRIDE_B;
    int f0 = flist[l];
    int f1 = (l < 8 * NF - 32) ? flist[32 + l] : 0;
    int o0, o1;
    precomb(f0, f1, l, o0, o1);
    float e0[8], e1[8], d[8], nn[8];
#pragma unroll
    for (int kk = 0; kk < 8; kk++) {
        ull acc = 0;
#pragma unroll
        for (int p = 0; 2 * p + 1 < NF; p++) {
            const int pa = kk * NF + 2 * p;
            int off = __shfl_sync(FULL, (pa < 32) ? o0 : o1, pa & 31);
            addp(acc, *(const ull*)(tbB + off + p * PAIR_STRIDE_B));
        }
        {
            const int ps = kk * NF + NF - 1;
            int ia = __shfl_sync(FULL, (ps < 32) ? f0 : f1, ps & 31);
            addp(acc, *(const ull*)(tbB + (ia << 8) + SINGLE_B));
        }
        float a0 = lo32(acc), a1 = hi32(acc);
        e0[kk] = a0; e1[kk] = a1;
        d[kk]  = fmaf(a1, c1, a0 * c0);
        nn[kk] = fmaf(a1, a1, a0 * a0);
    }
    ga_tail(e0, e1, d, nn, wptr, icd, l, out0, out1);
}

__device__ __forceinline__ void ga_reg(const float (&e0)[8], const float (&e1)[8],
                                       const float* __restrict__ wptr,
                                       float c0, float c1, float icd, int l,
                                       float& out0, float& out1) {
    float d[8], nn[8];
#pragma unroll
    for (int kk = 0; kk < 8; kk++) {
        d[kk]  = fmaf(e1[kk], c1, e0[kk] * c0);
        nn[kk] = fmaf(e1[kk], e1[kk], e0[kk] * e0[kk]);
    }
    ga_tail(e0, e1, d, nn, wptr, icd, l, out0, out1);
}

// relu(W2(64x128) @ X[128x8] + b2) via 3xBF16-k16 mma (hi/lo split);
// Y written back into xsw (stride XS_STRIDE)
__device__ __forceinline__ void lin_mma(const uint4* __restrict__ AWhi,
                                        const uint4* __restrict__ AWlo,
                                        float* __restrict__ xsw,
                                        const float (&bA)[4], const float (&bB)[4],
                                        int lane) {
    int g = lane >> 2, tg = lane & 3;
    float acc[4][4];
#pragma unroll
    for (int m = 0; m < 4; m++) {
        acc[m][0] = bA[m]; acc[m][1] = bA[m];
        acc[m][2] = bB[m]; acc[m][3] = bB[m];
    }
#pragma unroll 2
    for (int kt = 0; kt < 8; kt++) {
        int r0 = 16 * kt + 2 * tg;
        float xa0 = xsw[r0 * XS_STRIDE + g];
        float xa1 = xsw[(r0 + 1) * XS_STRIDE + g];
        float xb0 = xsw[(r0 + 8) * XS_STRIDE + g];
        float xb1 = xsw[(r0 + 9) * XS_STRIDE + g];
        float ha0 = bfr(xa0), ha1 = bfr(xa1), hb0 = bfr(xb0), hb1 = bfr(xb1);
        unsigned Bh0 = pk_bf(ha0, ha1), Bh1 = pk_bf(hb0, hb1);
        unsigned Bl0 = pk_bf(xa0 - ha0, xa1 - ha1), Bl1 = pk_bf(xb0 - hb0, xb1 - hb1);
        const uint4* ph = AWhi + kt * 4 * 32 + lane;
        const uint4* pl = AWlo + kt * 4 * 32 + lane;
#pragma unroll
        for (int m = 0; m < 4; m++) {
            uint4 ah = ph[m * 32];
            uint4 al = pl[m * 32];
            mma16(acc[m], ah, Bh0, Bh1);
            mma16(acc[m], ah, Bl0, Bl1);
            mma16(acc[m], al, Bh0, Bh1);
        }
    }
    __syncwarp();
#pragma unroll
    for (int m = 0; m < 4; m++) {
        xsw[(16 * m + g) * XS_STRIDE + 2 * tg]         = fmaxf(acc[m][0], 0.f);
        xsw[(16 * m + g) * XS_STRIDE + 2 * tg + 1]     = fmaxf(acc[m][1], 0.f);
        xsw[(16 * m + g + 8) * XS_STRIDE + 2 * tg]     = fmaxf(acc[m][2], 0.f);
        xsw[(16 * m + g + 8) * XS_STRIDE + 2 * tg + 1] = fmaxf(acc[m][3], 0.f);
    }
    __syncwarp();
}

__global__ void __launch_bounds__(512, 1)
gcn_kernel(const int* __restrict__ user_f, const int* __restrict__ url_f,
           const int* __restrict__ u1u_f, const float* __restrict__ u1u_w,
           const int* __restrict__ u1url_f, const float* __restrict__ u1url_w,
           const int* __restrict__ u2u_f, const float* __restrict__ u2u_w,
           const int* __restrict__ u2url_f, const float* __restrict__ u2url_w,
           const int* __restrict__ url2u_f, const float* __restrict__ url2u_w,
           const int* __restrict__ url2url_f, const float* __restrict__ url2url_w,
           const float* __restrict__ user_table, const float* __restrict__ url_table,
           const float* __restrict__ W2, const float* __restrict__ b2,
           const float* __restrict__ b1,
           const float* __restrict__ Wo, const float* __restrict__ bo,
           float* __restrict__ out, int N) {
    extern __shared__ float smf[];
    float* AWhiF = smf;
    float* AWloF = smf + AW_FLOATS;
    float* upF   = smf + 2 * AW_FLOATS;
    float* vpF   = upF + UP_FLOATS;
    float* xsAll = vpF + VP_FLOATS;

    int tid = threadIdx.x;

    // ---- W2 A-fragments for m16n8k16 bf16, hi/lo split (frag fid = kt*4+m) ----
    for (int i = tid; i < 1024; i += 512) {
        int fid = i >> 5, ln = i & 31;
        int kt = fid >> 2, m = fid & 3;
        int gg = ln >> 2, tg = ln & 3;
        int r0 = 16 * m + gg, r1 = r0 + 8;
        int c0 = 16 * kt + 2 * tg, c1 = c0 + 1, c2 = c0 + 8, c3 = c0 + 9;
        float v00 = W2[r0 * 128 + c0], v01 = W2[r0 * 128 + c1];
        float v10 = W2[r1 * 128 + c0], v11 = W2[r1 * 128 + c1];
        float v02 = W2[r0 * 128 + c2], v03 = W2[r0 * 128 + c3];
        float v12 = W2[r1 * 128 + c2], v13 = W2[r1 * 128 + c3];
        float h00 = bfr(v00), h01 = bfr(v01), h10 = bfr(v10), h11 = bfr(v11);
        float h02 = bfr(v02), h03 = bfr(v03), h12 = bfr(v12), h13 = bfr(v13);
        uint4 hi, lo;
        hi.x = pk_bf(h00, h01); hi.y = pk_bf(h10, h11);
        hi.z = pk_bf(h02, h03); hi.w = pk_bf(h12, h13);
        lo.x = pk_bf(v00 - h00, v01 - h01); lo.y = pk_bf(v10 - h10, v11 - h11);
        lo.z = pk_bf(v02 - h02, v03 - h03); lo.w = pk_bf(v12 - h12, v13 - h13);
        ((uint4*)AWhiF)[fid * 32 + ln] = hi;
        ((uint4*)AWloF)[fid * 32 + ln] = lo;
    }
    // ---- user tables: P0=(c0,c1) P1=(c2,c3) P2=(c4,c5) then 7-entry single (c6) ----
    for (int i = tid; i < UP_FLOATS; i += 512) {
        int e = i >> 6, q = i & 63, ln = q >> 1, c = q & 1;
        int dim = ln + 32 * c;
        float v;
        if (e < 147) {
            int p = e / 49, rem = e % 49, ia = rem / 7, ib = rem % 7;
            v = user_table[(UOFF[2 * p] + ia) * 64 + dim]
              + user_table[(UOFF[2 * p + 1] + ib) * 64 + dim];
        } else {
            v = user_table[(UOFF[6] + (e - 147)) * 64 + dim];
        }
        upF[i] = v;
    }
    // ---- url tables: P0=(c0,c1) P1=(c2,c3) then 7-entry single (c4) ----
    for (int i = tid; i < VP_FLOATS; i += 512) {
        int e = i >> 6, q = i & 63, ln = q >> 1, c = q & 1;
        int dim = ln + 32 * c;
        float v;
        if (e < 98) {
            int p = e / 49, rem = e % 49, ia = rem / 7, ib = rem % 7;
            v = url_table[(VOFF[2 * p] + ia) * 64 + dim]
              + url_table[(VOFF[2 * p + 1] + ib) * 64 + dim];
        } else {
            v = url_table[(VOFF[4] + (e - 98)) * 64 + dim];
        }
        vpF[i] = v;
    }
    __syncthreads();

    int l   = tid & 31;
    int wrp = tid >> 5;
    float* xsw = xsAll + wrp * XS_FLOATS;
    const char* upB = (const char*)upF + (l << 3);
    const char* vpB = (const char*)vpF + (l << 3);
    const uint4* AWhi = (const uint4*)AWhiF;
    const uint4* AWlo = (const uint4*)AWloF;

    int g = l >> 2;
    float bA[4], bB[4];
#pragma unroll
    for (int m = 0; m < 4; m++) { bA[m] = __ldg(b2 + 16 * m + g); bB[m] = __ldg(b2 + 16 * m + 8 + g); }
    float b10 = __ldg(b1 + l), b11 = __ldg(b1 + 32 + l);
    float wo0 = __ldg(Wo + l),       wo1 = __ldg(Wo + 32 + l);
    float wo2 = __ldg(Wo + 64 + l),  wo3 = __ldg(Wo + 96 + l);
    float wo4 = __ldg(Wo + 128 + l), wo5 = __ldg(Wo + 160 + l);
    float wo6 = __ldg(Wo + 192 + l), wo7 = __ldg(Wo + 224 + l);
    float bo0 = __ldg(bo), bo1 = __ldg(bo + 1);

    for (;;) {
        int n;
        if (l == 0) n = (int)atomicAdd(&g_ctr, 1u);
        n = __shfl_sync(FULL, n, 0);
        if (n >= N) break;

        // ---- stage B: user branch (hop2 -> hop1) -> eB regs ----
        float eB0[8], eB1[8];
        {
            const int* pc = u1u_f + n * 56;
            int fc0 = pc[l];
            int fc1 = (l < 24) ? pc[32 + l] : 0;
            int oc0, oc1;
            precomb(fc0, fc1, l, oc0, oc1);
#pragma unroll 1
            for (int k = 0; k < 8; k++) {
                float c0, c1;
                center_embed<7>(fc0, fc1, oc0, oc1, k * 7, upB, c0, c1);
                float icd = fminf(__frsqrt_rn(bfly_add(fmaf(c1, c1, c0 * c0))), 1e6f);
                float a0, a1, q0, q1;
                ga_tbl<7>(u2u_f + (n * 8 + k) * 56, upB, u2u_w + (n * 8 + k) * 8,
                          c0, c1, icd, l, a0, a1);
                ga_tbl<5>(u2url_f + (n * 8 + k) * 40, vpB, u2url_w + (n * 8 + k) * 8,
                          c0, c1, icd, l, q0, q1);
                xsw[l * XS_STRIDE + k]        = c0;
                xsw[(32 + l) * XS_STRIDE + k] = c1;
                xsw[(64 + l) * XS_STRIDE + k] = (a0 + q0) * 0.5f;
                xsw[(96 + l) * XS_STRIDE + k] = (a1 + q1) * 0.5f;
            }
            __syncwarp();
            lin_mma(AWhi, AWlo, xsw, bA, bB, l);
#pragma unroll
            for (int k = 0; k < 8; k++) {
                eB0[k] = xsw[l * XS_STRIDE + k];
                eB1[k] = xsw[(32 + l) * XS_STRIDE + k];
            }
            __syncwarp();
        }

        // ---- stage A: url branch (hop2 -> hop1) -> Y stays in xsw ----
        {
            const int* pc = u1url_f + n * 40;
            int fc0 = pc[l];
            int fc1 = (l < 8) ? pc[32 + l] : 0;
            int oc0, oc1;
            precomb(fc0, fc1, l, oc0, oc1);
#pragma unroll 1
            for (int k = 0; k < 8; k++) {
                float c0, c1;
                center_embed<5>(fc0, fc1, oc0, oc1, k * 5, vpB, c0, c1);
                float icd = fminf(__frsqrt_rn(bfly_add(fmaf(c1, c1, c0 * c0))), 1e6f);
                float a0, a1, q0, q1;
                ga_tbl<7>(url2u_f + (n * 8 + k) * 56, upB, url2u_w + (n * 8 + k) * 8,
                          c0, c1, icd, l, a0, a1);
                ga_tbl<5>(url2url_f + (n * 8 + k) * 40, vpB, url2url_w + (n * 8 + k) * 8,
                          c0, c1, icd, l, q0, q1);
                xsw[l * XS_STRIDE + k]        = c0;
                xsw[(32 + l) * XS_STRIDE + k] = c1;
                xsw[(64 + l) * XS_STRIDE + k] = (a0 + q0) * 0.5f;
                xsw[(96 + l) * XS_STRIDE + k] = (a1 + q1) * 0.5f;
            }
            __syncwarp();
            lin_mma(AWhi, AWlo, xsw, bA, bB, l);
        }

        // ---- stage C: hop1 -> center ----
        {
            int uf = (l < 7) ? user_f[n * 7 + l] : 0;
            int ou0, ou1;
            precomb(uf, 0, l, ou0, ou1);
            float c0, c1;
            center_embed<7>(uf, 0, ou0, ou1, 0, upB, c0, c1);
            float icd = fminf(__frsqrt_rn(bfly_add(fmaf(c1, c1, c0 * c0))), 1e6f);

            // eA from xsw (stage A's Y) — read before clobbering column 0
            float eA0[8], eA1[8];
#pragma unroll
            for (int k = 0; k < 8; k++) {
                eA0[k] = xsw[l * XS_STRIDE + k];
                eA1[k] = xsw[(32 + l) * XS_STRIDE + k];
            }

            float a0, a1, q0, q1;
            ga_reg(eA0, eA1, u1url_w + n * 8, c0, c1, icd, l, a0, a1);
            ga_reg(eB0, eB1, u1u_w + n * 8, c0, c1, icd, l, q0, q1);

            xsw[l * XS_STRIDE]        = c0;
            xsw[(32 + l) * XS_STRIDE] = c1;
            xsw[(64 + l) * XS_STRIDE] = (a0 + q0) * 0.5f;
            xsw[(96 + l) * XS_STRIDE] = (a1 + q1) * 0.5f;
            __syncwarp();

            float s0 = b10, s1 = b11, u0 = 0.f, u1 = 0.f;
#pragma unroll 8
            for (int i = 0; i < 128; i += 2) {
                float x0 = xsw[i * XS_STRIDE];
                float x1 = xsw[(i + 1) * XS_STRIDE];
                float2 w0 = __ldg(W1T + i * 32 + l);
                float2 w1 = __ldg(W1T + (i + 1) * 32 + l);
                s0 = fmaf(w0.x, x0, s0); s1 = fmaf(w0.y, x0, s1);
                u0 = fmaf(w1.x, x1, u0); u1 = fmaf(w1.y, x1, u1);
            }
            __syncwarp();
            float ue0 = fmaxf(s0 + u0, 0.f);
            float ue1 = fmaxf(s1 + u1, 0.f);

            int vf = (l < 5) ? url_f[n * 5 + l] : 0;
            int ov0, ov1;
            precomb(vf, 0, l, ov0, ov1);
            float v0, v1;
            center_embed<5>(vf, 0, ov0, ov1, 0, vpB, v0, v1);

            float p0 = fmaf(wo0, ue0, fmaf(wo1, ue1, fmaf(wo2, v0, wo3 * v1)));
            float p1 = fmaf(wo4, ue0, fmaf(wo5, ue1, fmaf(wo6, v0, wo7 * v1)));
            ull pp = pack2(p0, p1);
#pragma unroll
            for (int o = 16; o; o >>= 1) {
                ull q = __shfl_xor_sync(FULL, pp, o);
                addp(pp, q);
            }
            if (l == 0) {
                p0 = lo32(pp) + bo0; p1 = hi32(pp) + bo1;
                float mm = fmaxf(p0, p1);
                float z0 = __expf(p0 - mm), z1 = __expf(p1 - mm);
                float inv = __fdividef(1.f, z0 + z1);
                *(float2*)(out + n * 2) = make_float2(z0 * inv, z1 * inv);
            }
        }
    }
}

extern "C" void kernel_launch(void* const* d_in, const int* in_sizes, int n_in,
                              void* d_out, int out_size) {
    const int*   user_f    = (const int*)d_in[1];
    const int*   url_f     = (const int*)d_in[2];
    const int*   u1u_f     = (const int*)d_in[3];
    const float* u1u_w     = (const float*)d_in[4];
    const int*   u1url_f   = (const int*)d_in[5];
    const float* u1url_w   = (const float*)d_in[6];
    const int*   u2u_f     = (const int*)d_in[7];
    const float* u2u_w     = (const float*)d_in[8];
    const int*   u2url_f   = (const int*)d_in[9];
    const float* u2url_w   = (const float*)d_in[10];
    const int*   url2u_f   = (const int*)d_in[11];
    const float* url2u_w   = (const float*)d_in[12];
    const int*   url2url_f = (const int*)d_in[13];
    const float* url2url_w = (const float*)d_in[14];
    const float* user_table = (const float*)d_in[15];
    const float* url_table  = (const float*)d_in[16];
    const float* W2 = (const float*)d_in[17];
    const float* b2 = (const float*)d_in[18];
    const float* W1 = (const float*)d_in[19];
    const float* b1 = (const float*)d_in[20];
    const float* Wo = (const float*)d_in[21];
    const float* bo = (const float*)d_in[22];
    float* out = (float*)d_out;

    int N = in_sizes[0];

    cudaFuncSetAttribute(gcn_kernel, cudaFuncAttributeMaxDynamicSharedMemorySize, SMEM_BYTES);
    int sm = 148;
    cudaDeviceGetAttribute(&sm, cudaDevAttrMultiProcessorCount, 0);

    prep_kernel<<<16, 256>>>(W1);
    gcn_kernel<<<sm, 512, SMEM_BYTES>>>(
        user_f, url_f, u1u_f, u1u_w, u1url_f, u1url_w,
        u2u_f, u2u_w, u2url_f, u2url_w,
        url2u_f, url2u_w, url2url_f, url2url_w,
        user_table, url_table, W2, b2, b1, Wo, bo, out, N);
}

// round 12
// speedup vs baseline: 2.9446x; 1.0171x over previous
#include <cuda_runtime.h>
#include <cuda_bf16.h>
#include <cstdint>

#define FULL 0xffffffffu
typedef unsigned long long ull;

__constant__ int UOFF[7] = {0, 11577, 11588, 11599, 11610, 11621, 11642};
__constant__ int VOFF[5] = {0, 4733, 4754, 4761, 4772};

constexpr int NWARP = 20;
constexpr int NTHREADS = NWARP * 32;         // 640
constexpr int XS_STRIDE = 9;
constexpr int XS_FLOATS = 128 * XS_STRIDE;   // 1152 per warp
constexpr int AW_FLOATS = 32 * 32 * 4;       // 4096 floats each (bf16 hi / lo frag tables)
constexpr int UP_FLOATS = (3 * 49 + 7) * 64; // 9856: 3 user pair tables + 7-entry single
constexpr int VP_FLOATS = (2 * 49 + 7) * 64; // 6720: 2 url pair tables + 7-entry single
constexpr int PAIR_STRIDE_B = 49 * 256;      // 12544 bytes per pair table
constexpr int SMEM_FLOATS = 2 * AW_FLOATS + UP_FLOATS + VP_FLOATS + NWARP * XS_FLOATS;
constexpr int SMEM_BYTES = SMEM_FLOATS * 4;  // 191232

__device__ float2 W1T[128 * 32];   // [(i*32+l)] = (W1[l][i], W1[l+32][i])
__device__ unsigned int g_ctr;

__global__ void prep_kernel(const float* __restrict__ W1) {
    int i = blockIdx.x * blockDim.x + threadIdx.x;
    if (i == 0) g_ctr = 0;
    if (i < 128 * 32) {
        int col = i >> 5, l = i & 31;
        W1T[i] = make_float2(W1[l * 128 + col], W1[(l + 32) * 128 + col]);
    }
}

__device__ __forceinline__ float bfly_add(float v) {
#pragma unroll
    for (int o = 16; o; o >>= 1) v += __shfl_xor_sync(FULL, v, o);
    return v;
}
__device__ __forceinline__ void addp(ull& a, ull b) {
    asm("add.rn.f32x2 %0, %0, %1;" : "+l"(a) : "l"(b));
}
__device__ __forceinline__ ull pack2(float x, float y) {
    ull r; asm("mov.b64 %0, {%1, %2};" : "=l"(r) : "f"(x), "f"(y));
    return r;
}
__device__ __forceinline__ float lo32(ull v) { return __uint_as_float((unsigned)v); }
__device__ __forceinline__ float hi32(ull v) { return __uint_as_float((unsigned)(v >> 32)); }

// pack two floats as bf16x2 (first arg -> low half / lower k index)
__device__ __forceinline__ unsigned pk_bf(float lo, float hi) {
    __nv_bfloat162 h;
    h.x = __float2bfloat16_rn(lo);
    h.y = __float2bfloat16_rn(hi);
    return *(unsigned*)&h;
}
__device__ __forceinline__ float bfr(float x) {
    return __bfloat162float(__float2bfloat16_rn(x));
}

__device__ __forceinline__ void mma16(float (&c)[4], const uint4& a, unsigned b0, unsigned b1) {
    asm volatile("mma.sync.aligned.m16n8k16.row.col.f32.bf16.bf16.f32 "
                 "{%0,%1,%2,%3},{%4,%5,%6,%7},{%8,%9},{%0,%1,%2,%3};"
                 : "+f"(c[0]), "+f"(c[1]), "+f"(c[2]), "+f"(c[3])
                 : "r"(a.x), "r"(a.y), "r"(a.z), "r"(a.w), "r"(b0), "r"(b1));
}

// precombine adjacent-feature pair offsets:
// o0[l] = f[l]*1792 + f[l+1]*256 (l+1 wraps into f1 at lane 31); o1 same for f1.
__device__ __forceinline__ void precomb(int f0, int f1, int l, int& o0, int& o1) {
    int f0n = __shfl_down_sync(FULL, f0, 1);
    int f10 = __shfl_sync(FULL, f1, 0);
    f0n = (l == 31) ? f10 : f0n;
    int f1n = __shfl_down_sync(FULL, f1, 1);
    o0 = f0 * 1792 + (f0n << 8);
    o1 = f1 * 1792 + (f1n << 8);
}

// pair-table embed for one feature-list segment at warp-uniform `base`.
template <int NF>
__device__ __forceinline__ void center_embed(int f0, int f1, int o0, int o1, int base,
                                             const char* tbB, float& c0, float& c1) {
    constexpr int SINGLE_B = ((NF + 1) / 2 - 1) * PAIR_STRIDE_B;
    ull acc = 0;
#pragma unroll
    for (int p = 0; 2 * p + 1 < NF; p++) {
        int pa = base + 2 * p;
        int off = __shfl_sync(FULL, (pa < 32) ? o0 : o1, pa & 31);
        addp(acc, *(const ull*)(tbB + off + p * PAIR_STRIDE_B));
    }
    int ps = base + NF - 1;
    int ia = __shfl_sync(FULL, (ps < 32) ? f0 : f1, ps & 31);
    addp(acc, *(const ull*)(tbB + (ia << 8) + SINGLE_B));
    c0 = lo32(acc); c1 = hi32(acc);
}

// softmax(cosine) + weighted relu-sum over 8 neighbors.
// fold-and-redistribute multi-reduce; lane 4j owns neighbor j's (d,nn) sum.
__device__ __forceinline__ void ga_tail(const float (&e0)[8], const float (&e1)[8],
                                        float (&d)[8], float (&nn)[8],
                                        const float* __restrict__ wptr, float icd,
                                        int l, float& out0, float& out1) {
    ull P[8];
#pragma unroll
    for (int kk = 0; kk < 8; kk++) P[kk] = pack2(d[kk], nn[kk]);
#pragma unroll
    for (int i = 0; i < 8; i++) addp(P[i], __shfl_xor_sync(FULL, P[i], 16));
    bool b4 = (l & 16) != 0;
    ull Q[4];
#pragma unroll
    for (int i = 0; i < 4; i++) Q[i] = b4 ? P[i + 4] : P[i];
#pragma unroll
    for (int i = 0; i < 4; i++) addp(Q[i], __shfl_xor_sync(FULL, Q[i], 8));
    bool b3 = (l & 8) != 0;
    ull R0 = b3 ? Q[2] : Q[0];
    ull R1 = b3 ? Q[3] : Q[1];
    addp(R0, __shfl_xor_sync(FULL, R0, 4));
    addp(R1, __shfl_xor_sync(FULL, R1, 4));
    ull S = (l & 4) ? R1 : R0;
    addp(S, __shfl_xor_sync(FULL, S, 2));
    addp(S, __shfl_xor_sync(FULL, S, 1));
    float rr = fminf(__frsqrt_rn(hi32(S)), 1e6f);      // 1/max(sqrt(nn),1e-6)
    float mycw = __expf(lo32(S) * rr * icd);           // cosine in [-1,1]; safe
    float4 wA = *(const float4*)wptr;
    float4 wB = *(const float4*)(wptr + 4);
    float w[8] = {wA.x, wA.y, wA.z, wA.w, wB.x, wB.y, wB.z, wB.w};
    float cw[8];
#pragma unroll
    for (int k = 0; k < 8; k++) cw[k] = __shfl_sync(FULL, mycw, 4 * k);
    float s = 0.f;
#pragma unroll
    for (int k = 0; k < 8; k++) s += cw[k];
    float inv = __fdividef(1.f, s);
    float o0 = 0.f, o1 = 0.f;
#pragma unroll
    for (int k = 0; k < 8; k++) {
        float sc = cw[k] * inv;
        o0 = fmaf(fmaxf(e0[k] * w[k], 0.f), sc, o0);
        o1 = fmaf(fmaxf(e1[k] * w[k], 0.f), sc, o1);
    }
    out0 = o0; out1 = o1;
}

// graph attention over 8 neighbors via pair tables with precombined offsets;
// all shuffle positions compile-time.
template <int NF>
__device__ __forceinline__ void ga_tbl(const int* __restrict__ flist,
                                       const char* tbB,
                                       const float* __restrict__ wptr,
                                       float c0, float c1, float icd, int l,
                                       float& out0, float& out1) {
    constexpr int SINGLE_B = ((NF + 1) / 2 - 1) * PAIR_STRIDE_B;
    int f0 = flist[l];
    int f1 = (l < 8 * NF - 32) ? flist[32 + l] : 0;
    int o0, o1;
    precomb(f0, f1, l, o0, o1);
    float e0[8], e1[8], d[8], nn[8];
#pragma unroll
    for (int kk = 0; kk < 8; kk++) {
        ull acc = 0;
#pragma unroll
        for (int p = 0; 2 * p + 1 < NF; p++) {
            const int pa = kk * NF + 2 * p;
            int off = __shfl_sync(FULL, (pa < 32) ? o0 : o1, pa & 31);
            addp(acc, *(const ull*)(tbB + off + p * PAIR_STRIDE_B));
        }
        {
            const int ps = kk * NF + NF - 1;
            int ia = __shfl_sync(FULL, (ps < 32) ? f0 : f1, ps & 31);
            addp(acc, *(const ull*)(tbB + (ia << 8) + SINGLE_B));
        }
        float a0 = lo32(acc), a1 = hi32(acc);
        e0[kk] = a0; e1[kk] = a1;
        d[kk]  = fmaf(a1, c1, a0 * c0);
        nn[kk] = fmaf(a1, a1, a0 * a0);
    }
    ga_tail(e0, e1, d, nn, wptr, icd, l, out0, out1);
}

__device__ __forceinline__ void ga_reg(const float (&e0)[8], const float (&e1)[8],
                                       const float* __restrict__ wptr,
                                       float c0, float c1, float icd, int l,
                                       float& out0, float& out1) {
    float d[8], nn[8];
#pragma unroll
    for (int kk = 0; kk < 8; kk++) {
        d[kk]  = fmaf(e1[kk], c1, e0[kk] * c0);
        nn[kk] = fmaf(e1[kk], e1[kk], e0[kk] * e0[kk]);
    }
    ga_tail(e0, e1, d, nn, wptr, icd, l, out0, out1);
}

// relu(W2(64x128) @ X[128x8] + b2) via 3xBF16-k16 mma (hi/lo split);
// Y written back into xsw (stride XS_STRIDE). b2 loaded per call (L1-cached).
__device__ __forceinline__ void lin_mma(const uint4* __restrict__ AWhi,
                                        const uint4* __restrict__ AWlo,
                                        float* __restrict__ xsw,
                                        const float* __restrict__ b2,
                                        int lane) {
    int g = lane >> 2, tg = lane & 3;
    float acc[4][4];
#pragma unroll
    for (int m = 0; m < 4; m++) {
        float bAv = __ldg(b2 + 16 * m + g);
        float bBv = __ldg(b2 + 16 * m + 8 + g);
        acc[m][0] = bAv; acc[m][1] = bAv;
        acc[m][2] = bBv; acc[m][3] = bBv;
    }
#pragma unroll 2
    for (int kt = 0; kt < 8; kt++) {
        int r0 = 16 * kt + 2 * tg;
        float xa0 = xsw[r0 * XS_STRIDE + g];
        float xa1 = xsw[(r0 + 1) * XS_STRIDE + g];
        float xb0 = xsw[(r0 + 8) * XS_STRIDE + g];
        float xb1 = xsw[(r0 + 9) * XS_STRIDE + g];
        float ha0 = bfr(xa0), ha1 = bfr(xa1), hb0 = bfr(xb0), hb1 = bfr(xb1);
        unsigned Bh0 = pk_bf(ha0, ha1), Bh1 = pk_bf(hb0, hb1);
        unsigned Bl0 = pk_bf(xa0 - ha0, xa1 - ha1), Bl1 = pk_bf(xb0 - hb0, xb1 - hb1);
        const uint4* ph = AWhi + kt * 4 * 32 + lane;
        const uint4* pl = AWlo + kt * 4 * 32 + lane;
#pragma unroll
        for (int m = 0; m < 4; m++) {
            uint4 ah = ph[m * 32];
            uint4 al = pl[m * 32];
            mma16(acc[m], ah, Bh0, Bh1);
            mma16(acc[m], ah, Bl0, Bl1);
            mma16(acc[m], al, Bh0, Bh1);
        }
    }
    __syncwarp();
#pragma unroll
    for (int m = 0; m < 4; m++) {
        xsw[(16 * m + g) * XS_STRIDE + 2 * tg]         = fmaxf(acc[m][0], 0.f);
        xsw[(16 * m + g) * XS_STRIDE + 2 * tg + 1]     = fmaxf(acc[m][1], 0.f);
        xsw[(16 * m + g + 8) * XS_STRIDE + 2 * tg]     = fmaxf(acc[m][2], 0.f);
        xsw[(16 * m + g + 8) * XS_STRIDE + 2 * tg + 1] = fmaxf(acc[m][3], 0.f);
    }
    __syncwarp();
}

__global__ void __launch_bounds__(NTHREADS, 1)
gcn_kernel(const int* __restrict__ user_f, const int* __restrict__ url_f,
           const int* __restrict__ u1u_f, const float* __restrict__ u1u_w,
           const int* __restrict__ u1url_f, const float* __restrict__ u1url_w,
           const int* __restrict__ u2u_f, const float* __restrict__ u2u_w,
           const int* __restrict__ u2url_f, const float* __restrict__ u2url_w,
           const int* __restrict__ url2u_f, const float* __restrict__ url2u_w,
           const int* __restrict__ url2url_f, const float* __restrict__ url2url_w,
           const float* __restrict__ user_table, const float* __restrict__ url_table,
           const float* __restrict__ W2, const float* __restrict__ b2,
           const float* __restrict__ b1,
           const float* __restrict__ Wo, const float* __restrict__ bo,
           float* __restrict__ out, int N) {
    extern __shared__ float smf[];
    float* AWhiF = smf;
    float* AWloF = smf + AW_FLOATS;
    float* upF   = smf + 2 * AW_FLOATS;
    float* vpF   = upF + UP_FLOATS;
    float* xsAll = vpF + VP_FLOATS;

    int tid = threadIdx.x;

    // ---- W2 A-fragments for m16n8k16 bf16, hi/lo split (frag fid = kt*4+m) ----
    for (int i = tid; i < 1024; i += NTHREADS) {
        int fid = i >> 5, ln = i & 31;
        int kt = fid >> 2, m = fid & 3;
        int gg = ln >> 2, tg = ln & 3;
        int r0 = 16 * m + gg, r1 = r0 + 8;
        int c0 = 16 * kt + 2 * tg, c1 = c0 + 1, c2 = c0 + 8, c3 = c0 + 9;
        float v00 = W2[r0 * 128 + c0], v01 = W2[r0 * 128 + c1];
        float v10 = W2[r1 * 128 + c0], v11 = W2[r1 * 128 + c1];
        float v02 = W2[r0 * 128 + c2], v03 = W2[r0 * 128 + c3];
        float v12 = W2[r1 * 128 + c2], v13 = W2[r1 * 128 + c3];
        float h00 = bfr(v00), h01 = bfr(v01), h10 = bfr(v10), h11 = bfr(v11);
        float h02 = bfr(v02), h03 = bfr(v03), h12 = bfr(v12), h13 = bfr(v13);
        uint4 hi, lo;
        hi.x = pk_bf(h00, h01); hi.y = pk_bf(h10, h11);
        hi.z = pk_bf(h02, h03); hi.w = pk_bf(h12, h13);
        lo.x = pk_bf(v00 - h00, v01 - h01); lo.y = pk_bf(v10 - h10, v11 - h11);
        lo.z = pk_bf(v02 - h02, v03 - h03); lo.w = pk_bf(v12 - h12, v13 - h13);
        ((uint4*)AWhiF)[fid * 32 + ln] = hi;
        ((uint4*)AWloF)[fid * 32 + ln] = lo;
    }
    // ---- user tables: P0=(c0,c1) P1=(c2,c3) P2=(c4,c5) then 7-entry single (c6) ----
    for (int i = tid; i < UP_FLOATS; i += NTHREADS) {
        int e = i >> 6, q = i & 63, ln = q >> 1, c = q & 1;
        int dim = ln + 32 * c;
        float v;
        if (e < 147) {
            int p = e / 49, rem = e % 49, ia = rem / 7, ib = rem % 7;
            v = user_table[(UOFF[2 * p] + ia) * 64 + dim]
              + user_table[(UOFF[2 * p + 1] + ib) * 64 + dim];
        } else {
            v = user_table[(UOFF[6] + (e - 147)) * 64 + dim];
        }
        upF[i] = v;
    }
    // ---- url tables: P0=(c0,c1) P1=(c2,c3) then 7-entry single (c4) ----
    for (int i = tid; i < VP_FLOATS; i += NTHREADS) {
        int e = i >> 6, q = i & 63, ln = q >> 1, c = q & 1;
        int dim = ln + 32 * c;
        float v;
        if (e < 98) {
            int p = e / 49, rem = e % 49, ia = rem / 7, ib = rem % 7;
            v = url_table[(VOFF[2 * p] + ia) * 64 + dim]
              + url_table[(VOFF[2 * p + 1] + ib) * 64 + dim];
        } else {
            v = url_table[(VOFF[4] + (e - 98)) * 64 + dim];
        }
        vpF[i] = v;
    }
    __syncthreads();

    int l   = tid & 31;
    int wrp = tid >> 5;
    float* xsw = xsAll + wrp * XS_FLOATS;
    const char* upB = (const char*)upF + (l << 3);
    const char* vpB = (const char*)vpF + (l << 3);
    const uint4* AWhi = (const uint4*)AWhiF;
    const uint4* AWlo = (const uint4*)AWloF;

    for (;;) {
        int n;
        if (l == 0) n = (int)atomicAdd(&g_ctr, 1u);
        n = __shfl_sync(FULL, n, 0);
        if (n >= N) break;

        // ---- stage B: user branch (hop2 -> hop1) -> eB regs ----
        float eB0[8], eB1[8];
        {
            const int* pc = u1u_f + n * 56;
            int fc0 = pc[l];
            int fc1 = (l < 24) ? pc[32 + l] : 0;
            int oc0, oc1;
            precomb(fc0, fc1, l, oc0, oc1);
#pragma unroll 1
            for (int k = 0; k < 8; k++) {
                float c0, c1;
                center_embed<7>(fc0, fc1, oc0, oc1, k * 7, upB, c0, c1);
                float icd = fminf(__frsqrt_rn(bfly_add(fmaf(c1, c1, c0 * c0))), 1e6f);
                float a0, a1, q0, q1;
                ga_tbl<7>(u2u_f + (n * 8 + k) * 56, upB, u2u_w + (n * 8 + k) * 8,
                          c0, c1, icd, l, a0, a1);
                ga_tbl<5>(u2url_f + (n * 8 + k) * 40, vpB, u2url_w + (n * 8 + k) * 8,
                          c0, c1, icd, l, q0, q1);
                xsw[l * XS_STRIDE + k]        = c0;
                xsw[(32 + l) * XS_STRIDE + k] = c1;
                xsw[(64 + l) * XS_STRIDE + k] = (a0 + q0) * 0.5f;
                xsw[(96 + l) * XS_STRIDE + k] = (a1 + q1) * 0.5f;
            }
            __syncwarp();
            lin_mma(AWhi, AWlo, xsw, b2, l);
#pragma unroll
            for (int k = 0; k < 8; k++) {
                eB0[k] = xsw[l * XS_STRIDE + k];
                eB1[k] = xsw[(32 + l) * XS_STRIDE + k];
            }
            __syncwarp();
        }

        // ---- stage A: url branch (hop2 -> hop1) -> Y stays in xsw ----
        {
            const int* pc = u1url_f + n * 40;
            int fc0 = pc[l];
            int fc1 = (l < 8) ? pc[32 + l] : 0;
            int oc0, oc1;
            precomb(fc0, fc1, l, oc0, oc1);
#pragma unroll 1
            for (int k = 0; k < 8; k++) {
                float c0, c1;
                center_embed<5>(fc0, fc1, oc0, oc1, k * 5, vpB, c0, c1);
                float icd = fminf(__frsqrt_rn(bfly_add(fmaf(c1, c1, c0 * c0))), 1e6f);
                float a0, a1, q0, q1;
                ga_tbl<7>(url2u_f + (n * 8 + k) * 56, upB, url2u_w + (n * 8 + k) * 8,
                          c0, c1, icd, l, a0, a1);
                ga_tbl<5>(url2url_f + (n * 8 + k) * 40, vpB, url2url_w + (n * 8 + k) * 8,
                          c0, c1, icd, l, q0, q1);
                xsw[l * XS_STRIDE + k]        = c0;
                xsw[(32 + l) * XS_STRIDE + k] = c1;
                xsw[(64 + l) * XS_STRIDE + k] = (a0 + q0) * 0.5f;
                xsw[(96 + l) * XS_STRIDE + k] = (a1 + q1) * 0.5f;
            }
            __syncwarp();
            lin_mma(AWhi, AWlo, xsw, b2, l);
        }

        // ---- stage C: hop1 -> center ----
        {
            int uf = (l < 7) ? user_f[n * 7 + l] : 0;
            int ou0, ou1;
            precomb(uf, 0, l, ou0, ou1);
            float c0, c1;
            center_embed<7>(uf, 0, ou0, ou1, 0, upB, c0, c1);
            float icd = fminf(__frsqrt_rn(bfly_add(fmaf(c1, c1, c0 * c0))), 1e6f);

            // eA from xsw (stage A's Y) — read before clobbering column 0
            float eA0[8], eA1[8];
#pragma unroll
            for (int k = 0; k < 8; k++) {
                eA0[k] = xsw[l * XS_STRIDE + k];
                eA1[k] = xsw[(32 + l) * XS_STRIDE + k];
            }

            float a0, a1, q0, q1;
            ga_reg(eA0, eA1, u1url_w + n * 8, c0, c1, icd, l, a0, a1);
            ga_reg(eB0, eB1, u1u_w + n * 8, c0, c1, icd, l, q0, q1);

            xsw[l * XS_STRIDE]        = c0;
            xsw[(32 + l) * XS_STRIDE] = c1;
            xsw[(64 + l) * XS_STRIDE] = (a0 + q0) * 0.5f;
            xsw[(96 + l) * XS_STRIDE] = (a1 + q1) * 0.5f;
            __syncwarp();

            float s0 = __ldg(b1 + l), s1 = __ldg(b1 + 32 + l), u0 = 0.f, u1 = 0.f;
#pragma unroll 8
            for (int i = 0; i < 128; i += 2) {
                float x0 = xsw[i * XS_STRIDE];
                float x1 = xsw[(i + 1) * XS_STRIDE];
                float2 w0 = __ldg(W1T + i * 32 + l);
                float2 w1 = __ldg(W1T + (i + 1) * 32 + l);
                s0 = fmaf(w0.x, x0, s0); s1 = fmaf(w0.y, x0, s1);
                u0 = fmaf(w1.x, x1, u0); u1 = fmaf(w1.y, x1, u1);
            }
            __syncwarp();
            float ue0 = fmaxf(s0 + u0, 0.f);
            float ue1 = fmaxf(s1 + u1, 0.f);

            int vf = (l < 5) ? url_f[n * 5 + l] : 0;
            int ov0, ov1;
            precomb(vf, 0, l, ov0, ov1);
            float v0, v1;
            center_embed<5>(vf, 0, ov0, ov1, 0, vpB, v0, v1);

            float p0 = fmaf(__ldg(Wo + l), ue0, fmaf(__ldg(Wo + 32 + l), ue1,
                       fmaf(__ldg(Wo + 64 + l), v0, __ldg(Wo + 96 + l) * v1)));
            float p1 = fmaf(__ldg(Wo + 128 + l), ue0, fmaf(__ldg(Wo + 160 + l), ue1,
                       fmaf(__ldg(Wo + 192 + l), v0, __ldg(Wo + 224 + l) * v1)));
            ull pp = pack2(p0, p1);
#pragma unroll
            for (int o = 16; o; o >>= 1) {
                ull q = __shfl_xor_sync(FULL, pp, o);
                addp(pp, q);
            }
            if (l == 0) {
                p0 = lo32(pp) + __ldg(bo); p1 = hi32(pp) + __ldg(bo + 1);
                float mm = fmaxf(p0, p1);
                float z0 = __expf(p0 - mm), z1 = __expf(p1 - mm);
                float inv = __fdividef(1.f, z0 + z1);
                *(float2*)(out + n * 2) = make_float2(z0 * inv, z1 * inv);
            }
        }
    }
}

extern "C" void kernel_launch(void* const* d_in, const int* in_sizes, int n_in,
                              void* d_out, int out_size) {
    const int*   user_f    = (const int*)d_in[1];
    const int*   url_f     = (const int*)d_in[2];
    const int*   u1u_f     = (const int*)d_in[3];
    const float* u1u_w     = (const float*)d_in[4];
    const int*   u1url_f   = (const int*)d_in[5];
    const float* u1url_w   = (const float*)d_in[6];
    const int*   u2u_f     = (const int*)d_in[7];
    const float* u2u_w     = (const float*)d_in[8];
    const int*   u2url_f   = (const int*)d_in[9];
    const float* u2url_w   = (const float*)d_in[10];
    const int*   url2u_f   = (const int*)d_in[11];
    const float* url2u_w   = (const float*)d_in[12];
    const int*   url2url_f = (const int*)d_in[13];
    const float* url2url_w = (const float*)d_in[14];
    const float* user_table = (const float*)d_in[15];
    const float* url_table  = (const float*)d_in[16];
    const float* W2 = (const float*)d_in[17];
    const float* b2 = (const float*)d_in[18];
    const float* W1 = (const float*)d_in[19];
    const float* b1 = (const float*)d_in[20];
    const float* Wo = (const float*)d_in[21];
    const float* bo = (const float*)d_in[22];
    float* out = (float*)d_out;

    int N = in_sizes[0];

    cudaFuncSetAttribute(gcn_kernel, cudaFuncAttributeMaxDynamicSharedMemorySize, SMEM_BYTES);
    int sm = 148;
    cudaDeviceGetAttribute(&sm, cudaDevAttrMultiProcessorCount, 0);

    prep_kernel<<<16, 256>>>(W1);
    gcn_kernel<<<sm, NTHREADS, SMEM_BYTES>>>(
        user_f, url_f, u1u_f, u1u_w, u1url_f, u1url_w,
        u2u_f, u2u_w, u2url_f, u2url_w,
        url2u_f, url2u_w, url2url_f, url2url_w,
        user_table, url_table, W2, b2, b1, Wo, bo, out, N);
}

// round 13
// speedup vs baseline: 3.2308x; 1.0972x over previous
#include <cuda_runtime.h>
#include <cuda_bf16.h>
#include <cuda_fp16.h>
#include <cstdint>

#define FULL 0xffffffffu
typedef unsigned long long ull;

__constant__ int UOFF[7] = {0, 11577, 11588, 11599, 11610, 11621, 11642};
__constant__ int VOFF[5] = {0, 4733, 4754, 4761, 4772};

constexpr int NWARP = 20;
constexpr int NTHREADS = NWARP * 32;         // 640
constexpr int XS_STRIDE = 9;
constexpr int XS_FLOATS = 128 * XS_STRIDE;   // 1152 per warp
constexpr int AW_FLOATS = 32 * 32 * 4;       // 4096 floats each (bf16 hi / lo frag tables)
constexpr int UP_FLOATS = (3 * 49 + 7) * 64; // 9856 fp32: user pair tables + single
constexpr int VP_FLOATS = (2 * 49 + 7) * 64; // 6720 fp32: url pair tables + single
constexpr int UP_ENT = 3 * 49 + 7;           // 154
constexpr int VP_ENT = 2 * 49 + 7;           // 105
constexpr int PAIR_F32_B = 49 * 256;         // fp32 pair-table stride (bytes)
constexpr int PAIR_F16_B = 49 * 128;         // fp16 pair-table stride (bytes)
constexpr int SMEM_WORDS = 2 * AW_FLOATS + UP_FLOATS + VP_FLOATS
                         + UP_ENT * 32 + VP_ENT * 32 + NWARP * XS_FLOATS;
constexpr int SMEM_BYTES = SMEM_WORDS * 4;   // 224384

__device__ float2 W1T[128 * 32];   // [(i*32+l)] = (W1[l][i], W1[l+32][i])
__device__ unsigned int g_ctr;

__global__ void prep_kernel(const float* __restrict__ W1) {
    int i = blockIdx.x * blockDim.x + threadIdx.x;
    if (i == 0) g_ctr = 0;
    if (i < 128 * 32) {
        int col = i >> 5, l = i & 31;
        W1T[i] = make_float2(W1[l * 128 + col], W1[(l + 32) * 128 + col]);
    }
}

__device__ __forceinline__ float bfly_add(float v) {
#pragma unroll
    for (int o = 16; o; o >>= 1) v += __shfl_xor_sync(FULL, v, o);
    return v;
}
__device__ __forceinline__ void addp(ull& a, ull b) {
    asm("add.rn.f32x2 %0, %0, %1;" : "+l"(a) : "l"(b));
}
__device__ __forceinline__ ull pack2(float x, float y) {
    ull r; asm("mov.b64 %0, {%1, %2};" : "=l"(r) : "f"(x), "f"(y));
    return r;
}
__device__ __forceinline__ float lo32(ull v) { return __uint_as_float((unsigned)v); }
__device__ __forceinline__ float hi32(ull v) { return __uint_as_float((unsigned)(v >> 32)); }

__device__ __forceinline__ unsigned pk_bf(float lo, float hi) {
    __nv_bfloat162 h;
    h.x = __float2bfloat16_rn(lo);
    h.y = __float2bfloat16_rn(hi);
    return *(unsigned*)&h;
}
__device__ __forceinline__ float bfr(float x) {
    return __bfloat162float(__float2bfloat16_rn(x));
}

__device__ __forceinline__ void mma16(float (&c)[4], const uint4& a, unsigned b0, unsigned b1) {
    asm volatile("mma.sync.aligned.m16n8k16.row.col.f32.bf16.bf16.f32 "
                 "{%0,%1,%2,%3},{%4,%5,%6,%7},{%8,%9},{%0,%1,%2,%3};"
                 : "+f"(c[0]), "+f"(c[1]), "+f"(c[2]), "+f"(c[3])
                 : "r"(a.x), "r"(a.y), "r"(a.z), "r"(a.w), "r"(b0), "r"(b1));
}

// precombine adjacent-feature pair offsets with parametric strides:
// o0[l] = f[l]*MA + f[l+1]*MB (l+1 wraps into f1 at lane 31); o1 same for f1.
template <int MA, int MB>
__device__ __forceinline__ void precomb(int f0, int f1, int l, int& o0, int& o1) {
    int f0n = __shfl_down_sync(FULL, f0, 1);
    int f10 = __shfl_sync(FULL, f1, 0);
    f0n = (l == 31) ? f10 : f0n;
    int f1n = __shfl_down_sync(FULL, f1, 1);
    o0 = f0 * MA + f0n * MB;
    o1 = f1 * MA + f1n * MB;
}

// fp32 pair-table embed for one feature-list segment at warp-uniform `base`.
template <int NF>
__device__ __forceinline__ void center_embed(int f0, int f1, int o0, int o1, int base,
                                             const char* tbB, float& c0, float& c1) {
    constexpr int SINGLE_B = ((NF + 1) / 2 - 1) * PAIR_F32_B;
    ull acc = 0;
#pragma unroll
    for (int p = 0; 2 * p + 1 < NF; p++) {
        int pa = base + 2 * p;
        int off = __shfl_sync(FULL, (pa < 32) ? o0 : o1, pa & 31);
        addp(acc, *(const ull*)(tbB + off + p * PAIR_F32_B));
    }
    int ps = base + NF - 1;
    int ia = __shfl_sync(FULL, (ps < 32) ? f0 : f1, ps & 31);
    addp(acc, *(const ull*)(tbB + (ia << 8) + SINGLE_B));
    c0 = lo32(acc); c1 = hi32(acc);
}

// softmax(cosine) + weighted relu-sum over 8 neighbors.
// fold-and-redistribute multi-reduce; lane 4j owns neighbor j's (d,nn) sum.
__device__ __forceinline__ void ga_tail(const float (&e0)[8], const float (&e1)[8],
                                        float (&d)[8], float (&nn)[8],
                                        const float* __restrict__ wptr, float icd,
                                        int l, float& out0, float& out1) {
    ull P[8];
#pragma unroll
    for (int kk = 0; kk < 8; kk++) P[kk] = pack2(d[kk], nn[kk]);
#pragma unroll
    for (int i = 0; i < 8; i++) addp(P[i], __shfl_xor_sync(FULL, P[i], 16));
    bool b4 = (l & 16) != 0;
    ull Q[4];
#pragma unroll
    for (int i = 0; i < 4; i++) Q[i] = b4 ? P[i + 4] : P[i];
#pragma unroll
    for (int i = 0; i < 4; i++) addp(Q[i], __shfl_xor_sync(FULL, Q[i], 8));
    bool b3 = (l & 8) != 0;
    ull R0 = b3 ? Q[2] : Q[0];
    ull R1 = b3 ? Q[3] : Q[1];
    addp(R0, __shfl_xor_sync(FULL, R0, 4));
    addp(R1, __shfl_xor_sync(FULL, R1, 4));
    ull S = (l & 4) ? R1 : R0;
    addp(S, __shfl_xor_sync(FULL, S, 2));
    addp(S, __shfl_xor_sync(FULL, S, 1));
    float rr = fminf(__frsqrt_rn(hi32(S)), 1e6f);      // 1/max(sqrt(nn),1e-6)
    float mycw = __expf(lo32(S) * rr * icd);           // cosine in [-1,1]; safe
    float4 wA = *(const float4*)wptr;
    float4 wB = *(const float4*)(wptr + 4);
    float w[8] = {wA.x, wA.y, wA.z, wA.w, wB.x, wB.y, wB.z, wB.w};
    float cw[8];
#pragma unroll
    for (int k = 0; k < 8; k++) cw[k] = __shfl_sync(FULL, mycw, 4 * k);
    float s = 0.f;
#pragma unroll
    for (int k = 0; k < 8; k++) s += cw[k];
    float inv = __fdividef(1.f, s);
    float o0 = 0.f, o1 = 0.f;
#pragma unroll
    for (int k = 0; k < 8; k++) {
        float sc = cw[k] * inv;
        o0 = fmaf(fmaxf(e0[k] * w[k], 0.f), sc, o0);
        o1 = fmaf(fmaxf(e1[k] * w[k], 0.f), sc, o1);
    }
    out0 = o0; out1 = o1;
}

// graph attention over 8 neighbors via fp16 pair tables (halved L1 traffic);
// all shuffle positions compile-time; accumulation in fp32.
template <int NF>
__device__ __forceinline__ void ga_tbl(const int* __restrict__ flist,
                                       const char* tbHB,
                                       const float* __restrict__ wptr,
                                       float c0, float c1, float icd, int l,
                                       float& out0, float& out1) {
    constexpr int SINGLE_B = ((NF + 1) / 2 - 1) * PAIR_F16_B;
    int f0 = flist[l];
    int f1 = (l < 8 * NF - 32) ? flist[32 + l] : 0;
    int o0, o1;
    precomb<896, 128>(f0, f1, l, o0, o1);
    float e0[8], e1[8], d[8], nn[8];
#pragma unroll
    for (int kk = 0; kk < 8; kk++) {
        float a0 = 0.f, a1 = 0.f;
#pragma unroll
        for (int p = 0; 2 * p + 1 < NF; p++) {
            const int pa = kk * NF + 2 * p;
            int off = __shfl_sync(FULL, (pa < 32) ? o0 : o1, pa & 31);
            __half2 hv = *(const __half2*)(tbHB + off + p * PAIR_F16_B);
            float2 fv = __half22float2(hv);
            a0 += fv.x; a1 += fv.y;
        }
        {
            const int ps = kk * NF + NF - 1;
            int ia = __shfl_sync(FULL, (ps < 32) ? f0 : f1, ps & 31);
            __half2 hv = *(const __half2*)(tbHB + (ia << 7) + SINGLE_B);
            float2 fv = __half22float2(hv);
            a0 += fv.x; a1 += fv.y;
        }
        e0[kk] = a0; e1[kk] = a1;
        d[kk]  = fmaf(a1, c1, a0 * c0);
        nn[kk] = fmaf(a1, a1, a0 * a0);
    }
    ga_tail(e0, e1, d, nn, wptr, icd, l, out0, out1);
}

__device__ __forceinline__ void ga_reg(const float (&e0)[8], const float (&e1)[8],
                                       const float* __restrict__ wptr,
                                       float c0, float c1, float icd, int l,
                                       float& out0, float& out1) {
    float d[8], nn[8];
#pragma unroll
    for (int kk = 0; kk < 8; kk++) {
        d[kk]  = fmaf(e1[kk], c1, e0[kk] * c0);
        nn[kk] = fmaf(e1[kk], e1[kk], e0[kk] * e0[kk]);
    }
    ga_tail(e0, e1, d, nn, wptr, icd, l, out0, out1);
}

// relu(W2(64x128) @ X[128x8] + b2) via 3xBF16-k16 mma (hi/lo split);
// Y written back into xsw (stride XS_STRIDE). b2 loaded per call (L1-cached).
__device__ __forceinline__ void lin_mma(const uint4* __restrict__ AWhi,
                                        const uint4* __restrict__ AWlo,
                                        float* __restrict__ xsw,
                                        const float* __restrict__ b2,
                                        int lane) {
    int g = lane >> 2, tg = lane & 3;
    float acc[4][4];
#pragma unroll
    for (int m = 0; m < 4; m++) {
        float bAv = __ldg(b2 + 16 * m + g);
        float bBv = __ldg(b2 + 16 * m + 8 + g);
        acc[m][0] = bAv; acc[m][1] = bAv;
        acc[m][2] = bBv; acc[m][3] = bBv;
    }
#pragma unroll 2
    for (int kt = 0; kt < 8; kt++) {
        int r0 = 16 * kt + 2 * tg;
        float xa0 = xsw[r0 * XS_STRIDE + g];
        float xa1 = xsw[(r0 + 1) * XS_STRIDE + g];
        float xb0 = xsw[(r0 + 8) * XS_STRIDE + g];
        float xb1 = xsw[(r0 + 9) * XS_STRIDE + g];
        float ha0 = bfr(xa0), ha1 = bfr(xa1), hb0 = bfr(xb0), hb1 = bfr(xb1);
        unsigned Bh0 = pk_bf(ha0, ha1), Bh1 = pk_bf(hb0, hb1);
        unsigned Bl0 = pk_bf(xa0 - ha0, xa1 - ha1), Bl1 = pk_bf(xb0 - hb0, xb1 - hb1);
        const uint4* ph = AWhi + kt * 4 * 32 + lane;
        const uint4* pl = AWlo + kt * 4 * 32 + lane;
#pragma unroll
        for (int m = 0; m < 4; m++) {
            uint4 ah = ph[m * 32];
            uint4 al = pl[m * 32];
            mma16(acc[m], ah, Bh0, Bh1);
            mma16(acc[m], ah, Bl0, Bl1);
            mma16(acc[m], al, Bh0, Bh1);
        }
    }
    __syncwarp();
#pragma unroll
    for (int m = 0; m < 4; m++) {
        xsw[(16 * m + g) * XS_STRIDE + 2 * tg]         = fmaxf(acc[m][0], 0.f);
        xsw[(16 * m + g) * XS_STRIDE + 2 * tg + 1]     = fmaxf(acc[m][1], 0.f);
        xsw[(16 * m + g + 8) * XS_STRIDE + 2 * tg]     = fmaxf(acc[m][2], 0.f);
        xsw[(16 * m + g + 8) * XS_STRIDE + 2 * tg + 1] = fmaxf(acc[m][3], 0.f);
    }
    __syncwarp();
}

__global__ void __launch_bounds__(NTHREADS, 1)
gcn_kernel(const int* __restrict__ user_f, const int* __restrict__ url_f,
           const int* __restrict__ u1u_f, const float* __restrict__ u1u_w,
           const int* __restrict__ u1url_f, const float* __restrict__ u1url_w,
           const int* __restrict__ u2u_f, const float* __restrict__ u2u_w,
           const int* __restrict__ u2url_f, const float* __restrict__ u2url_w,
           const int* __restrict__ url2u_f, const float* __restrict__ url2u_w,
           const int* __restrict__ url2url_f, const float* __restrict__ url2url_w,
           const float* __restrict__ user_table, const float* __restrict__ url_table,
           const float* __restrict__ W2, const float* __restrict__ b2,
           const float* __restrict__ b1,
           const float* __restrict__ Wo, const float* __restrict__ bo,
           float* __restrict__ out, int N) {
    extern __shared__ float smf[];
    float* AWhiF = smf;
    float* AWloF = smf + AW_FLOATS;
    float* upF   = smf + 2 * AW_FLOATS;
    float* vpF   = upF + UP_FLOATS;
    unsigned* upH = (unsigned*)(vpF + VP_FLOATS);     // fp16x2 user tables
    unsigned* vpH = upH + UP_ENT * 32;                // fp16x2 url tables
    float* xsAll = (float*)(vpH + VP_ENT * 32);

    int tid = threadIdx.x;

    // ---- W2 A-fragments for m16n8k16 bf16, hi/lo split (frag fid = kt*4+m) ----
    for (int i = tid; i < 1024; i += NTHREADS) {
        int fid = i >> 5, ln = i & 31;
        int kt = fid >> 2, m = fid & 3;
        int gg = ln >> 2, tg = ln & 3;
        int r0 = 16 * m + gg, r1 = r0 + 8;
        int c0 = 16 * kt + 2 * tg, c1 = c0 + 1, c2 = c0 + 8, c3 = c0 + 9;
        float v00 = W2[r0 * 128 + c0], v01 = W2[r0 * 128 + c1];
        float v10 = W2[r1 * 128 + c0], v11 = W2[r1 * 128 + c1];
        float v02 = W2[r0 * 128 + c2], v03 = W2[r0 * 128 + c3];
        float v12 = W2[r1 * 128 + c2], v13 = W2[r1 * 128 + c3];
        float h00 = bfr(v00), h01 = bfr(v01), h10 = bfr(v10), h11 = bfr(v11);
        float h02 = bfr(v02), h03 = bfr(v03), h12 = bfr(v12), h13 = bfr(v13);
        uint4 hi, lo;
        hi.x = pk_bf(h00, h01); hi.y = pk_bf(h10, h11);
        hi.z = pk_bf(h02, h03); hi.w = pk_bf(h12, h13);
        lo.x = pk_bf(v00 - h00, v01 - h01); lo.y = pk_bf(v10 - h10, v11 - h11);
        lo.z = pk_bf(v02 - h02, v03 - h03); lo.w = pk_bf(v12 - h12, v13 - h13);
        ((uint4*)AWhiF)[fid * 32 + ln] = hi;
        ((uint4*)AWloF)[fid * 32 + ln] = lo;
    }
    // ---- fp32 user tables: P0=(c0,c1) P1=(c2,c3) P2=(c4,c5) then 7-entry single (c6) ----
    for (int i = tid; i < UP_FLOATS; i += NTHREADS) {
        int e = i >> 6, q = i & 63, ln = q >> 1, c = q & 1;
        int dim = ln + 32 * c;
        float v;
        if (e < 147) {
            int p = e / 49, rem = e % 49, ia = rem / 7, ib = rem % 7;
            v = user_table[(UOFF[2 * p] + ia) * 64 + dim]
              + user_table[(UOFF[2 * p + 1] + ib) * 64 + dim];
        } else {
            v = user_table[(UOFF[6] + (e - 147)) * 64 + dim];
        }
        upF[i] = v;
    }
    // ---- fp32 url tables: P0=(c0,c1) P1=(c2,c3) then 7-entry single (c4) ----
    for (int i = tid; i < VP_FLOATS; i += NTHREADS) {
        int e = i >> 6, q = i & 63, ln = q >> 1, c = q & 1;
        int dim = ln + 32 * c;
        float v;
        if (e < 98) {
            int p = e / 49, rem = e % 49, ia = rem / 7, ib = rem % 7;
            v = url_table[(VOFF[2 * p] + ia) * 64 + dim]
              + url_table[(VOFF[2 * p + 1] + ib) * 64 + dim];
        } else {
            v = url_table[(VOFF[4] + (e - 98)) * 64 + dim];
        }
        vpF[i] = v;
    }
    __syncthreads();
    // ---- fp16 copies of the pair tables (derived from fp32 smem) ----
    for (int i = tid; i < UP_ENT * 32; i += NTHREADS) {
        int e = i >> 5, ln = i & 31;
        __half2 h = __floats2half2_rn(upF[e * 64 + 2 * ln], upF[e * 64 + 2 * ln + 1]);
        upH[i] = *(unsigned*)&h;
    }
    for (int i = tid; i < VP_ENT * 32; i += NTHREADS) {
        int e = i >> 5, ln = i & 31;
        __half2 h = __floats2half2_rn(vpF[e * 64 + 2 * ln], vpF[e * 64 + 2 * ln + 1]);
        vpH[i] = *(unsigned*)&h;
    }
    __syncthreads();

    int l   = tid & 31;
    int wrp = tid >> 5;
    float* xsw = xsAll + wrp * XS_FLOATS;
    const char* upB  = (const char*)upF + (l << 3);
    const char* vpB  = (const char*)vpF + (l << 3);
    const char* upHB = (const char*)upH + (l << 2);
    const char* vpHB = (const char*)vpH + (l << 2);
    const uint4* AWhi = (const uint4*)AWhiF;
    const uint4* AWlo = (const uint4*)AWloF;

    for (;;) {
        int n;
        if (l == 0) n = (int)atomicAdd(&g_ctr, 1u);
        n = __shfl_sync(FULL, n, 0);
        if (n >= N) break;

        // ---- stage B: user branch (hop2 -> hop1) -> eB regs ----
        float eB0[8], eB1[8];
        {
            const int* pc = u1u_f + n * 56;
            int fc0 = pc[l];
            int fc1 = (l < 24) ? pc[32 + l] : 0;
            int oc0, oc1;
            precomb<1792, 256>(fc0, fc1, l, oc0, oc1);
#pragma unroll 1
            for (int k = 0; k < 8; k++) {
                float c0, c1;
                center_embed<7>(fc0, fc1, oc0, oc1, k * 7, upB, c0, c1);
                float icd = fminf(__frsqrt_rn(bfly_add(fmaf(c1, c1, c0 * c0))), 1e6f);
                float a0, a1, q0, q1;
                ga_tbl<7>(u2u_f + (n * 8 + k) * 56, upHB, u2u_w + (n * 8 + k) * 8,
                          c0, c1, icd, l, a0, a1);
                ga_tbl<5>(u2url_f + (n * 8 + k) * 40, vpHB, u2url_w + (n * 8 + k) * 8,
                          c0, c1, icd, l, q0, q1);
                xsw[l * XS_STRIDE + k]        = c0;
                xsw[(32 + l) * XS_STRIDE + k] = c1;
                xsw[(64 + l) * XS_STRIDE + k] = (a0 + q0) * 0.5f;
                xsw[(96 + l) * XS_STRIDE + k] = (a1 + q1) * 0.5f;
            }
            __syncwarp();
            lin_mma(AWhi, AWlo, xsw, b2, l);
#pragma unroll
            for (int k = 0; k < 8; k++) {
                eB0[k] = xsw[l * XS_STRIDE + k];
                eB1[k] = xsw[(32 + l) * XS_STRIDE + k];
            }
            __syncwarp();
        }

        // ---- stage A: url branch (hop2 -> hop1) -> Y stays in xsw ----
        {
            const int* pc = u1url_f + n * 40;
            int fc0 = pc[l];
            int fc1 = (l < 8) ? pc[32 + l] : 0;
            int oc0, oc1;
            precomb<1792, 256>(fc0, fc1, l, oc0, oc1);
#pragma unroll 1
            for (int k = 0; k < 8; k++) {
                float c0, c1;
                center_embed<5>(fc0, fc1, oc0, oc1, k * 5, vpB, c0, c1);
                float icd = fminf(__frsqrt_rn(bfly_add(fmaf(c1, c1, c0 * c0))), 1e6f);
                float a0, a1, q0, q1;
                ga_tbl<7>(url2u_f + (n * 8 + k) * 56, upHB, url2u_w + (n * 8 + k) * 8,
                          c0, c1, icd, l, a0, a1);
                ga_tbl<5>(url2url_f + (n * 8 + k) * 40, vpHB, url2url_w + (n * 8 + k) * 8,
                          c0, c1, icd, l, q0, q1);
                xsw[l * XS_STRIDE + k]        = c0;
                xsw[(32 + l) * XS_STRIDE + k] = c1;
                xsw[(64 + l) * XS_STRIDE + k] = (a0 + q0) * 0.5f;
                xsw[(96 + l) * XS_STRIDE + k] = (a1 + q1) * 0.5f;
            }
            __syncwarp();
            lin_mma(AWhi, AWlo, xsw, b2, l);
        }

        // ---- stage C: hop1 -> center (fp32 tables: feeds output directly) ----
        {
            int uf = (l < 7) ? user_f[n * 7 + l] : 0;
            int ou0, ou1;
            precomb<1792, 256>(uf, 0, l, ou0, ou1);
            float c0, c1;
            center_embed<7>(uf, 0, ou0, ou1, 0, upB, c0, c1);
            float icd = fminf(__frsqrt_rn(bfly_add(fmaf(c1, c1, c0 * c0))), 1e6f);

            // eA from xsw (stage A's Y) — read before clobbering column 0
            float eA0[8], eA1[8];
#pragma unroll
            for (int k = 0; k < 8; k++) {
                eA0[k] = xsw[l * XS_STRIDE + k];
                eA1[k] = xsw[(32 + l) * XS_STRIDE + k];
            }

            float a0, a1, q0, q1;
            ga_reg(eA0, eA1, u1url_w + n * 8, c0, c1, icd, l, a0, a1);
            ga_reg(eB0, eB1, u1u_w + n * 8, c0, c1, icd, l, q0, q1);

            xsw[l * XS_STRIDE]        = c0;
            xsw[(32 + l) * XS_STRIDE] = c1;
            xsw[(64 + l) * XS_STRIDE] = (a0 + q0) * 0.5f;
            xsw[(96 + l) * XS_STRIDE] = (a1 + q1) * 0.5f;
            __syncwarp();

            float s0 = __ldg(b1 + l), s1 = __ldg(b1 + 32 + l), u0 = 0.f, u1 = 0.f;
#pragma unroll 8
            for (int i = 0; i < 128; i += 2) {
                float x0 = xsw[i * XS_STRIDE];
                float x1 = xsw[(i + 1) * XS_STRIDE];
                float2 w0 = __ldg(W1T + i * 32 + l);
                float2 w1 = __ldg(W1T + (i + 1) * 32 + l);
                s0 = fmaf(w0.x, x0, s0); s1 = fmaf(w0.y, x0, s1);
                u0 = fmaf(w1.x, x1, u0); u1 = fmaf(w1.y, x1, u1);
            }
            __syncwarp();
            float ue0 = fmaxf(s0 + u0, 0.f);
            float ue1 = fmaxf(s1 + u1, 0.f);

            int vf = (l < 5) ? url_f[n * 5 + l] : 0;
            int ov0, ov1;
            precomb<1792, 256>(vf, 0, l, ov0, ov1);
            float v0, v1;
            center_embed<5>(vf, 0, ov0, ov1, 0, vpB, v0, v1);

            float p0 = fmaf(__ldg(Wo + l), ue0, fmaf(__ldg(Wo + 32 + l), ue1,
                       fmaf(__ldg(Wo + 64 + l), v0, __ldg(Wo + 96 + l) * v1)));
            float p1 = fmaf(__ldg(Wo + 128 + l), ue0, fmaf(__ldg(Wo + 160 + l), ue1,
                       fmaf(__ldg(Wo + 192 + l), v0, __ldg(Wo + 224 + l) * v1)));
            ull pp = pack2(p0, p1);
#pragma unroll
            for (int o = 16; o; o >>= 1) {
                ull q = __shfl_xor_sync(FULL, pp, o);
                addp(pp, q);
            }
            if (l == 0) {
                p0 = lo32(pp) + __ldg(bo); p1 = hi32(pp) + __ldg(bo + 1);
                float mm = fmaxf(p0, p1);
                float z0 = __expf(p0 - mm), z1 = __expf(p1 - mm);
                float inv = __fdividef(1.f, z0 + z1);
                *(float2*)(out + n * 2) = make_float2(z0 * inv, z1 * inv);
            }
        }
    }
}

extern "C" void kernel_launch(void* const* d_in, const int* in_sizes, int n_in,
                              void* d_out, int out_size) {
    const int*   user_f    = (const int*)d_in[1];
    const int*   url_f     = (const int*)d_in[2];
    const int*   u1u_f     = (const int*)d_in[3];
    const float* u1u_w     = (const float*)d_in[4];
    const int*   u1url_f   = (const int*)d_in[5];
    const float* u1url_w   = (const float*)d_in[6];
    const int*   u2u_f     = (const int*)d_in[7];
    const float* u2u_w     = (const float*)d_in[8];
    const int*   u2url_f   = (const int*)d_in[9];
    const float* u2url_w   = (const float*)d_in[10];
    const int*   url2u_f   = (const int*)d_in[11];
    const float* url2u_w   = (const float*)d_in[12];
    const int*   url2url_f = (const int*)d_in[13];
    const float* url2url_w = (const float*)d_in[14];
    const float* user_table = (const float*)d_in[15];
    const float* url_table  = (const float*)d_in[16];
    const float* W2 = (const float*)d_in[17];
    const float* b2 = (const float*)d_in[18];
    const float* W1 = (const float*)d_in[19];
    const float* b1 = (const float*)d_in[20];
    const float* Wo = (const float*)d_in[21];
    const float* bo = (const float*)d_in[22];
    float* out = (float*)d_out;

    int N = in_sizes[0];

    cudaFuncSetAttribute(gcn_kernel, cudaFuncAttributeMaxDynamicSharedMemorySize, SMEM_BYTES);
    int sm = 148;
    cudaDeviceGetAttribute(&sm, cudaDevAttrMultiProcessorCount, 0);

    prep_kernel<<<16, 256>>>(W1);
    gcn_kernel<<<sm, NTHREADS, SMEM_BYTES>>>(
        user_f, url_f, u1u_f, u1u_w, u1url_f, u1url_w,
        u2u_f, u2u_w, u2url_f, u2url_w,
        url2u_f, url2u_w, url2url_f, url2url_w,
        user_table, url_table, W2, b2, b1, Wo, bo, out, N);
}

// round 14
// speedup vs baseline: 3.3081x; 1.0239x over previous
#include <cuda_runtime.h>
#include <cuda_bf16.h>
#include <cuda_fp16.h>
#include <cstdint>

#define FULL 0xffffffffu
typedef unsigned long long ull;

__constant__ int UOFF[7] = {0, 11577, 11588, 11599, 11610, 11621, 11642};
__constant__ int VOFF[5] = {0, 4733, 4754, 4761, 4772};

constexpr int NWARP = 20;
constexpr int NTHREADS = NWARP * 32;         // 640
constexpr int XS_STRIDE = 9;
constexpr int XS_FLOATS = 128 * XS_STRIDE;   // 1152 per warp
constexpr int AW_FLOATS = 32 * 32 * 4;       // 4096 floats each (bf16 hi / lo frag tables)
constexpr int UP_FLOATS = (3 * 49 + 7) * 64; // 9856 fp32: user pair tables + single
constexpr int VP_FLOATS = (2 * 49 + 7) * 64; // 6720 fp32: url pair tables + single
constexpr int UP_ENT = 3 * 49 + 7;           // 154
constexpr int VP_ENT = 2 * 49 + 7;           // 105
constexpr int PAIR_F32_B = 49 * 256;         // fp32 pair-table stride (bytes)
constexpr int PAIR_F16_B = 49 * 128;         // fp16 pair-table stride (bytes)
constexpr int SMEM_WORDS = 2 * AW_FLOATS + UP_FLOATS + VP_FLOATS
                         + UP_ENT * 32 + VP_ENT * 32 + NWARP * XS_FLOATS;
constexpr int SMEM_BYTES = SMEM_WORDS * 4;   // 224384

__device__ float2 W1T[128 * 32];   // [(i*32+l)] = (W1[l][i], W1[l+32][i])
__device__ unsigned int g_ctr;

__global__ void prep_kernel(const float* __restrict__ W1) {
    int i = blockIdx.x * blockDim.x + threadIdx.x;
    if (i == 0) g_ctr = 0;
    if (i < 128 * 32) {
        int col = i >> 5, l = i & 31;
        W1T[i] = make_float2(W1[l * 128 + col], W1[(l + 32) * 128 + col]);
    }
}

__device__ __forceinline__ float bfly_add(float v) {
#pragma unroll
    for (int o = 16; o; o >>= 1) v += __shfl_xor_sync(FULL, v, o);
    return v;
}
__device__ __forceinline__ void addp(ull& a, ull b) {
    asm("add.rn.f32x2 %0, %0, %1;" : "+l"(a) : "l"(b));
}
__device__ __forceinline__ ull pack2(float x, float y) {
    ull r; asm("mov.b64 %0, {%1, %2};" : "=l"(r) : "f"(x), "f"(y));
    return r;
}
__device__ __forceinline__ float lo32(ull v) { return __uint_as_float((unsigned)v); }
__device__ __forceinline__ float hi32(ull v) { return __uint_as_float((unsigned)(v >> 32)); }

__device__ __forceinline__ unsigned pk_bf(float lo, float hi) {
    __nv_bfloat162 h;
    h.x = __float2bfloat16_rn(lo);
    h.y = __float2bfloat16_rn(hi);
    return *(unsigned*)&h;
}
__device__ __forceinline__ float bfr(float x) {
    return __bfloat162float(__float2bfloat16_rn(x));
}

__device__ __forceinline__ void mma16(float (&c)[4], const uint4& a, unsigned b0, unsigned b1) {
    asm volatile("mma.sync.aligned.m16n8k16.row.col.f32.bf16.bf16.f32 "
                 "{%0,%1,%2,%3},{%4,%5,%6,%7},{%8,%9},{%0,%1,%2,%3};"
                 : "+f"(c[0]), "+f"(c[1]), "+f"(c[2]), "+f"(c[3])
                 : "r"(a.x), "r"(a.y), "r"(a.z), "r"(a.w), "r"(b0), "r"(b1));
}

// precombine adjacent-feature pair offsets with parametric strides:
// o0[l] = f[l]*MA + f[l+1]*MB (l+1 wraps into f1 at lane 31); o1 same for f1.
template <int MA, int MB>
__device__ __forceinline__ void precomb(int f0, int f1, int l, int& o0, int& o1) {
    int f0n = __shfl_down_sync(FULL, f0, 1);
    int f10 = __shfl_sync(FULL, f1, 0);
    f0n = (l == 31) ? f10 : f0n;
    int f1n = __shfl_down_sync(FULL, f1, 1);
    o0 = f0 * MA + f0n * MB;
    o1 = f1 * MA + f1n * MB;
}

// fp32 pair-table embed for one feature-list segment at warp-uniform `base`.
template <int NF>
__device__ __forceinline__ void center_embed(int f0, int f1, int o0, int o1, int base,
                                             const char* tbB, float& c0, float& c1) {
    constexpr int SINGLE_B = ((NF + 1) / 2 - 1) * PAIR_F32_B;
    ull acc = 0;
#pragma unroll
    for (int p = 0; 2 * p + 1 < NF; p++) {
        int pa = base + 2 * p;
        int off = __shfl_sync(FULL, (pa < 32) ? o0 : o1, pa & 31);
        addp(acc, *(const ull*)(tbB + off + p * PAIR_F32_B));
    }
    int ps = base + NF - 1;
    int ia = __shfl_sync(FULL, (ps < 32) ? f0 : f1, ps & 31);
    addp(acc, *(const ull*)(tbB + (ia << 8) + SINGLE_B));
    c0 = lo32(acc); c1 = hi32(acc);
}

// softmax(cosine) + weighted relu-sum over 8 neighbors.
// fold-and-redistribute multi-reduce; lane 4j owns neighbor j's (d,nn) sum.
__device__ __forceinline__ void ga_tail(const float (&e0)[8], const float (&e1)[8],
                                        float (&d)[8], float (&nn)[8],
                                        const float* __restrict__ wptr, float icd,
                                        int l, float& out0, float& out1) {
    ull P[8];
#pragma unroll
    for (int kk = 0; kk < 8; kk++) P[kk] = pack2(d[kk], nn[kk]);
#pragma unroll
    for (int i = 0; i < 8; i++) addp(P[i], __shfl_xor_sync(FULL, P[i], 16));
    bool b4 = (l & 16) != 0;
    ull Q[4];
#pragma unroll
    for (int i = 0; i < 4; i++) Q[i] = b4 ? P[i + 4] : P[i];
#pragma unroll
    for (int i = 0; i < 4; i++) addp(Q[i], __shfl_xor_sync(FULL, Q[i], 8));
    bool b3 = (l & 8) != 0;
    ull R0 = b3 ? Q[2] : Q[0];
    ull R1 = b3 ? Q[3] : Q[1];
    addp(R0, __shfl_xor_sync(FULL, R0, 4));
    addp(R1, __shfl_xor_sync(FULL, R1, 4));
    ull S = (l & 4) ? R1 : R0;
    addp(S, __shfl_xor_sync(FULL, S, 2));
    addp(S, __shfl_xor_sync(FULL, S, 1));
    float rr = fminf(__frsqrt_rn(hi32(S)), 1e6f);      // 1/max(sqrt(nn),1e-6)
    float mycw = __expf(lo32(S) * rr * icd);           // cosine in [-1,1]; safe
    float4 wA = *(const float4*)wptr;
    float4 wB = *(const float4*)(wptr + 4);
    float w[8] = {wA.x, wA.y, wA.z, wA.w, wB.x, wB.y, wB.z, wB.w};
    float cw[8];
#pragma unroll
    for (int k = 0; k < 8; k++) cw[k] = __shfl_sync(FULL, mycw, 4 * k);
    float s = 0.f;
#pragma unroll
    for (int k = 0; k < 8; k++) s += cw[k];
    float inv = __fdividef(1.f, s);
    float o0 = 0.f, o1 = 0.f;
#pragma unroll
    for (int k = 0; k < 8; k++) {
        float sc = cw[k] * inv;
        o0 = fmaf(fmaxf(e0[k] * w[k], 0.f), sc, o0);
        o1 = fmaf(fmaxf(e1[k] * w[k], 0.f), sc, o1);
    }
    out0 = o0; out1 = o1;
}

// graph attention over 8 neighbors via fp16 pair tables with packed HADD2
// accumulation (1 alu op per lookup); single convert per neighbor.
template <int NF>
__device__ __forceinline__ void ga_tbl(const int* __restrict__ flist,
                                       const char* tbHB,
                                       const float* __restrict__ wptr,
                                       float c0, float c1, float icd, int l,
                                       float& out0, float& out1) {
    constexpr int SINGLE_B = ((NF + 1) / 2 - 1) * PAIR_F16_B;
    int f0 = flist[l];
    int f1 = (l < 8 * NF - 32) ? flist[32 + l] : 0;
    int o0, o1;
    precomb<896, 128>(f0, f1, l, o0, o1);
    float e0[8], e1[8], d[8], nn[8];
#pragma unroll
    for (int kk = 0; kk < 8; kk++) {
        __half2 acc;
        {
            const int pa = kk * NF;
            int off = __shfl_sync(FULL, (pa < 32) ? o0 : o1, pa & 31);
            acc = *(const __half2*)(tbHB + off);
        }
#pragma unroll
        for (int p = 1; 2 * p + 1 < NF; p++) {
            const int pa = kk * NF + 2 * p;
            int off = __shfl_sync(FULL, (pa < 32) ? o0 : o1, pa & 31);
            acc = __hadd2(acc, *(const __half2*)(tbHB + off + p * PAIR_F16_B));
        }
        {
            const int ps = kk * NF + NF - 1;
            int ia = __shfl_sync(FULL, (ps < 32) ? f0 : f1, ps & 31);
            acc = __hadd2(acc, *(const __half2*)(tbHB + (ia << 7) + SINGLE_B));
        }
        float2 fv = __half22float2(acc);
        float a0 = fv.x, a1 = fv.y;
        e0[kk] = a0; e1[kk] = a1;
        d[kk]  = fmaf(a1, c1, a0 * c0);
        nn[kk] = fmaf(a1, a1, a0 * a0);
    }
    ga_tail(e0, e1, d, nn, wptr, icd, l, out0, out1);
}

__device__ __forceinline__ void ga_reg(const float (&e0)[8], const float (&e1)[8],
                                       const float* __restrict__ wptr,
                                       float c0, float c1, float icd, int l,
                                       float& out0, float& out1) {
    float d[8], nn[8];
#pragma unroll
    for (int kk = 0; kk < 8; kk++) {
        d[kk]  = fmaf(e1[kk], c1, e0[kk] * c0);
        nn[kk] = fmaf(e1[kk], e1[kk], e0[kk] * e0[kk]);
    }
    ga_tail(e0, e1, d, nn, wptr, icd, l, out0, out1);
}

// relu(W2(64x128) @ X[128x8] + b2) via 3xBF16-k16 mma (hi/lo split);
// Y written back into xsw (stride XS_STRIDE). b2 loaded per call (L1-cached).
__device__ __forceinline__ void lin_mma(const uint4* __restrict__ AWhi,
                                        const uint4* __restrict__ AWlo,
                                        float* __restrict__ xsw,
                                        const float* __restrict__ b2,
                                        int lane) {
    int g = lane >> 2, tg = lane & 3;
    float acc[4][4];
#pragma unroll
    for (int m = 0; m < 4; m++) {
        float bAv = __ldg(b2 + 16 * m + g);
        float bBv = __ldg(b2 + 16 * m + 8 + g);
        acc[m][0] = bAv; acc[m][1] = bAv;
        acc[m][2] = bBv; acc[m][3] = bBv;
    }
#pragma unroll 2
    for (int kt = 0; kt < 8; kt++) {
        int r0 = 16 * kt + 2 * tg;
        float xa0 = xsw[r0 * XS_STRIDE + g];
        float xa1 = xsw[(r0 + 1) * XS_STRIDE + g];
        float xb0 = xsw[(r0 + 8) * XS_STRIDE + g];
        float xb1 = xsw[(r0 + 9) * XS_STRIDE + g];
        float ha0 = bfr(xa0), ha1 = bfr(xa1), hb0 = bfr(xb0), hb1 = bfr(xb1);
        unsigned Bh0 = pk_bf(ha0, ha1), Bh1 = pk_bf(hb0, hb1);
        unsigned Bl0 = pk_bf(xa0 - ha0, xa1 - ha1), Bl1 = pk_bf(xb0 - hb0, xb1 - hb1);
        const uint4* ph = AWhi + kt * 4 * 32 + lane;
        const uint4* pl = AWlo + kt * 4 * 32 + lane;
#pragma unroll
        for (int m = 0; m < 4; m++) {
            uint4 ah = ph[m * 32];
            uint4 al = pl[m * 32];
            mma16(acc[m], ah, Bh0, Bh1);
            mma16(acc[m], ah, Bl0, Bl1);
            mma16(acc[m], al, Bh0, Bh1);
        }
    }
    __syncwarp();
#pragma unroll
    for (int m = 0; m < 4; m++) {
        xsw[(16 * m + g) * XS_STRIDE + 2 * tg]         = fmaxf(acc[m][0], 0.f);
        xsw[(16 * m + g) * XS_STRIDE + 2 * tg + 1]     = fmaxf(acc[m][1], 0.f);
        xsw[(16 * m + g + 8) * XS_STRIDE + 2 * tg]     = fmaxf(acc[m][2], 0.f);
        xsw[(16 * m + g + 8) * XS_STRIDE + 2 * tg + 1] = fmaxf(acc[m][3], 0.f);
    }
    __syncwarp();
}

__global__ void __launch_bounds__(NTHREADS, 1)
gcn_kernel(const int* __restrict__ user_f, const int* __restrict__ url_f,
           const int* __restrict__ u1u_f, const float* __restrict__ u1u_w,
           const int* __restrict__ u1url_f, const float* __restrict__ u1url_w,
           const int* __restrict__ u2u_f, const float* __restrict__ u2u_w,
           const int* __restrict__ u2url_f, const float* __restrict__ u2url_w,
           const int* __restrict__ url2u_f, const float* __restrict__ url2u_w,
           const int* __restrict__ url2url_f, const float* __restrict__ url2url_w,
           const float* __restrict__ user_table, const float* __restrict__ url_table,
           const float* __restrict__ W2, const float* __restrict__ b2,
           const float* __restrict__ b1,
           const float* __restrict__ Wo, const float* __restrict__ bo,
           float* __restrict__ out, int N) {
    extern __shared__ float smf[];
    float* AWhiF = smf;
    float* AWloF = smf + AW_FLOATS;
    float* upF   = smf + 2 * AW_FLOATS;
    float* vpF   = upF + UP_FLOATS;
    unsigned* upH = (unsigned*)(vpF + VP_FLOATS);     // fp16x2 user tables
    unsigned* vpH = upH + UP_ENT * 32;                // fp16x2 url tables
    float* xsAll = (float*)(vpH + VP_ENT * 32);

    int tid = threadIdx.x;

    // ---- W2 A-fragments for m16n8k16 bf16, hi/lo split (frag fid = kt*4+m) ----
    for (int i = tid; i < 1024; i += NTHREADS) {
        int fid = i >> 5, ln = i & 31;
        int kt = fid >> 2, m = fid & 3;
        int gg = ln >> 2, tg = ln & 3;
        int r0 = 16 * m + gg, r1 = r0 + 8;
        int c0 = 16 * kt + 2 * tg, c1 = c0 + 1, c2 = c0 + 8, c3 = c0 + 9;
        float v00 = W2[r0 * 128 + c0], v01 = W2[r0 * 128 + c1];
        float v10 = W2[r1 * 128 + c0], v11 = W2[r1 * 128 + c1];
        float v02 = W2[r0 * 128 + c2], v03 = W2[r0 * 128 + c3];
        float v12 = W2[r1 * 128 + c2], v13 = W2[r1 * 128 + c3];
        float h00 = bfr(v00), h01 = bfr(v01), h10 = bfr(v10), h11 = bfr(v11);
        float h02 = bfr(v02), h03 = bfr(v03), h12 = bfr(v12), h13 = bfr(v13);
        uint4 hi, lo;
        hi.x = pk_bf(h00, h01); hi.y = pk_bf(h10, h11);
        hi.z = pk_bf(h02, h03); hi.w = pk_bf(h12, h13);
        lo.x = pk_bf(v00 - h00, v01 - h01); lo.y = pk_bf(v10 - h10, v11 - h11);
        lo.z = pk_bf(v02 - h02, v03 - h03); lo.w = pk_bf(v12 - h12, v13 - h13);
        ((uint4*)AWhiF)[fid * 32 + ln] = hi;
        ((uint4*)AWloF)[fid * 32 + ln] = lo;
    }
    // ---- fp32 user tables: P0=(c0,c1) P1=(c2,c3) P2=(c4,c5) then 7-entry single (c6) ----
    for (int i = tid; i < UP_FLOATS; i += NTHREADS) {
        int e = i >> 6, q = i & 63, ln = q >> 1, c = q & 1;
        int dim = ln + 32 * c;
        float v;
        if (e < 147) {
            int p = e / 49, rem = e % 49, ia = rem / 7, ib = rem % 7;
            v = user_table[(UOFF[2 * p] + ia) * 64 + dim]
              + user_table[(UOFF[2 * p + 1] + ib) * 64 + dim];
        } else {
            v = user_table[(UOFF[6] + (e - 147)) * 64 + dim];
        }
        upF[i] = v;
    }
    // ---- fp32 url tables: P0=(c0,c1) P1=(c2,c3) then 7-entry single (c4) ----
    for (int i = tid; i < VP_FLOATS; i += NTHREADS) {
        int e = i >> 6, q = i & 63, ln = q >> 1, c = q & 1;
        int dim = ln + 32 * c;
        float v;
        if (e < 98) {
            int p = e / 49, rem = e % 49, ia = rem / 7, ib = rem % 7;
            v = url_table[(VOFF[2 * p] + ia) * 64 + dim]
              + url_table[(VOFF[2 * p + 1] + ib) * 64 + dim];
        } else {
            v = url_table[(VOFF[4] + (e - 98)) * 64 + dim];
        }
        vpF[i] = v;
    }
    __syncthreads();
    // ---- fp16 copies of the pair tables (derived from fp32 smem) ----
    for (int i = tid; i < UP_ENT * 32; i += NTHREADS) {
        int e = i >> 5, ln = i & 31;
        __half2 h = __floats2half2_rn(upF[e * 64 + 2 * ln], upF[e * 64 + 2 * ln + 1]);
        upH[i] = *(unsigned*)&h;
    }
    for (int i = tid; i < VP_ENT * 32; i += NTHREADS) {
        int e = i >> 5, ln = i & 31;
        __half2 h = __floats2half2_rn(vpF[e * 64 + 2 * ln], vpF[e * 64 + 2 * ln + 1]);
        vpH[i] = *(unsigned*)&h;
    }
    __syncthreads();

    int l   = tid & 31;
    int wrp = tid >> 5;
    float* xsw = xsAll + wrp * XS_FLOATS;
    const char* upB  = (const char*)upF + (l << 3);
    const char* vpB  = (const char*)vpF + (l << 3);
    const char* upHB = (const char*)upH + (l << 2);
    const char* vpHB = (const char*)vpH + (l << 2);
    const uint4* AWhi = (const uint4*)AWhiF;
    const uint4* AWlo = (const uint4*)AWloF;

    for (;;) {
        int n;
        if (l == 0) n = (int)atomicAdd(&g_ctr, 1u);
        n = __shfl_sync(FULL, n, 0);
        if (n >= N) break;

        // ---- stage B: user branch (hop2 -> hop1) -> eB regs ----
        float eB0[8], eB1[8];
        {
            const int* pc = u1u_f + n * 56;
            int fc0 = pc[l];
            int fc1 = (l < 24) ? pc[32 + l] : 0;
            int oc0, oc1;
            precomb<1792, 256>(fc0, fc1, l, oc0, oc1);
#pragma unroll 1
            for (int k = 0; k < 8; k++) {
                float c0, c1;
                center_embed<7>(fc0, fc1, oc0, oc1, k * 7, upB, c0, c1);
                float icd = fminf(__frsqrt_rn(bfly_add(fmaf(c1, c1, c0 * c0))), 1e6f);
                float a0, a1, q0, q1;
                ga_tbl<7>(u2u_f + (n * 8 + k) * 56, upHB, u2u_w + (n * 8 + k) * 8,
                          c0, c1, icd, l, a0, a1);
                ga_tbl<5>(u2url_f + (n * 8 + k) * 40, vpHB, u2url_w + (n * 8 + k) * 8,
                          c0, c1, icd, l, q0, q1);
                xsw[l * XS_STRIDE + k]        = c0;
                xsw[(32 + l) * XS_STRIDE + k] = c1;
                xsw[(64 + l) * XS_STRIDE + k] = (a0 + q0) * 0.5f;
                xsw[(96 + l) * XS_STRIDE + k] = (a1 + q1) * 0.5f;
            }
            __syncwarp();
            lin_mma(AWhi, AWlo, xsw, b2, l);
#pragma unroll
            for (int k = 0; k < 8; k++) {
                eB0[k] = xsw[l * XS_STRIDE + k];
                eB1[k] = xsw[(32 + l) * XS_STRIDE + k];
            }
            __syncwarp();
        }

        // ---- stage A: url branch (hop2 -> hop1) -> Y stays in xsw ----
        {
            const int* pc = u1url_f + n * 40;
            int fc0 = pc[l];
            int fc1 = (l < 8) ? pc[32 + l] : 0;
            int oc0, oc1;
            precomb<1792, 256>(fc0, fc1, l, oc0, oc1);
#pragma unroll 1
            for (int k = 0; k < 8; k++) {
                float c0, c1;
                center_embed<5>(fc0, fc1, oc0, oc1, k * 5, vpB, c0, c1);
                float icd = fminf(__frsqrt_rn(bfly_add(fmaf(c1, c1, c0 * c0))), 1e6f);
                float a0, a1, q0, q1;
                ga_tbl<7>(url2u_f + (n * 8 + k) * 56, upHB, url2u_w + (n * 8 + k) * 8,
                          c0, c1, icd, l, a0, a1);
                ga_tbl<5>(url2url_f + (n * 8 + k) * 40, vpHB, url2url_w + (n * 8 + k) * 8,
                          c0, c1, icd, l, q0, q1);
                xsw[l * XS_STRIDE + k]        = c0;
                xsw[(32 + l) * XS_STRIDE + k] = c1;
                xsw[(64 + l) * XS_STRIDE + k] = (a0 + q0) * 0.5f;
                xsw[(96 + l) * XS_STRIDE + k] = (a1 + q1) * 0.5f;
            }
            __syncwarp();
            lin_mma(AWhi, AWlo, xsw, b2, l);
        }

        // ---- stage C: hop1 -> center (fp32 tables: feeds output directly) ----
        {
            int uf = (l < 7) ? user_f[n * 7 + l] : 0;
            int ou0, ou1;
            precomb<1792, 256>(uf, 0, l, ou0, ou1);
            float c0, c1;
            center_embed<7>(uf, 0, ou0, ou1, 0, upB, c0, c1);
            float icd = fminf(__frsqrt_rn(bfly_add(fmaf(c1, c1, c0 * c0))), 1e6f);

            // eA from xsw (stage A's Y) — read before clobbering column 0
            float eA0[8], eA1[8];
#pragma unroll
            for (int k = 0; k < 8; k++) {
                eA0[k] = xsw[l * XS_STRIDE + k];
                eA1[k] = xsw[(32 + l) * XS_STRIDE + k];
            }

            float a0, a1, q0, q1;
            ga_reg(eA0, eA1, u1url_w + n * 8, c0, c1, icd, l, a0, a1);
            ga_reg(eB0, eB1, u1u_w + n * 8, c0, c1, icd, l, q0, q1);

            xsw[l * XS_STRIDE]        = c0;
            xsw[(32 + l) * XS_STRIDE] = c1;
            xsw[(64 + l) * XS_STRIDE] = (a0 + q0) * 0.5f;
            xsw[(96 + l) * XS_STRIDE] = (a1 + q1) * 0.5f;
            __syncwarp();

            float s0 = __ldg(b1 + l), s1 = __ldg(b1 + 32 + l), u0 = 0.f, u1 = 0.f;
#pragma unroll 8
            for (int i = 0; i < 128; i += 2) {
                float x0 = xsw[i * XS_STRIDE];
                float x1 = xsw[(i + 1) * XS_STRIDE];
                float2 w0 = __ldg(W1T + i * 32 + l);
                float2 w1 = __ldg(W1T + (i + 1) * 32 + l);
                s0 = fmaf(w0.x, x0, s0); s1 = fmaf(w0.y, x0, s1);
                u0 = fmaf(w1.x, x1, u0); u1 = fmaf(w1.y, x1, u1);
            }
            __syncwarp();
            float ue0 = fmaxf(s0 + u0, 0.f);
            float ue1 = fmaxf(s1 + u1, 0.f);

            int vf = (l < 5) ? url_f[n * 5 + l] : 0;
            int ov0, ov1;
            precomb<1792, 256>(vf, 0, l, ov0, ov1);
            float v0, v1;
            center_embed<5>(vf, 0, ov0, ov1, 0, vpB, v0, v1);

            float p0 = fmaf(__ldg(Wo + l), ue0, fmaf(__ldg(Wo + 32 + l), ue1,
                       fmaf(__ldg(Wo + 64 + l), v0, __ldg(Wo + 96 + l) * v1)));
            float p1 = fmaf(__ldg(Wo + 128 + l), ue0, fmaf(__ldg(Wo + 160 + l), ue1,
                       fmaf(__ldg(Wo + 192 + l), v0, __ldg(Wo + 224 + l) * v1)));
            ull pp = pack2(p0, p1);
#pragma unroll
            for (int o = 16; o; o >>= 1) {
                ull q = __shfl_xor_sync(FULL, pp, o);
                addp(pp, q);
            }
            if (l == 0) {
                p0 = lo32(pp) + __ldg(bo); p1 = hi32(pp) + __ldg(bo + 1);
                float mm = fmaxf(p0, p1);
                float z0 = __expf(p0 - mm), z1 = __expf(p1 - mm);
                float inv = __fdividef(1.f, z0 + z1);
                *(float2*)(out + n * 2) = make_float2(z0 * inv, z1 * inv);
            }
        }
    }
}

extern "C" void kernel_launch(void* const* d_in, const int* in_sizes, int n_in,
                              void* d_out, int out_size) {
    const int*   user_f    = (const int*)d_in[1];
    const int*   url_f     = (const int*)d_in[2];
    const int*   u1u_f     = (const int*)d_in[3];
    const float* u1u_w     = (const float*)d_in[4];
    const int*   u1url_f   = (const int*)d_in[5];
    const float* u1url_w   = (const float*)d_in[6];
    const int*   u2u_f     = (const int*)d_in[7];
    const float* u2u_w     = (const float*)d_in[8];
    const int*   u2url_f   = (const int*)d_in[9];
    const float* u2url_w   = (const float*)d_in[10];
    const int*   url2u_f   = (const int*)d_in[11];
    const float* url2u_w   = (const float*)d_in[12];
    const int*   url2url_f = (const int*)d_in[13];
    const float* url2url_w = (const float*)d_in[14];
    const float* user_table = (const float*)d_in[15];
    const float* url_table  = (const float*)d_in[16];
    const float* W2 = (const float*)d_in[17];
    const float* b2 = (const float*)d_in[18];
    const float* W1 = (const float*)d_in[19];
    const float* b1 = (const float*)d_in[20];
    const float* Wo = (const float*)d_in[21];
    const float* bo = (const float*)d_in[22];
    float* out = (float*)d_out;

    int N = in_sizes[0];

    cudaFuncSetAttribute(gcn_kernel, cudaFuncAttributeMaxDynamicSharedMemorySize, SMEM_BYTES);
    int sm = 148;
    cudaDeviceGetAttribute(&sm, cudaDevAttrMultiProcessorCount, 0);

    prep_kernel<<<16, 256>>>(W1);
    gcn_kernel<<<sm, NTHREADS, SMEM_BYTES>>>(
        user_f, url_f, u1u_f, u1u_w, u1url_f, u1url_w,
        u2u_f, u2u_w, u2url_f, u2url_w,
        url2u_f, url2u_w, url2url_f, url2url_w,
        user_table, url_table, W2, b2, b1, Wo, bo, out, N);
}

// round 15
// speedup vs baseline: 3.5473x; 1.0723x over previous
#include <cuda_runtime.h>
#include <cuda_fp16.h>
#include <cstdint>

#define FULL 0xffffffffu
typedef unsigned long long ull;

__constant__ int UOFF[7] = {0, 11577, 11588, 11599, 11610, 11621, 11642};
__constant__ int VOFF[5] = {0, 4733, 4754, 4761, 4772};

constexpr int NWARP = 20;
constexpr int NTHREADS = NWARP * 32;         // 640
constexpr int XS_STRIDE = 9;
constexpr int XS_FLOATS = 128 * XS_STRIDE;   // 1152 per warp
constexpr int AW_WORDS = 32 * 32 * 4;        // 4096 words: fp16 A-frag table (uint4/lane)
constexpr int UP_FLOATS = (3 * 49 + 7) * 64; // 9856 fp32: user pair tables + single
constexpr int VP_FLOATS = (2 * 49 + 7) * 64; // 6720 fp32: url pair tables + single
constexpr int UP_ENT = 3 * 49 + 7;           // 154
constexpr int VP_ENT = 2 * 49 + 7;           // 105
constexpr int PAIR_F32_B = 49 * 256;         // fp32 pair-table stride (bytes)
constexpr int PAIR_F16_B = 49 * 128;         // fp16 pair-table stride (bytes)
constexpr int SMEM_WORDS = AW_WORDS + UP_FLOATS + VP_FLOATS
                         + UP_ENT * 32 + VP_ENT * 32 + NWARP * XS_FLOATS;
constexpr int SMEM_BYTES = SMEM_WORDS * 4;   // 208000

__device__ unsigned W1TH[128 * 32];  // half2(W1[l][i], W1[l+32][i]) at [i*32+l]
__device__ unsigned int g_ctr;

__global__ void prep_kernel(const float* __restrict__ W1) {
    int i = blockIdx.x * blockDim.x + threadIdx.x;
    if (i == 0) g_ctr = 0;
    if (i < 128 * 32) {
        int col = i >> 5, l = i & 31;
        __half2 h = __floats2half2_rn(W1[l * 128 + col], W1[(l + 32) * 128 + col]);
        W1TH[i] = *(unsigned*)&h;
    }
}

__device__ __forceinline__ float bfly_add(float v) {
#pragma unroll
    for (int o = 16; o; o >>= 1) v += __shfl_xor_sync(FULL, v, o);
    return v;
}
__device__ __forceinline__ void addp(ull& a, ull b) {
    asm("add.rn.f32x2 %0, %0, %1;" : "+l"(a) : "l"(b));
}
__device__ __forceinline__ ull pack2(float x, float y) {
    ull r; asm("mov.b64 %0, {%1, %2};" : "=l"(r) : "f"(x), "f"(y));
    return r;
}
__device__ __forceinline__ float lo32(ull v) { return __uint_as_float((unsigned)v); }
__device__ __forceinline__ float hi32(ull v) { return __uint_as_float((unsigned)(v >> 32)); }

__device__ __forceinline__ unsigned pk_hf(float lo, float hi) {
    __half2 h = __floats2half2_rn(lo, hi);
    return *(unsigned*)&h;
}
__device__ __forceinline__ float hfr(float x) {
    return __half2float(__float2half_rn(x));
}

__device__ __forceinline__ void mma16h(float (&c)[4], const uint4& a, unsigned b0, unsigned b1) {
    asm volatile("mma.sync.aligned.m16n8k16.row.col.f32.f16.f16.f32 "
                 "{%0,%1,%2,%3},{%4,%5,%6,%7},{%8,%9},{%0,%1,%2,%3};"
                 : "+f"(c[0]), "+f"(c[1]), "+f"(c[2]), "+f"(c[3])
                 : "r"(a.x), "r"(a.y), "r"(a.z), "r"(a.w), "r"(b0), "r"(b1));
}

// precombine adjacent-feature pair offsets with parametric strides:
// o0[l] = f[l]*MA + f[l+1]*MB (l+1 wraps into f1 at lane 31); o1 same for f1.
template <int MA, int MB>
__device__ __forceinline__ void precomb(int f0, int f1, int l, int& o0, int& o1) {
    int f0n = __shfl_down_sync(FULL, f0, 1);
    int f10 = __shfl_sync(FULL, f1, 0);
    f0n = (l == 31) ? f10 : f0n;
    int f1n = __shfl_down_sync(FULL, f1, 1);
    o0 = f0 * MA + f0n * MB;
    o1 = f1 * MA + f1n * MB;
}

// fp32 pair-table embed (stage C / output-facing)
template <int NF>
__device__ __forceinline__ void center_embed(int f0, int f1, int o0, int o1, int base,
                                             const char* tbB, float& c0, float& c1) {
    constexpr int SINGLE_B = ((NF + 1) / 2 - 1) * PAIR_F32_B;
    ull acc = 0;
#pragma unroll
    for (int p = 0; 2 * p + 1 < NF; p++) {
        int pa = base + 2 * p;
        int off = __shfl_sync(FULL, (pa < 32) ? o0 : o1, pa & 31);
        addp(acc, *(const ull*)(tbB + off + p * PAIR_F32_B));
    }
    int ps = base + NF - 1;
    int ia = __shfl_sync(FULL, (ps < 32) ? f0 : f1, ps & 31);
    addp(acc, *(const ull*)(tbB + (ia << 8) + SINGLE_B));
    c0 = lo32(acc); c1 = hi32(acc);
}

// fp16 pair-table embed (stages A/B: feeds cosine + x vector; noise-tolerant)
template <int NF>
__device__ __forceinline__ void center_embed_h(int f0, int f1, int o0, int o1, int base,
                                               const char* tbHB, float& c0, float& c1) {
    constexpr int SINGLE_B = ((NF + 1) / 2 - 1) * PAIR_F16_B;
    __half2 acc;
    {
        int pa = base;
        int off = __shfl_sync(FULL, (pa < 32) ? o0 : o1, pa & 31);
        acc = *(const __half2*)(tbHB + off);
    }
#pragma unroll
    for (int p = 1; 2 * p + 1 < NF; p++) {
        int pa = base + 2 * p;
        int off = __shfl_sync(FULL, (pa < 32) ? o0 : o1, pa & 31);
        acc = __hadd2(acc, *(const __half2*)(tbHB + off + p * PAIR_F16_B));
    }
    int ps = base + NF - 1;
    int ia = __shfl_sync(FULL, (ps < 32) ? f0 : f1, ps & 31);
    acc = __hadd2(acc, *(const __half2*)(tbHB + (ia << 7) + SINGLE_B));
    float2 fv = __half22float2(acc);
    c0 = fv.x; c1 = fv.y;
}

// softmax(cosine) + weighted relu-sum over 8 neighbors.
// fold-and-redistribute multi-reduce; lane 4j owns neighbor j's (d,nn) sum.
__device__ __forceinline__ void ga_tail(const float (&e0)[8], const float (&e1)[8],
                                        float (&d)[8], float (&nn)[8],
                                        const float* __restrict__ wptr, float icd,
                                        int l, float& out0, float& out1) {
    ull P[8];
#pragma unroll
    for (int kk = 0; kk < 8; kk++) P[kk] = pack2(d[kk], nn[kk]);
#pragma unroll
    for (int i = 0; i < 8; i++) addp(P[i], __shfl_xor_sync(FULL, P[i], 16));
    bool b4 = (l & 16) != 0;
    ull Q[4];
#pragma unroll
    for (int i = 0; i < 4; i++) Q[i] = b4 ? P[i + 4] : P[i];
#pragma unroll
    for (int i = 0; i < 4; i++) addp(Q[i], __shfl_xor_sync(FULL, Q[i], 8));
    bool b3 = (l & 8) != 0;
    ull R0 = b3 ? Q[2] : Q[0];
    ull R1 = b3 ? Q[3] : Q[1];
    addp(R0, __shfl_xor_sync(FULL, R0, 4));
    addp(R1, __shfl_xor_sync(FULL, R1, 4));
    ull S = (l & 4) ? R1 : R0;
    addp(S, __shfl_xor_sync(FULL, S, 2));
    addp(S, __shfl_xor_sync(FULL, S, 1));
    float rr = fminf(__frsqrt_rn(hi32(S)), 1e6f);      // 1/max(sqrt(nn),1e-6)
    float mycw = __expf(lo32(S) * rr * icd);           // cosine in [-1,1]; safe
    float4 wA = *(const float4*)wptr;
    float4 wB = *(const float4*)(wptr + 4);
    float w[8] = {wA.x, wA.y, wA.z, wA.w, wB.x, wB.y, wB.z, wB.w};
    float cw[8];
#pragma unroll
    for (int k = 0; k < 8; k++) cw[k] = __shfl_sync(FULL, mycw, 4 * k);
    float s = 0.f;
#pragma unroll
    for (int k = 0; k < 8; k++) s += cw[k];
    float inv = __fdividef(1.f, s);
    float o0 = 0.f, o1 = 0.f;
#pragma unroll
    for (int k = 0; k < 8; k++) {
        float sc = cw[k] * inv;
        o0 = fmaf(fmaxf(e0[k] * w[k], 0.f), sc, o0);
        o1 = fmaf(fmaxf(e1[k] * w[k], 0.f), sc, o1);
    }
    out0 = o0; out1 = o1;
}

// graph attention over 8 neighbors via fp16 pair tables with packed HADD2
// accumulation; single convert per neighbor.
template <int NF>
__device__ __forceinline__ void ga_tbl(const int* __restrict__ flist,
                                       const char* tbHB,
                                       const float* __restrict__ wptr,
                                       float c0, float c1, float icd, int l,
                                       float& out0, float& out1) {
    constexpr int SINGLE_B = ((NF + 1) / 2 - 1) * PAIR_F16_B;
    int f0 = flist[l];
    int f1 = (l < 8 * NF - 32) ? flist[32 + l] : 0;
    int o0, o1;
    precomb<896, 128>(f0, f1, l, o0, o1);
    float e0[8], e1[8], d[8], nn[8];
#pragma unroll
    for (int kk = 0; kk < 8; kk++) {
        __half2 acc;
        {
            const int pa = kk * NF;
            int off = __shfl_sync(FULL, (pa < 32) ? o0 : o1, pa & 31);
            acc = *(const __half2*)(tbHB + off);
        }
#pragma unroll
        for (int p = 1; 2 * p + 1 < NF; p++) {
            const int pa = kk * NF + 2 * p;
            int off = __shfl_sync(FULL, (pa < 32) ? o0 : o1, pa & 31);
            acc = __hadd2(acc, *(const __half2*)(tbHB + off + p * PAIR_F16_B));
        }
        {
            const int ps = kk * NF + NF - 1;
            int ia = __shfl_sync(FULL, (ps < 32) ? f0 : f1, ps & 31);
            acc = __hadd2(acc, *(const __half2*)(tbHB + (ia << 7) + SINGLE_B));
        }
        float2 fv = __half22float2(acc);
        float a0 = fv.x, a1 = fv.y;
        e0[kk] = a0; e1[kk] = a1;
        d[kk]  = fmaf(a1, c1, a0 * c0);
        nn[kk] = fmaf(a1, a1, a0 * a0);
    }
    ga_tail(e0, e1, d, nn, wptr, icd, l, out0, out1);
}

__device__ __forceinline__ void ga_reg(const float (&e0)[8], const float (&e1)[8],
                                       const float* __restrict__ wptr,
                                       float c0, float c1, float icd, int l,
                                       float& out0, float& out1) {
    float d[8], nn[8];
#pragma unroll
    for (int kk = 0; kk < 8; kk++) {
        d[kk]  = fmaf(e1[kk], c1, e0[kk] * c0);
        nn[kk] = fmaf(e1[kk], e1[kk], e0[kk] * e0[kk]);
    }
    ga_tail(e0, e1, d, nn, wptr, icd, l, out0, out1);
}

// relu(W2(64x128) @ X[128x8] + b2): fp16 single-A, x hi/lo split, 2 MMAs per frag.
// Y written back into xsw (stride XS_STRIDE). b2 loaded per call (L1-cached).
__device__ __forceinline__ void lin_mma(const uint4* __restrict__ AWH,
                                        float* __restrict__ xsw,
                                        const float* __restrict__ b2,
                                        int lane) {
    int g = lane >> 2, tg = lane & 3;
    float acc[4][4];
#pragma unroll
    for (int m = 0; m < 4; m++) {
        float bAv = __ldg(b2 + 16 * m + g);
        float bBv = __ldg(b2 + 16 * m + 8 + g);
        acc[m][0] = bAv; acc[m][1] = bAv;
        acc[m][2] = bBv; acc[m][3] = bBv;
    }
#pragma unroll 2
    for (int kt = 0; kt < 8; kt++) {
        int r0 = 16 * kt + 2 * tg;
        float xa0 = xsw[r0 * XS_STRIDE + g];
        float xa1 = xsw[(r0 + 1) * XS_STRIDE + g];
        float xb0 = xsw[(r0 + 8) * XS_STRIDE + g];
        float xb1 = xsw[(r0 + 9) * XS_STRIDE + g];
        unsigned Bh0 = pk_hf(xa0, xa1), Bh1 = pk_hf(xb0, xb1);
        unsigned Bl0 = pk_hf(xa0 - hfr(xa0), xa1 - hfr(xa1));
        unsigned Bl1 = pk_hf(xb0 - hfr(xb0), xb1 - hfr(xb1));
        const uint4* pa = AWH + kt * 4 * 32 + lane;
#pragma unroll
        for (int m = 0; m < 4; m++) {
            uint4 a = pa[m * 32];
            mma16h(acc[m], a, Bh0, Bh1);
            mma16h(acc[m], a, Bl0, Bl1);
        }
    }
    __syncwarp();
#pragma unroll
    for (int m = 0; m < 4; m++) {
        xsw[(16 * m + g) * XS_STRIDE + 2 * tg]         = fmaxf(acc[m][0], 0.f);
        xsw[(16 * m + g) * XS_STRIDE + 2 * tg + 1]     = fmaxf(acc[m][1], 0.f);
        xsw[(16 * m + g + 8) * XS_STRIDE + 2 * tg]     = fmaxf(acc[m][2], 0.f);
        xsw[(16 * m + g + 8) * XS_STRIDE + 2 * tg + 1] = fmaxf(acc[m][3], 0.f);
    }
    __syncwarp();
}

__global__ void __launch_bounds__(NTHREADS, 1)
gcn_kernel(const int* __restrict__ user_f, const int* __restrict__ url_f,
           const int* __restrict__ u1u_f, const float* __restrict__ u1u_w,
           const int* __restrict__ u1url_f, const float* __restrict__ u1url_w,
           const int* __restrict__ u2u_f, const float* __restrict__ u2u_w,
           const int* __restrict__ u2url_f, const float* __restrict__ u2url_w,
           const int* __restrict__ url2u_f, const float* __restrict__ url2u_w,
           const int* __restrict__ url2url_f, const float* __restrict__ url2url_w,
           const float* __restrict__ user_table, const float* __restrict__ url_table,
           const float* __restrict__ W2, const float* __restrict__ b2,
           const float* __restrict__ b1,
           const float* __restrict__ Wo, const float* __restrict__ bo,
           float* __restrict__ out, int N) {
    extern __shared__ float smf[];
    uint4* AWHv  = (uint4*)smf;                       // 32 frags x 32 lanes
    float* upF   = smf + AW_WORDS;
    float* vpF   = upF + UP_FLOATS;
    unsigned* upH = (unsigned*)(vpF + VP_FLOATS);     // fp16x2 user tables
    unsigned* vpH = upH + UP_ENT * 32;                // fp16x2 url tables
    float* xsAll = (float*)(vpH + VP_ENT * 32);

    int tid = threadIdx.x;

    // ---- W2 A-fragments for m16n8k16 fp16, single table (frag fid = kt*4+m) ----
    for (int i = tid; i < 1024; i += NTHREADS) {
        int fid = i >> 5, ln = i & 31;
        int kt = fid >> 2, m = fid & 3;
        int gg = ln >> 2, tg = ln & 3;
        int r0 = 16 * m + gg, r1 = r0 + 8;
        int c0 = 16 * kt + 2 * tg, c1 = c0 + 1, c2 = c0 + 8, c3 = c0 + 9;
        uint4 a;
        a.x = pk_hf(W2[r0 * 128 + c0], W2[r0 * 128 + c1]);
        a.y = pk_hf(W2[r1 * 128 + c0], W2[r1 * 128 + c1]);
        a.z = pk_hf(W2[r0 * 128 + c2], W2[r0 * 128 + c3]);
        a.w = pk_hf(W2[r1 * 128 + c2], W2[r1 * 128 + c3]);
        AWHv[fid * 32 + ln] = a;
    }
    // ---- fp32 user tables: P0=(c0,c1) P1=(c2,c3) P2=(c4,c5) then 7-entry single (c6) ----
    for (int i = tid; i < UP_FLOATS; i += NTHREADS) {
        int e = i >> 6, q = i & 63, ln = q >> 1, c = q & 1;
        int dim = ln + 32 * c;
        float v;
        if (e < 147) {
            int p = e / 49, rem = e % 49, ia = rem / 7, ib = rem % 7;
            v = user_table[(UOFF[2 * p] + ia) * 64 + dim]
              + user_table[(UOFF[2 * p + 1] + ib) * 64 + dim];
        } else {
            v = user_table[(UOFF[6] + (e - 147)) * 64 + dim];
        }
        upF[i] = v;
    }
    // ---- fp32 url tables: P0=(c0,c1) P1=(c2,c3) then 7-entry single (c4) ----
    for (int i = tid; i < VP_FLOATS; i += NTHREADS) {
        int e = i >> 6, q = i & 63, ln = q >> 1, c = q & 1;
        int dim = ln + 32 * c;
        float v;
        if (e < 98) {
            int p = e / 49, rem = e % 49, ia = rem / 7, ib = rem % 7;
            v = url_table[(VOFF[2 * p] + ia) * 64 + dim]
              + url_table[(VOFF[2 * p + 1] + ib) * 64 + dim];
        } else {
            v = url_table[(VOFF[4] + (e - 98)) * 64 + dim];
        }
        vpF[i] = v;
    }
    __syncthreads();
    // ---- fp16 copies of the pair tables (derived from fp32 smem) ----
    for (int i = tid; i < UP_ENT * 32; i += NTHREADS) {
        int e = i >> 5, ln = i & 31;
        upH[i] = pk_hf(upF[e * 64 + 2 * ln], upF[e * 64 + 2 * ln + 1]);
    }
    for (int i = tid; i < VP_ENT * 32; i += NTHREADS) {
        int e = i >> 5, ln = i & 31;
        vpH[i] = pk_hf(vpF[e * 64 + 2 * ln], vpF[e * 64 + 2 * ln + 1]);
    }
    __syncthreads();

    int l   = tid & 31;
    int wrp = tid >> 5;
    float* xsw = xsAll + wrp * XS_FLOATS;
    const char* upB  = (const char*)upF + (l << 3);
    const char* vpB  = (const char*)vpF + (l << 3);
    const char* upHB = (const char*)upH + (l << 2);
    const char* vpHB = (const char*)vpH + (l << 2);
    const uint4* AWH = AWHv;

    for (;;) {
        int n;
        if (l == 0) n = (int)atomicAdd(&g_ctr, 1u);
        n = __shfl_sync(FULL, n, 0);
        if (n >= N) break;

        // ---- stage B: user branch (hop2 -> hop1) -> eB regs ----
        float eB0[8], eB1[8];
        {
            const int* pc = u1u_f + n * 56;
            int fc0 = pc[l];
            int fc1 = (l < 24) ? pc[32 + l] : 0;
            int oc0, oc1;
            precomb<896, 128>(fc0, fc1, l, oc0, oc1);
#pragma unroll 1
            for (int k = 0; k < 8; k++) {
                float c0, c1;
                center_embed_h<7>(fc0, fc1, oc0, oc1, k * 7, upHB, c0, c1);
                float icd = fminf(__frsqrt_rn(bfly_add(fmaf(c1, c1, c0 * c0))), 1e6f);
                float a0, a1, q0, q1;
                ga_tbl<7>(u2u_f + (n * 8 + k) * 56, upHB, u2u_w + (n * 8 + k) * 8,
                          c0, c1, icd, l, a0, a1);
                ga_tbl<5>(u2url_f + (n * 8 + k) * 40, vpHB, u2url_w + (n * 8 + k) * 8,
                          c0, c1, icd, l, q0, q1);
                xsw[l * XS_STRIDE + k]        = c0;
                xsw[(32 + l) * XS_STRIDE + k] = c1;
                xsw[(64 + l) * XS_STRIDE + k] = (a0 + q0) * 0.5f;
                xsw[(96 + l) * XS_STRIDE + k] = (a1 + q1) * 0.5f;
            }
            __syncwarp();
            lin_mma(AWH, xsw, b2, l);
#pragma unroll
            for (int k = 0; k < 8; k++) {
                eB0[k] = xsw[l * XS_STRIDE + k];
                eB1[k] = xsw[(32 + l) * XS_STRIDE + k];
            }
            __syncwarp();
        }

        // ---- stage A: url branch (hop2 -> hop1) -> Y stays in xsw ----
        {
            const int* pc = u1url_f + n * 40;
            int fc0 = pc[l];
            int fc1 = (l < 8) ? pc[32 + l] : 0;
            int oc0, oc1;
            precomb<896, 128>(fc0, fc1, l, oc0, oc1);
#pragma unroll 1
            for (int k = 0; k < 8; k++) {
                float c0, c1;
                center_embed_h<5>(fc0, fc1, oc0, oc1, k * 5, vpHB, c0, c1);
                float icd = fminf(__frsqrt_rn(bfly_add(fmaf(c1, c1, c0 * c0))), 1e6f);
                float a0, a1, q0, q1;
                ga_tbl<7>(url2u_f + (n * 8 + k) * 56, upHB, url2u_w + (n * 8 + k) * 8,
                          c0, c1, icd, l, a0, a1);
                ga_tbl<5>(url2url_f + (n * 8 + k) * 40, vpHB, url2url_w + (n * 8 + k) * 8,
                          c0, c1, icd, l, q0, q1);
                xsw[l * XS_STRIDE + k]        = c0;
                xsw[(32 + l) * XS_STRIDE + k] = c1;
                xsw[(64 + l) * XS_STRIDE + k] = (a0 + q0) * 0.5f;
                xsw[(96 + l) * XS_STRIDE + k] = (a1 + q1) * 0.5f;
            }
            __syncwarp();
            lin_mma(AWH, xsw, b2, l);
        }

        // ---- stage C: hop1 -> center (fp32 tables: feeds output directly) ----
        {
            int uf = (l < 7) ? user_f[n * 7 + l] : 0;
            int ou0, ou1;
            precomb<1792, 256>(uf, 0, l, ou0, ou1);
            float c0, c1;
            center_embed<7>(uf, 0, ou0, ou1, 0, upB, c0, c1);
            float icd = fminf(__frsqrt_rn(bfly_add(fmaf(c1, c1, c0 * c0))), 1e6f);

            // eA from xsw (stage A's Y) — read before clobbering column 0
            float eA0[8], eA1[8];
#pragma unroll
            for (int k = 0; k < 8; k++) {
                eA0[k] = xsw[l * XS_STRIDE + k];
                eA1[k] = xsw[(32 + l) * XS_STRIDE + k];
            }

            float a0, a1, q0, q1;
            ga_reg(eA0, eA1, u1url_w + n * 8, c0, c1, icd, l, a0, a1);
            ga_reg(eB0, eB1, u1u_w + n * 8, c0, c1, icd, l, q0, q1);

            xsw[l * XS_STRIDE]        = c0;
            xsw[(32 + l) * XS_STRIDE] = c1;
            xsw[(64 + l) * XS_STRIDE] = (a0 + q0) * 0.5f;
            xsw[(96 + l) * XS_STRIDE] = (a1 + q1) * 0.5f;
            __syncwarp();

            float s0 = __ldg(b1 + l), s1 = __ldg(b1 + 32 + l), u0 = 0.f, u1 = 0.f;
#pragma unroll 8
            for (int i = 0; i < 128; i += 2) {
                float x0 = xsw[i * XS_STRIDE];
                float x1 = xsw[(i + 1) * XS_STRIDE];
                float2 w0 = __half22float2(*(const __half2*)&W1TH[i * 32 + l]);
                float2 w1 = __half22float2(*(const __half2*)&W1TH[(i + 1) * 32 + l]);
                s0 = fmaf(w0.x, x0, s0); s1 = fmaf(w0.y, x0, s1);
                u0 = fmaf(w1.x, x1, u0); u1 = fmaf(w1.y, x1, u1);
            }
            __syncwarp();
            float ue0 = fmaxf(s0 + u0, 0.f);
            float ue1 = fmaxf(s1 + u1, 0.f);

            int vf = (l < 5) ? url_f[n * 5 + l] : 0;
            int ov0, ov1;
            precomb<1792, 256>(vf, 0, l, ov0, ov1);
            float v0, v1;
            center_embed<5>(vf, 0, ov0, ov1, 0, vpB, v0, v1);

            float p0 = fmaf(__ldg(Wo + l), ue0, fmaf(__ldg(Wo + 32 + l), ue1,
                       fmaf(__ldg(Wo + 64 + l), v0, __ldg(Wo + 96 + l) * v1)));
            float p1 = fmaf(__ldg(Wo + 128 + l), ue0, fmaf(__ldg(Wo + 160 + l), ue1,
                       fmaf(__ldg(Wo + 192 + l), v0, __ldg(Wo + 224 + l) * v1)));
            ull pp = pack2(p0, p1);
#pragma unroll
            for (int o = 16; o; o >>= 1) {
                ull q = __shfl_xor_sync(FULL, pp, o);
                addp(pp, q);
            }
            if (l == 0) {
                p0 = lo32(pp) + __ldg(bo); p1 = hi32(pp) + __ldg(bo + 1);
                float mm = fmaxf(p0, p1);
                float z0 = __expf(p0 - mm), z1 = __expf(p1 - mm);
                float inv = __fdividef(1.f, z0 + z1);
                *(float2*)(out + n * 2) = make_float2(z0 * inv, z1 * inv);
            }
        }
    }
}

extern "C" void kernel_launch(void* const* d_in, const int* in_sizes, int n_in,
                              void* d_out, int out_size) {
    const int*   user_f    = (const int*)d_in[1];
    const int*   url_f     = (const int*)d_in[2];
    const int*   u1u_f     = (const int*)d_in[3];
    const float* u1u_w     = (const float*)d_in[4];
    const int*   u1url_f   = (const int*)d_in[5];
    const float* u1url_w   = (const float*)d_in[6];
    const int*   u2u_f     = (const int*)d_in[7];
    const float* u2u_w     = (const float*)d_in[8];
    const int*   u2url_f   = (const int*)d_in[9];
    const float* u2url_w   = (const float*)d_in[10];
    const int*   url2u_f   = (const int*)d_in[11];
    const float* url2u_w   = (const float*)d_in[12];
    const int*   url2url_f = (const int*)d_in[13];
    const float* url2url_w = (const float*)d_in[14];
    const float* user_table = (const float*)d_in[15];
    const float* url_table  = (const float*)d_in[16];
    const float* W2 = (const float*)d_in[17];
    const float* b2 = (const float*)d_in[18];
    const float* W1 = (const float*)d_in[19];
    const float* b1 = (const float*)d_in[20];
    const float* Wo = (const float*)d_in[21];
    const float* bo = (const float*)d_in[22];
    float* out = (float*)d_out;

    int N = in_sizes[0];

    cudaFuncSetAttribute(gcn_kernel, cudaFuncAttributeMaxDynamicSharedMemorySize, SMEM_BYTES);
    int sm = 148;
    cudaDeviceGetAttribute(&sm, cudaDevAttrMultiProcessorCount, 0);

    prep_kernel<<<16, 256>>>(W1);
    gcn_kernel<<<sm, NTHREADS, SMEM_BYTES>>>(
        user_f, url_f, u1u_f, u1u_w, u1url_f, u1url_w,
        u2u_f, u2u_w, u2url_f, u2url_w,
        url2u_f, url2u_w, url2url_f, url2url_w,
        user_table, url_table, W2, b2, b1, Wo, bo, out, N);
}